// round 10
// baseline (speedup 1.0000x reference)
#include <cuda_runtime.h>
#include <cuda_bf16.h>
#include <math.h>

#define NN 256
#define TT 30000
#define HH 512
#define LL 256
#define EE 32768

#define KSTEPS 1875
#define SPLITKZ 37
#define SPG 51

// bigmm smem stage layout (bytes)
#define ASTRIDE 24
#define BSTRIDE 136
#define ST_AH 0
#define ST_AL 6144
#define ST_BH 12288
#define ST_BL 16640
#define STAGE 20992
#define NSTAGE 4
#define SMEM_DYN (STAGE * NSTAGE)

// chain gemm strides / smem layout — k32 stages (2 x k16 sub-tiles)
#define SASTR 24
#define SBSTR 72
#define ASUB 3072                  // 64*24*2
#define BSUB 2304                  // 16*72*2
#define NST 3
#define CG_AH 0
#define CG_AL 6144                 // 2*ASUB
#define CG_BH 12288
#define CG_BL 16896                // +2*BSUB
#define CSTAGE 21504
#define CGRP (CSTAGE * NST)        // 64512 per K-group
#define CH_TOT2 (2 * CGRP)         // 129024

#define NCTA 32

// ---------------- device scratch ----------------
__device__ float g_B[NN * NN];
__device__ __nv_bfloat16 g_Bh[NN * NN];
__device__ __nv_bfloat16 g_Xh[NN * TT], g_Xl[NN * TT];
__device__ __nv_bfloat16 g_Wh[TT * HH], g_Wl[TT * HH];
__device__ float g_Ppart[SPLITKZ * NN * HH];
__device__ __nv_bfloat16 g_Ph[NN * HH], g_Pl[NN * HH];
__device__ __nv_bfloat16 g_U1h[NN * HH], g_U1l[NN * HH];
__device__ __nv_bfloat16 g_hh[NN * HH], g_hl[NN * HH];
__device__ __nv_bfloat16 g_Q2h[NN * LL], g_Q2l[NN * LL];
__device__ __nv_bfloat16 g_U2h[NN * LL], g_U2l[NN * LL];
__device__ __nv_bfloat16 g_fh[NN * LL], g_fl[NN * LL];
__device__ __nv_bfloat16 g_Q3h[NN * HH], g_Q3l[NN * HH];
__device__ __nv_bfloat16 g_U3h[NN * HH], g_U3l[NN * HH];
__device__ __nv_bfloat16 g_sh2[NN * HH], g_sl2[NN * HH];
__device__ __nv_bfloat16 g_W1bh[HH * HH], g_W1bl[HH * HH];
__device__ __nv_bfloat16 g_W2ah[HH * LL], g_W2al[HH * LL];
__device__ __nv_bfloat16 g_W2bh[LL * LL], g_W2bl[LL * LL];
__device__ __nv_bfloat16 g_Wc1ah[LL * HH], g_Wc1al[LL * HH];
__device__ __nv_bfloat16 g_Wc1bh[HH * HH], g_Wc1bl[HH * HH];
__device__ float g_Q4[NN];
__device__ float g_dpart[NCTA];
__device__ unsigned g_bar_cnt;
__device__ unsigned g_bar_gen;

// ---------------- conversion sizes (in 8-elem units) ----------------
#define N_X   (NN * TT / 8)
#define N_W   (TT * HH / 8)
#define N_W1B (HH * HH / 8)
#define N_W2A (HH * LL / 8)
#define N_W2B (LL * LL / 8)
#define N_WC1A (LL * HH / 8)
#define N_WC1B (HH * HH / 8)
#define N_CVT (N_X + N_W + N_W1B + N_W2A + N_W2B + N_WC1A + N_WC1B)
#define N_B4  (NN * NN / 4)
#define N_TOT (N_CVT + N_B4)

__device__ __forceinline__ void cvt8(const float* __restrict__ src,
                                     __nv_bfloat16* __restrict__ hi,
                                     __nv_bfloat16* __restrict__ lo, int j8) {
    float4 v0 = ((const float4*)src)[2 * j8], v1 = ((const float4*)src)[2 * j8 + 1];
    float f[8] = {v0.x, v0.y, v0.z, v0.w, v1.x, v1.y, v1.z, v1.w};
    union { __nv_bfloat16 b[8]; uint4 u; } H, L;
    #pragma unroll
    for (int j = 0; j < 8; j++) {
        __nv_bfloat16 h = __float2bfloat16(f[j]);
        H.b[j] = h; L.b[j] = __float2bfloat16(f[j] - __bfloat162float(h));
    }
    ((uint4*)hi)[j8] = H.u;
    ((uint4*)lo)[j8] = L.u;
}

__global__ void k_cvt2(const float* __restrict__ X, const float* __restrict__ W,
                       const float* __restrict__ W1b, const float* __restrict__ W2a,
                       const float* __restrict__ W2b, const float* __restrict__ Wc1a,
                       const float* __restrict__ Wc1b) {
    int o = blockIdx.x * blockDim.x + threadIdx.x;
    if (o < N_X) { cvt8(X, g_Xh, g_Xl, o); return; }
    o -= N_X;
    if (o < N_W) { cvt8(W, g_Wh, g_Wl, o); return; }
    o -= N_W;
    if (o < N_W1B) { cvt8(W1b, g_W1bh, g_W1bl, o); return; }
    o -= N_W1B;
    if (o < N_W2A) { cvt8(W2a, g_W2ah, g_W2al, o); return; }
    o -= N_W2A;
    if (o < N_W2B) { cvt8(W2b, g_W2bh, g_W2bl, o); return; }
    o -= N_W2B;
    if (o < N_WC1A) { cvt8(Wc1a, g_Wc1ah, g_Wc1al, o); return; }
    o -= N_WC1A;
    if (o < N_WC1B) { cvt8(Wc1b, g_Wc1bh, g_Wc1bl, o); return; }
    o -= N_WC1B;
    if (o < N_B4) {
        int e0 = o * 4;
        float4 v = make_float4(0.f, 0.f, 0.f, 0.f);
        float* pv = &v.x;
        #pragma unroll
        for (int q = 0; q < 4; q++) {
            int e = e0 + q;
            if ((e >> 8) == (e & 255)) pv[q] = 1.f;
        }
        ((float4*)g_B)[o] = v;
    }
}

__global__ void k_edges(const int* __restrict__ idx) {
    int e = blockIdx.x * blockDim.x + threadIdx.x;
    if (e < EE) atomicAdd(&g_B[idx[EE + e] * NN + idx[e]], 1.0f);
}

// ---------------- PTX helpers ----------------
__device__ __forceinline__ void mma_bf16(float* c, const unsigned* a, const unsigned* b) {
    asm volatile(
        "mma.sync.aligned.m16n8k16.row.col.f32.bf16.bf16.f32 "
        "{%0,%1,%2,%3},{%4,%5,%6,%7},{%8,%9},{%0,%1,%2,%3};"
        : "+f"(c[0]), "+f"(c[1]), "+f"(c[2]), "+f"(c[3])
        : "r"(a[0]), "r"(a[1]), "r"(a[2]), "r"(a[3]), "r"(b[0]), "r"(b[1]));
}
__device__ __forceinline__ void ldsm4(unsigned* r, unsigned addr) {
    asm volatile("ldmatrix.sync.aligned.m8n8.x4.shared.b16 {%0,%1,%2,%3},[%4];"
                 : "=r"(r[0]), "=r"(r[1]), "=r"(r[2]), "=r"(r[3]) : "r"(addr));
}
__device__ __forceinline__ void ldsm4t(unsigned* r, unsigned addr) {
    asm volatile("ldmatrix.sync.aligned.m8n8.x4.trans.shared.b16 {%0,%1,%2,%3},[%4];"
                 : "=r"(r[0]), "=r"(r[1]), "=r"(r[2]), "=r"(r[3]) : "r"(addr));
}
__device__ __forceinline__ void cpa16(unsigned dst, const void* src) {
    asm volatile("cp.async.cg.shared.global [%0], [%1], 16;" :: "r"(dst), "l"(src));
}
__device__ __forceinline__ void cpa_commit() { asm volatile("cp.async.commit_group;"); }
template <int N> __device__ __forceinline__ void cpa_wait() {
    asm volatile("cp.async.wait_group %0;" :: "n"(N));
}

// ---------------- big GEMM (unchanged) ----------------
__global__ __launch_bounds__(256, 2)
void bigmm3(float* __restrict__ Ppart)
{
    extern __shared__ char dyn[];
    const unsigned sb = (unsigned)__cvta_generic_to_shared(dyn);

    const int t = threadIdx.x;
    const int m0 = blockIdx.y * 128, n0 = blockIdx.x * 128, z = blockIdx.z;
    const int s0 = z * SPG;
    const int ns = min(SPG, KSTEPS - s0);

    const int arow = t >> 1, ach = t & 1;
    const int brow = t >> 4, bch = t & 15;
    const __nv_bfloat16* gAh = g_Xh + (size_t)(m0 + arow) * TT + (size_t)s0 * 16 + ach * 8;
    const __nv_bfloat16* gAl = g_Xl + (size_t)(m0 + arow) * TT + (size_t)s0 * 16 + ach * 8;
    const __nv_bfloat16* gBh = g_Wh + (size_t)((size_t)s0 * 16 + brow) * HH + n0 + bch * 8;
    const __nv_bfloat16* gBl = g_Wl + (size_t)((size_t)s0 * 16 + brow) * HH + n0 + bch * 8;
    const unsigned dA = arow * 48 + ach * 16;
    const unsigned dB = brow * 272 + bch * 16;

    const int lane = t & 31, wid = t >> 5;
    const int wm = wid & 3, wn = wid >> 2;
    unsigned offA[2], offB[4];
    {
        int r = lane & 15, c = (lane >> 4) * 8;
        offA[0] = ((wm * 32 + r) * ASTRIDE + c) * 2;
        offA[1] = ((wm * 32 + 16 + r) * ASTRIDE + c) * 2;
        int br = (lane & 7) + ((lane & 16) ? 8 : 0);
        int bc = (lane & 8) ? 8 : 0;
        #pragma unroll
        for (int p = 0; p < 4; p++)
            offB[p] = (br * BSTRIDE + wn * 64 + p * 16 + bc) * 2;
    }

    float acc[2][8][4];
    #pragma unroll
    for (int i = 0; i < 2; i++)
        #pragma unroll
        for (int j = 0; j < 8; j++)
            #pragma unroll
            for (int q = 0; q < 4; q++) acc[i][j][q] = 0.f;

    #pragma unroll
    for (int sg = 0; sg < NSTAGE - 1; sg++) {
        if (sg < ns) {
            unsigned base = sb + sg * STAGE;
            cpa16(base + ST_AH + dA, gAh + sg * 16);
            cpa16(base + ST_AL + dA, gAl + sg * 16);
            cpa16(base + ST_BH + dB, gBh + (size_t)sg * 16 * HH);
            cpa16(base + ST_BL + dB, gBl + (size_t)sg * 16 * HH);
        }
        cpa_commit();
    }

    for (int s = 0; s < ns; s++) {
        cpa_wait<NSTAGE - 2>();
        __syncthreads();

        int sg = s + NSTAGE - 1;
        if (sg < ns) {
            unsigned base = sb + (sg & (NSTAGE - 1)) * STAGE;
            cpa16(base + ST_AH + dA, gAh + (size_t)sg * 16);
            cpa16(base + ST_AL + dA, gAl + (size_t)sg * 16);
            cpa16(base + ST_BH + dB, gBh + (size_t)sg * 16 * HH);
            cpa16(base + ST_BL + dB, gBl + (size_t)sg * 16 * HH);
        }
        cpa_commit();

        const unsigned base = sb + (s & (NSTAGE - 1)) * STAGE;
        unsigned aH[2][4], aL[2][4];
        ldsm4(aH[0], base + ST_AH + offA[0]);
        ldsm4(aH[1], base + ST_AH + offA[1]);
        ldsm4(aL[0], base + ST_AL + offA[0]);
        ldsm4(aL[1], base + ST_AL + offA[1]);
        #pragma unroll
        for (int p = 0; p < 4; p++) {
            unsigned r[4], q[4];
            ldsm4t(r, base + ST_BH + offB[p]);
            ldsm4t(q, base + ST_BL + offB[p]);
            unsigned bh0[2] = {r[0], r[2]}, bh1[2] = {r[1], r[3]};
            unsigned bl0[2] = {q[0], q[2]}, bl1[2] = {q[1], q[3]};
            #pragma unroll
            for (int mi = 0; mi < 2; mi++) {
                mma_bf16(acc[mi][2 * p],     aH[mi], bh0);
                mma_bf16(acc[mi][2 * p],     aH[mi], bl0);
                mma_bf16(acc[mi][2 * p],     aL[mi], bh0);
                mma_bf16(acc[mi][2 * p + 1], aH[mi], bh1);
                mma_bf16(acc[mi][2 * p + 1], aH[mi], bl1);
                mma_bf16(acc[mi][2 * p + 1], aL[mi], bh1);
            }
        }
    }

    float* Po = Ppart + (size_t)z * NN * HH;
    #pragma unroll
    for (int mi = 0; mi < 2; mi++) {
        int row = m0 + wm * 32 + mi * 16 + (lane >> 2);
        #pragma unroll
        for (int ni = 0; ni < 8; ni++) {
            int col = n0 + wn * 64 + ni * 8 + (lane & 3) * 2;
            *(float2*)&Po[(size_t)row * HH + col]       = make_float2(acc[mi][ni][0], acc[mi][ni][1]);
            *(float2*)&Po[(size_t)(row + 8) * HH + col] = make_float2(acc[mi][ni][2], acc[mi][ni][3]);
        }
    }
}

// ---------------- device-wide barrier ----------------
__device__ __forceinline__ void gbar() {
    __syncthreads();
    if (threadIdx.x == 0) {
        __threadfence();
        unsigned old = *(volatile unsigned*)&g_bar_gen;
        unsigned a = atomicAdd(&g_bar_cnt, 1u);
        if (a == NCTA - 1) {
            g_bar_cnt = 0;
            __threadfence();
            *(volatile unsigned*)&g_bar_gen = old + 1;
        } else {
            while (*(volatile unsigned*)&g_bar_gen == old) __nanosleep(64);
        }
        __threadfence();
    }
    __syncthreads();
}

// ---------------- 64x64 tile GEMM: k32 stages, cp.async 3-deep, warp-split-K ----------------
__device__ void dgemm64(const __nv_bfloat16* __restrict__ Ah, const __nv_bfloat16* __restrict__ Al,
                        const __nv_bfloat16* __restrict__ Bh, const __nv_bfloat16* __restrict__ Bl,
                        const float* __restrict__ bias,
                        __nv_bfloat16* __restrict__ Ch, __nv_bfloat16* __restrict__ Cl,
                        int N, int K, int m0, int n0, int epi, int aexact, char* sm)
{
    const int t = threadIdx.x;
    const int kg = t >> 7, t7 = t & 127;
    const int Kh = K >> 1;
    const int ns = Kh >> 5;            // k32 per stage

    const int arow = t7 >> 1, ak = (t7 & 1) * 8;
    const int brow = t7 >> 3, bn = (t7 & 7) * 8;
    const __nv_bfloat16* gAh = Ah + (size_t)(m0 + arow) * K + kg * Kh + ak;
    const __nv_bfloat16* gAl = aexact ? gAh : (Al + (size_t)(m0 + arow) * K + kg * Kh + ak);
    const __nv_bfloat16* gBh = Bh + (size_t)(kg * Kh + brow) * N + n0 + bn;
    const __nv_bfloat16* gBl = Bl + (size_t)(kg * Kh + brow) * N + n0 + bn;

    const unsigned grpBase = (unsigned)__cvta_generic_to_shared(sm) + kg * CGRP;
    const unsigned dA = (arow * SASTR + ak) * 2;
    const unsigned dB = (brow * SBSTR + bn) * 2;

    const int lane = t & 31;
    const int wid2 = (t >> 5) & 3;
    const int wm = wid2 & 1, wn = wid2 >> 1;

    unsigned offA[2], offB[2];
    {
        int r = lane & 15, c = (lane >> 4) * 8;
        offA[0] = ((wm * 32 + r) * SASTR + c) * 2;
        offA[1] = ((wm * 32 + 16 + r) * SASTR + c) * 2;
        int br = (lane & 7) + ((lane & 16) ? 8 : 0);
        int bc = (lane & 8) ? 8 : 0;
        offB[0] = (br * SBSTR + wn * 32 + bc) * 2;
        offB[1] = (br * SBSTR + wn * 32 + 16 + bc) * 2;
    }

    float acc[2][4][4];
    #pragma unroll
    for (int i = 0; i < 2; i++)
        #pragma unroll
        for (int j = 0; j < 4; j++)
            #pragma unroll
            for (int q = 0; q < 4; q++) acc[i][j][q] = 0.f;

    // prologue: stages 0..NST-2 (each stage = 2 k16 sub-tiles)
    #pragma unroll
    for (int sg = 0; sg < NST - 1; sg++) {
        if (sg < ns) {
            unsigned bs = grpBase + sg * CSTAGE;
            #pragma unroll
            for (int sub = 0; sub < 2; sub++) {
                size_t ko = (size_t)sg * 32 + sub * 16;
                cpa16(bs + CG_AH + sub * ASUB + dA, gAh + ko);
                if (!aexact) cpa16(bs + CG_AL + sub * ASUB + dA, gAl + ko);
                cpa16(bs + CG_BH + sub * BSUB + dB, gBh + ko * N);
                cpa16(bs + CG_BL + sub * BSUB + dB, gBl + ko * N);
            }
        }
        cpa_commit();
    }

    for (int s = 0; s < ns; s++) {
        cpa_wait<NST - 2>();
        __syncthreads();

        int sg = s + NST - 1;
        if (sg < ns) {
            unsigned bs = grpBase + (sg % NST) * CSTAGE;
            #pragma unroll
            for (int sub = 0; sub < 2; sub++) {
                size_t ko = (size_t)sg * 32 + sub * 16;
                cpa16(bs + CG_AH + sub * ASUB + dA, gAh + ko);
                if (!aexact) cpa16(bs + CG_AL + sub * ASUB + dA, gAl + ko);
                cpa16(bs + CG_BH + sub * BSUB + dB, gBh + ko * N);
                cpa16(bs + CG_BL + sub * BSUB + dB, gBl + ko * N);
            }
        }
        cpa_commit();

        const unsigned bs = grpBase + (s % NST) * CSTAGE;
        #pragma unroll
        for (int sub = 0; sub < 2; sub++) {
            unsigned aH[2][4], aL[2][4];
            ldsm4(aH[0], bs + CG_AH + sub * ASUB + offA[0]);
            ldsm4(aH[1], bs + CG_AH + sub * ASUB + offA[1]);
            if (!aexact) {
                ldsm4(aL[0], bs + CG_AL + sub * ASUB + offA[0]);
                ldsm4(aL[1], bs + CG_AL + sub * ASUB + offA[1]);
            }
            unsigned bH[4][2], bL[4][2];
            #pragma unroll
            for (int p = 0; p < 2; p++) {
                unsigned r[4];
                ldsm4t(r, bs + CG_BH + sub * BSUB + offB[p]);
                bH[2*p][0] = r[0]; bH[2*p][1] = r[2]; bH[2*p+1][0] = r[1]; bH[2*p+1][1] = r[3];
                ldsm4t(r, bs + CG_BL + sub * BSUB + offB[p]);
                bL[2*p][0] = r[0]; bL[2*p][1] = r[2]; bL[2*p+1][0] = r[1]; bL[2*p+1][1] = r[3];
            }
            #pragma unroll
            for (int mi = 0; mi < 2; mi++)
                #pragma unroll
                for (int ni = 0; ni < 4; ni++) {
                    mma_bf16(acc[mi][ni], aH[mi], bH[ni]);
                    mma_bf16(acc[mi][ni], aH[mi], bL[ni]);
                }
            if (!aexact) {
                #pragma unroll
                for (int mi = 0; mi < 2; mi++)
                    #pragma unroll
                    for (int ni = 0; ni < 4; ni++)
                        mma_bf16(acc[mi][ni], aL[mi], bH[ni]);
            }
        }
    }

    // combine K-groups through smem (reuse stage area)
    __syncthreads();
    float* comb = (float*)sm;
    if (kg == 1) {
        int base = t7 * 33;
        #pragma unroll
        for (int mi = 0; mi < 2; mi++)
            #pragma unroll
            for (int ni = 0; ni < 4; ni++)
                #pragma unroll
                for (int q = 0; q < 4; q++)
                    comb[base + mi * 16 + ni * 4 + q] = acc[mi][ni][q];
    }
    __syncthreads();
    if (kg == 0) {
        int base = t7 * 33;
        #pragma unroll
        for (int mi = 0; mi < 2; mi++) {
            int row = m0 + wm * 32 + mi * 16 + (lane >> 2);
            #pragma unroll
            for (int ni = 0; ni < 4; ni++) {
                int col = n0 + wn * 32 + ni * 8 + (lane & 3) * 2;
                float v[4];
                #pragma unroll
                for (int q = 0; q < 4; q++)
                    v[q] = acc[mi][ni][q] + comb[base + mi * 16 + ni * 4 + q];
                if (epi) {
                    float2 b = *(const float2*)&bias[col];
                    v[0] += b.x; v[1] += b.y; v[2] += b.x; v[3] += b.y;
                }
                if (epi == 1) {
                    v[0] = fmaxf(v[0], 0.f); v[1] = fmaxf(v[1], 0.f);
                    v[2] = fmaxf(v[2], 0.f); v[3] = fmaxf(v[3], 0.f);
                }
                #pragma unroll
                for (int rr = 0; rr < 2; rr++) {
                    float x0 = v[rr * 2], x1 = v[rr * 2 + 1];
                    __nv_bfloat16 h0 = __float2bfloat16(x0), h1 = __float2bfloat16(x1);
                    __nv_bfloat162 Hp, Lp;
                    Hp.x = h0; Hp.y = h1;
                    Lp.x = __float2bfloat16(x0 - __bfloat162float(h0));
                    Lp.y = __float2bfloat16(x1 - __bfloat162float(h1));
                    size_t off = (size_t)(row + rr * 8) * N + col;
                    *(__nv_bfloat162*)&Ch[off] = Hp;
                    *(__nv_bfloat162*)&Cl[off] = Lp;
                }
            }
        }
    }
    __syncthreads();
}

// ---------------- persistent chain kernel ----------------
__global__ __launch_bounds__(256)
void k_chain(const float* __restrict__ bs1a, const float* __restrict__ bs1b,
             const float* __restrict__ bs2a, const float* __restrict__ bs2b,
             const float* __restrict__ bc1a, const float* __restrict__ bc1b,
             const float* __restrict__ Wc2a, const float* __restrict__ bc2a,
             const float* __restrict__ Wc2b, const float* __restrict__ bc2b,
             const float* __restrict__ Wd, const float* __restrict__ bd,
             float* __restrict__ out)
{
    extern __shared__ char s_all[];
    __shared__ float dred[8];

    const int bid = blockIdx.x, t = threadIdx.x;
    const int gid = bid * 256 + t;
    const int wid = t >> 5, lane = t & 31;

    // ---- phase 0: reduceP -> Ph/Pl ; convert B -> Bh ----
    #pragma unroll
    for (int j = 0; j < 4; j++) {
        int i = gid + j * 8192;
        float4 s = make_float4(0.f, 0.f, 0.f, 0.f);
        #pragma unroll
        for (int z = 0; z < SPLITKZ; z++) {
            float4 v = ((const float4*)g_Ppart)[(size_t)z * (NN * HH / 4) + i];
            s.x += v.x; s.y += v.y; s.z += v.z; s.w += v.w;
        }
        int e = i * 4;
        float f[4] = {s.x, s.y, s.z, s.w};
        union { __nv_bfloat16 b[4]; uint2 u; } H, L;
        #pragma unroll
        for (int q = 0; q < 4; q++) {
            __nv_bfloat16 h = __float2bfloat16(f[q]);
            H.b[q] = h; L.b[q] = __float2bfloat16(f[q] - __bfloat162float(h));
        }
        *(uint2*)&g_Ph[e] = H.u;
        *(uint2*)&g_Pl[e] = L.u;
    }
    {
        float4 a = ((const float4*)g_B)[gid * 2], b = ((const float4*)g_B)[gid * 2 + 1];
        float f[8] = {a.x, a.y, a.z, a.w, b.x, b.y, b.z, b.w};
        union { __nv_bfloat16 v[8]; uint4 u; } H;
        #pragma unroll
        for (int q = 0; q < 8; q++) H.v[q] = __float2bfloat16(f[q]);
        ((uint4*)g_Bh)[gid] = H.u;
    }
    gbar();

    const int tx8 = bid & 7, ty8 = bid >> 3;
    const int tx4 = bid & 3, ty4 = bid >> 2;

    // G1: U1 = relu(B @ P + bs1a)   K=256, A exact
    dgemm64(g_Bh, (const __nv_bfloat16*)0, g_Ph, g_Pl, bs1a, g_U1h, g_U1l,
            HH, NN, ty8 * 64, tx8 * 64, 1, 1, s_all);
    gbar();
    // G2: h = relu(U1 @ Ws1b + bs1b)  K=512
    dgemm64(g_U1h, g_U1l, g_W1bh, g_W1bl, bs1b, g_hh, g_hl,
            HH, HH, ty8 * 64, tx8 * 64, 1, 0, s_all);
    gbar();
    // G3: Q2 = h @ Ws2a   K=512
    if (bid < 16)
        dgemm64(g_hh, g_hl, g_W2ah, g_W2al, (const float*)0, g_Q2h, g_Q2l,
                LL, HH, ty4 * 64, tx4 * 64, 0, 0, s_all);
    gbar();
    // G4: U2 = relu(B @ Q2 + bs2a)  K=256, A exact
    if (bid < 16)
        dgemm64(g_Bh, (const __nv_bfloat16*)0, g_Q2h, g_Q2l, bs2a, g_U2h, g_U2l,
                LL, NN, ty4 * 64, tx4 * 64, 1, 1, s_all);
    gbar();
    // G5: feat = U2 @ Ws2b + bs2b   K=256
    if (bid < 16)
        dgemm64(g_U2h, g_U2l, g_W2bh, g_W2bl, bs2b, g_fh, g_fl,
                LL, LL, ty4 * 64, tx4 * 64, 2, 0, s_all);
    gbar();
    // G6: Q3 = feat @ Wc1a   K=256
    dgemm64(g_fh, g_fl, g_Wc1ah, g_Wc1al, (const float*)0, g_Q3h, g_Q3l,
            HH, LL, ty8 * 64, tx8 * 64, 0, 0, s_all);
    gbar();
    // G7: U3 = relu(B @ Q3 + bc1a)  K=256, A exact
    dgemm64(g_Bh, (const __nv_bfloat16*)0, g_Q3h, g_Q3l, bc1a, g_U3h, g_U3l,
            HH, NN, ty8 * 64, tx8 * 64, 1, 1, s_all);
    gbar();
    // G8: s = relu(U3 @ Wc1b + bc1b)  K=512
    dgemm64(g_U3h, g_U3l, g_Wc1bh, g_Wc1bl, bc1b, g_sh2, g_sl2,
            HH, HH, ty8 * 64, tx8 * 64, 1, 0, s_all);
    gbar();

    // ---- q4 + dementia partials ----
    {
        int row = bid * 8 + wid;
        float s = 0.f;
        for (int i = lane; i < HH; i += 32)
            s += (__bfloat162float(g_sh2[row * HH + i]) + __bfloat162float(g_sl2[row * HH + i])) * Wc2a[i];
        #pragma unroll
        for (int o = 16; o; o >>= 1) s += __shfl_down_sync(0xFFFFFFFFu, s, o);
        if (lane == 0) g_Q4[row] = s;
    }
    {
        float ds = 0.f;
        int base = bid * 2048;
        for (int i = t; i < 2048; i += 256)
            ds += (__bfloat162float(g_fh[base + i]) + __bfloat162float(g_fl[base + i])) * Wd[base + i];
        #pragma unroll
        for (int o = 16; o; o >>= 1) ds += __shfl_down_sync(0xFFFFFFFFu, ds, o);
        if (lane == 0) dred[wid] = ds;
        __syncthreads();
        if (t == 0) {
            float v = 0.f;
            #pragma unroll
            for (int j = 0; j < 8; j++) v += dred[j];
            g_dpart[bid] = v;
        }
    }
    gbar();

    // ---- region scores + dementia combine ----
    {
        int row = bid * 8 + wid;
        float s = 0.f;
        for (int i = lane; i < NN; i += 32) s += g_B[row * NN + i] * g_Q4[i];
        #pragma unroll
        for (int o = 16; o; o >>= 1) s += __shfl_down_sync(0xFFFFFFFFu, s, o);
        if (lane == 0) {
            float u = fmaxf(s + bc2a[0], 0.f);
            float sc = u * Wc2b[0] + bc2b[0];
            out[1 + row] = 1.f / (1.f + expf(-sc));
        }
    }
    if (bid == 0 && wid == 0) {
        float v = g_dpart[lane];
        #pragma unroll
        for (int o = 16; o; o >>= 1) v += __shfl_down_sync(0xFFFFFFFFu, v, o);
        if (lane == 0) out[0] = 1.f / (1.f + expf(-(v + bd[0])));
    }
}

// ---------------- launch ----------------
extern "C" void kernel_launch(void* const* d_in, const int* in_sizes, int n_in,
                              void* d_out, int out_size) {
    const float* X    = (const float*)d_in[0];
    const int*   idx  = (const int*)d_in[1];
    const float* Ws1a = (const float*)d_in[3];
    const float* bs1a = (const float*)d_in[4];
    const float* Ws1b = (const float*)d_in[5];
    const float* bs1b = (const float*)d_in[6];
    const float* Ws2a = (const float*)d_in[7];
    const float* bs2a = (const float*)d_in[8];
    const float* Ws2b = (const float*)d_in[9];
    const float* bs2b = (const float*)d_in[10];
    const float* Wc1a = (const float*)d_in[11];
    const float* bc1a = (const float*)d_in[12];
    const float* Wc1b = (const float*)d_in[13];
    const float* bc1b = (const float*)d_in[14];
    const float* Wc2a = (const float*)d_in[15];
    const float* bc2a = (const float*)d_in[16];
    const float* Wc2b = (const float*)d_in[17];
    const float* bc2b = (const float*)d_in[18];
    const float* Wd   = (const float*)d_in[19];
    const float* bd   = (const float*)d_in[20];
    float* out = (float*)d_out;

    float* pPpart;
    cudaGetSymbolAddress((void**)&pPpart, g_Ppart);

    cudaFuncSetAttribute(bigmm3, cudaFuncAttributeMaxDynamicSharedMemorySize, SMEM_DYN);
    cudaFuncSetAttribute(k_chain, cudaFuncAttributeMaxDynamicSharedMemorySize, CH_TOT2);

    k_cvt2<<<(N_TOT + 255) / 256, 256>>>(X, Ws1a, Ws1b, Ws2a, Ws2b, Wc1a, Wc1b);
    k_edges<<<(EE + 255) / 256, 256>>>(idx);
    bigmm3<<<dim3(4, 2, SPLITKZ), 256, SMEM_DYN>>>(pPpart);
    k_chain<<<NCTA, 256, CH_TOT2>>>(bs1a, bs1b, bs2a, bs2b, bc1a, bc1b,
                                    Wc2a, bc2a, Wc2b, bc2b, Wd, bd, out);
}

// round 11
// speedup vs baseline: 1.1032x; 1.1032x over previous
#include <cuda_runtime.h>
#include <cuda_bf16.h>
#include <math.h>

#define NN 256
#define TT 30000
#define HH 512
#define LL 256
#define EE 32768

#define KSTEPS 1875
#define SPLITKZ 37
#define SPG 51

// bigmm smem stage layout (bytes)
#define ASTRIDE 24
#define BSTRIDE 136
#define ST_AH 0
#define ST_AL 6144
#define ST_BH 12288
#define ST_BL 16640
#define STAGE 20992
#define NSTAGE 4
#define SMEM_DYN (STAGE * NSTAGE)

// chain gemm strides / smem layout — k16 stages, 4 K-groups
#define SASTR 24
#define SBSTR 72
#define NST 3
#define CG_AH 0
#define CG_AL 3072
#define CG_BH 6144
#define CG_BL 8448
#define CSTAGE 10752
#define CGRP (CSTAGE * NST)        // 32256 per K-group
#define NKG 4
#define CH_TOT2 (NKG * CGRP)       // 129024

#define NCTA 32
#define CTHREADS 512

// ---------------- device scratch ----------------
__device__ float g_B[NN * NN];
__device__ __nv_bfloat16 g_Bh[NN * NN];
__device__ __nv_bfloat16 g_Xh[NN * TT], g_Xl[NN * TT];
__device__ __nv_bfloat16 g_Wh[TT * HH], g_Wl[TT * HH];
__device__ float g_Ppart[SPLITKZ * NN * HH];
__device__ __nv_bfloat16 g_Ph[NN * HH], g_Pl[NN * HH];
__device__ __nv_bfloat16 g_U1h[NN * HH], g_U1l[NN * HH];
__device__ __nv_bfloat16 g_hh[NN * HH], g_hl[NN * HH];
__device__ __nv_bfloat16 g_Q2h[NN * LL], g_Q2l[NN * LL];
__device__ __nv_bfloat16 g_U2h[NN * LL], g_U2l[NN * LL];
__device__ __nv_bfloat16 g_fh[NN * LL], g_fl[NN * LL];
__device__ __nv_bfloat16 g_Q3h[NN * HH], g_Q3l[NN * HH];
__device__ __nv_bfloat16 g_U3h[NN * HH], g_U3l[NN * HH];
__device__ __nv_bfloat16 g_sh2[NN * HH], g_sl2[NN * HH];
__device__ __nv_bfloat16 g_W1bh[HH * HH], g_W1bl[HH * HH];
__device__ __nv_bfloat16 g_W2ah[HH * LL], g_W2al[HH * LL];
__device__ __nv_bfloat16 g_W2bh[LL * LL], g_W2bl[LL * LL];
__device__ __nv_bfloat16 g_Wc1ah[LL * HH], g_Wc1al[LL * HH];
__device__ __nv_bfloat16 g_Wc1bh[HH * HH], g_Wc1bl[HH * HH];
__device__ float g_Q4[NN];
__device__ float g_dpart[NCTA];
__device__ unsigned g_bar_cnt;
__device__ unsigned g_bar_gen;

// ---------------- conversion sizes (in 8-elem units) ----------------
#define N_X   (NN * TT / 8)
#define N_W   (TT * HH / 8)
#define N_W1B (HH * HH / 8)
#define N_W2A (HH * LL / 8)
#define N_W2B (LL * LL / 8)
#define N_WC1A (LL * HH / 8)
#define N_WC1B (HH * HH / 8)
#define N_CVT (N_X + N_W + N_W1B + N_W2A + N_W2B + N_WC1A + N_WC1B)
#define N_B4  (NN * NN / 4)
#define N_TOT (N_CVT + N_B4)

__device__ __forceinline__ void cvt8(const float* __restrict__ src,
                                     __nv_bfloat16* __restrict__ hi,
                                     __nv_bfloat16* __restrict__ lo, int j8) {
    float4 v0 = ((const float4*)src)[2 * j8], v1 = ((const float4*)src)[2 * j8 + 1];
    float f[8] = {v0.x, v0.y, v0.z, v0.w, v1.x, v1.y, v1.z, v1.w};
    union { __nv_bfloat16 b[8]; uint4 u; } H, L;
    #pragma unroll
    for (int j = 0; j < 8; j++) {
        __nv_bfloat16 h = __float2bfloat16(f[j]);
        H.b[j] = h; L.b[j] = __float2bfloat16(f[j] - __bfloat162float(h));
    }
    ((uint4*)hi)[j8] = H.u;
    ((uint4*)lo)[j8] = L.u;
}

__global__ void k_cvt2(const float* __restrict__ X, const float* __restrict__ W,
                       const float* __restrict__ W1b, const float* __restrict__ W2a,
                       const float* __restrict__ W2b, const float* __restrict__ Wc1a,
                       const float* __restrict__ Wc1b) {
    int o = blockIdx.x * blockDim.x + threadIdx.x;
    if (o < N_X) { cvt8(X, g_Xh, g_Xl, o); return; }
    o -= N_X;
    if (o < N_W) { cvt8(W, g_Wh, g_Wl, o); return; }
    o -= N_W;
    if (o < N_W1B) { cvt8(W1b, g_W1bh, g_W1bl, o); return; }
    o -= N_W1B;
    if (o < N_W2A) { cvt8(W2a, g_W2ah, g_W2al, o); return; }
    o -= N_W2A;
    if (o < N_W2B) { cvt8(W2b, g_W2bh, g_W2bl, o); return; }
    o -= N_W2B;
    if (o < N_WC1A) { cvt8(Wc1a, g_Wc1ah, g_Wc1al, o); return; }
    o -= N_WC1A;
    if (o < N_WC1B) { cvt8(Wc1b, g_Wc1bh, g_Wc1bl, o); return; }
    o -= N_WC1B;
    if (o < N_B4) {
        int e0 = o * 4;
        float4 v = make_float4(0.f, 0.f, 0.f, 0.f);
        float* pv = &v.x;
        #pragma unroll
        for (int q = 0; q < 4; q++) {
            int e = e0 + q;
            if ((e >> 8) == (e & 255)) pv[q] = 1.f;
        }
        ((float4*)g_B)[o] = v;
    }
}

__global__ void k_edges(const int* __restrict__ idx) {
    int e = blockIdx.x * blockDim.x + threadIdx.x;
    if (e < EE) atomicAdd(&g_B[idx[EE + e] * NN + idx[e]], 1.0f);
}

// ---------------- PTX helpers ----------------
__device__ __forceinline__ void mma_bf16(float* c, const unsigned* a, const unsigned* b) {
    asm volatile(
        "mma.sync.aligned.m16n8k16.row.col.f32.bf16.bf16.f32 "
        "{%0,%1,%2,%3},{%4,%5,%6,%7},{%8,%9},{%0,%1,%2,%3};"
        : "+f"(c[0]), "+f"(c[1]), "+f"(c[2]), "+f"(c[3])
        : "r"(a[0]), "r"(a[1]), "r"(a[2]), "r"(a[3]), "r"(b[0]), "r"(b[1]));
}
__device__ __forceinline__ void ldsm4(unsigned* r, unsigned addr) {
    asm volatile("ldmatrix.sync.aligned.m8n8.x4.shared.b16 {%0,%1,%2,%3},[%4];"
                 : "=r"(r[0]), "=r"(r[1]), "=r"(r[2]), "=r"(r[3]) : "r"(addr));
}
__device__ __forceinline__ void ldsm4t(unsigned* r, unsigned addr) {
    asm volatile("ldmatrix.sync.aligned.m8n8.x4.trans.shared.b16 {%0,%1,%2,%3},[%4];"
                 : "=r"(r[0]), "=r"(r[1]), "=r"(r[2]), "=r"(r[3]) : "r"(addr));
}
__device__ __forceinline__ void cpa16(unsigned dst, const void* src) {
    asm volatile("cp.async.cg.shared.global [%0], [%1], 16;" :: "r"(dst), "l"(src));
}
__device__ __forceinline__ void cpa_commit() { asm volatile("cp.async.commit_group;"); }
template <int N> __device__ __forceinline__ void cpa_wait() {
    asm volatile("cp.async.wait_group %0;" :: "n"(N));
}

// ---------------- big GEMM (unchanged) ----------------
__global__ __launch_bounds__(256, 2)
void bigmm3(float* __restrict__ Ppart)
{
    extern __shared__ char dyn[];
    const unsigned sb = (unsigned)__cvta_generic_to_shared(dyn);

    const int t = threadIdx.x;
    const int m0 = blockIdx.y * 128, n0 = blockIdx.x * 128, z = blockIdx.z;
    const int s0 = z * SPG;
    const int ns = min(SPG, KSTEPS - s0);

    const int arow = t >> 1, ach = t & 1;
    const int brow = t >> 4, bch = t & 15;
    const __nv_bfloat16* gAh = g_Xh + (size_t)(m0 + arow) * TT + (size_t)s0 * 16 + ach * 8;
    const __nv_bfloat16* gAl = g_Xl + (size_t)(m0 + arow) * TT + (size_t)s0 * 16 + ach * 8;
    const __nv_bfloat16* gBh = g_Wh + (size_t)((size_t)s0 * 16 + brow) * HH + n0 + bch * 8;
    const __nv_bfloat16* gBl = g_Wl + (size_t)((size_t)s0 * 16 + brow) * HH + n0 + bch * 8;
    const unsigned dA = arow * 48 + ach * 16;
    const unsigned dB = brow * 272 + bch * 16;

    const int lane = t & 31, wid = t >> 5;
    const int wm = wid & 3, wn = wid >> 2;
    unsigned offA[2], offB[4];
    {
        int r = lane & 15, c = (lane >> 4) * 8;
        offA[0] = ((wm * 32 + r) * ASTRIDE + c) * 2;
        offA[1] = ((wm * 32 + 16 + r) * ASTRIDE + c) * 2;
        int br = (lane & 7) + ((lane & 16) ? 8 : 0);
        int bc = (lane & 8) ? 8 : 0;
        #pragma unroll
        for (int p = 0; p < 4; p++)
            offB[p] = (br * BSTRIDE + wn * 64 + p * 16 + bc) * 2;
    }

    float acc[2][8][4];
    #pragma unroll
    for (int i = 0; i < 2; i++)
        #pragma unroll
        for (int j = 0; j < 8; j++)
            #pragma unroll
            for (int q = 0; q < 4; q++) acc[i][j][q] = 0.f;

    #pragma unroll
    for (int sg = 0; sg < NSTAGE - 1; sg++) {
        if (sg < ns) {
            unsigned base = sb + sg * STAGE;
            cpa16(base + ST_AH + dA, gAh + sg * 16);
            cpa16(base + ST_AL + dA, gAl + sg * 16);
            cpa16(base + ST_BH + dB, gBh + (size_t)sg * 16 * HH);
            cpa16(base + ST_BL + dB, gBl + (size_t)sg * 16 * HH);
        }
        cpa_commit();
    }

    for (int s = 0; s < ns; s++) {
        cpa_wait<NSTAGE - 2>();
        __syncthreads();

        int sg = s + NSTAGE - 1;
        if (sg < ns) {
            unsigned base = sb + (sg & (NSTAGE - 1)) * STAGE;
            cpa16(base + ST_AH + dA, gAh + (size_t)sg * 16);
            cpa16(base + ST_AL + dA, gAl + (size_t)sg * 16);
            cpa16(base + ST_BH + dB, gBh + (size_t)sg * 16 * HH);
            cpa16(base + ST_BL + dB, gBl + (size_t)sg * 16 * HH);
        }
        cpa_commit();

        const unsigned base = sb + (s & (NSTAGE - 1)) * STAGE;
        unsigned aH[2][4], aL[2][4];
        ldsm4(aH[0], base + ST_AH + offA[0]);
        ldsm4(aH[1], base + ST_AH + offA[1]);
        ldsm4(aL[0], base + ST_AL + offA[0]);
        ldsm4(aL[1], base + ST_AL + offA[1]);
        #pragma unroll
        for (int p = 0; p < 4; p++) {
            unsigned r[4], q[4];
            ldsm4t(r, base + ST_BH + offB[p]);
            ldsm4t(q, base + ST_BL + offB[p]);
            unsigned bh0[2] = {r[0], r[2]}, bh1[2] = {r[1], r[3]};
            unsigned bl0[2] = {q[0], q[2]}, bl1[2] = {q[1], q[3]};
            #pragma unroll
            for (int mi = 0; mi < 2; mi++) {
                mma_bf16(acc[mi][2 * p],     aH[mi], bh0);
                mma_bf16(acc[mi][2 * p],     aH[mi], bl0);
                mma_bf16(acc[mi][2 * p],     aL[mi], bh0);
                mma_bf16(acc[mi][2 * p + 1], aH[mi], bh1);
                mma_bf16(acc[mi][2 * p + 1], aH[mi], bl1);
                mma_bf16(acc[mi][2 * p + 1], aL[mi], bh1);
            }
        }
    }

    float* Po = Ppart + (size_t)z * NN * HH;
    #pragma unroll
    for (int mi = 0; mi < 2; mi++) {
        int row = m0 + wm * 32 + mi * 16 + (lane >> 2);
        #pragma unroll
        for (int ni = 0; ni < 8; ni++) {
            int col = n0 + wn * 64 + ni * 8 + (lane & 3) * 2;
            *(float2*)&Po[(size_t)row * HH + col]       = make_float2(acc[mi][ni][0], acc[mi][ni][1]);
            *(float2*)&Po[(size_t)(row + 8) * HH + col] = make_float2(acc[mi][ni][2], acc[mi][ni][3]);
        }
    }
}

// ---------------- device-wide barrier (tight spin) ----------------
__device__ __forceinline__ void gbar() {
    __syncthreads();
    if (threadIdx.x == 0) {
        __threadfence();
        unsigned old = *(volatile unsigned*)&g_bar_gen;
        unsigned a = atomicAdd(&g_bar_cnt, 1u);
        if (a == NCTA - 1) {
            g_bar_cnt = 0;
            __threadfence();
            *(volatile unsigned*)&g_bar_gen = old + 1;
        } else {
            while (*(volatile unsigned*)&g_bar_gen == old) { }
        }
        __threadfence();
    }
    __syncthreads();
}

// ---------------- 64x64 tile GEMM: 512 threads, 4-way warp-split-K, k16 stages ----------------
__device__ void dgemm64(const __nv_bfloat16* __restrict__ Ah, const __nv_bfloat16* __restrict__ Al,
                        const __nv_bfloat16* __restrict__ Bh, const __nv_bfloat16* __restrict__ Bl,
                        const float* __restrict__ bias,
                        __nv_bfloat16* __restrict__ Ch, __nv_bfloat16* __restrict__ Cl,
                        int N, int K, int m0, int n0, int epi, int aexact, char* sm)
{
    const int t = threadIdx.x;
    const int kg = t >> 7, t7 = t & 127;   // 4 K-groups x 128 threads
    const int Kq = K >> 2;
    const int ns = Kq >> 4;                // k16 steps per group (4 or 8)

    const int arow = t7 >> 1, ak = (t7 & 1) * 8;
    const int brow = t7 >> 3, bn = (t7 & 7) * 8;
    const __nv_bfloat16* gAh = Ah + (size_t)(m0 + arow) * K + kg * Kq + ak;
    const __nv_bfloat16* gAl = aexact ? gAh : (Al + (size_t)(m0 + arow) * K + kg * Kq + ak);
    const __nv_bfloat16* gBh = Bh + (size_t)(kg * Kq + brow) * N + n0 + bn;
    const __nv_bfloat16* gBl = Bl + (size_t)(kg * Kq + brow) * N + n0 + bn;

    const unsigned grpBase = (unsigned)__cvta_generic_to_shared(sm) + kg * CGRP;
    const unsigned dA = (arow * SASTR + ak) * 2;
    const unsigned dB = (brow * SBSTR + bn) * 2;

    const int lane = t & 31;
    const int wid2 = (t >> 5) & 3;         // warp within group (also SMSP id)
    const int wm = wid2 & 1, wn = wid2 >> 1;

    unsigned offA[2], offB[2];
    {
        int r = lane & 15, c = (lane >> 4) * 8;
        offA[0] = ((wm * 32 + r) * SASTR + c) * 2;
        offA[1] = ((wm * 32 + 16 + r) * SASTR + c) * 2;
        int br = (lane & 7) + ((lane & 16) ? 8 : 0);
        int bc = (lane & 8) ? 8 : 0;
        offB[0] = (br * SBSTR + wn * 32 + bc) * 2;
        offB[1] = (br * SBSTR + wn * 32 + 16 + bc) * 2;
    }

    float acc[2][4][4];
    #pragma unroll
    for (int i = 0; i < 2; i++)
        #pragma unroll
        for (int j = 0; j < 4; j++)
            #pragma unroll
            for (int q = 0; q < 4; q++) acc[i][j][q] = 0.f;

    // prologue
    #pragma unroll
    for (int sg = 0; sg < NST - 1; sg++) {
        if (sg < ns) {
            unsigned bs = grpBase + sg * CSTAGE;
            size_t ko = (size_t)sg * 16;
            cpa16(bs + CG_AH + dA, gAh + ko);
            if (!aexact) cpa16(bs + CG_AL + dA, gAl + ko);
            cpa16(bs + CG_BH + dB, gBh + ko * N);
            cpa16(bs + CG_BL + dB, gBl + ko * N);
        }
        cpa_commit();
    }

    for (int s = 0; s < ns; s++) {
        cpa_wait<NST - 2>();
        __syncthreads();

        int sg = s + NST - 1;
        if (sg < ns) {
            unsigned bs = grpBase + (sg % NST) * CSTAGE;
            size_t ko = (size_t)sg * 16;
            cpa16(bs + CG_AH + dA, gAh + ko);
            if (!aexact) cpa16(bs + CG_AL + dA, gAl + ko);
            cpa16(bs + CG_BH + dB, gBh + ko * N);
            cpa16(bs + CG_BL + dB, gBl + ko * N);
        }
        cpa_commit();

        const unsigned bs = grpBase + (s % NST) * CSTAGE;
        unsigned aH[2][4], aL[2][4];
        ldsm4(aH[0], bs + CG_AH + offA[0]);
        ldsm4(aH[1], bs + CG_AH + offA[1]);
        if (!aexact) {
            ldsm4(aL[0], bs + CG_AL + offA[0]);
            ldsm4(aL[1], bs + CG_AL + offA[1]);
        }
        unsigned bH[4][2], bL[4][2];
        #pragma unroll
        for (int p = 0; p < 2; p++) {
            unsigned r[4];
            ldsm4t(r, bs + CG_BH + offB[p]);
            bH[2*p][0] = r[0]; bH[2*p][1] = r[2]; bH[2*p+1][0] = r[1]; bH[2*p+1][1] = r[3];
            ldsm4t(r, bs + CG_BL + offB[p]);
            bL[2*p][0] = r[0]; bL[2*p][1] = r[2]; bL[2*p+1][0] = r[1]; bL[2*p+1][1] = r[3];
        }
        #pragma unroll
        for (int mi = 0; mi < 2; mi++)
            #pragma unroll
            for (int ni = 0; ni < 4; ni++) {
                mma_bf16(acc[mi][ni], aH[mi], bH[ni]);
                mma_bf16(acc[mi][ni], aH[mi], bL[ni]);
            }
        if (!aexact) {
            #pragma unroll
            for (int mi = 0; mi < 2; mi++)
                #pragma unroll
                for (int ni = 0; ni < 4; ni++)
                    mma_bf16(acc[mi][ni], aL[mi], bH[ni]);
        }
    }

    // combine the 4 K-groups through smem (deterministic order)
    __syncthreads();
    float* comb = (float*)sm;
    if (kg != 0) {
        int base = (kg - 1) * 4224 + t7 * 33;
        #pragma unroll
        for (int mi = 0; mi < 2; mi++)
            #pragma unroll
            for (int ni = 0; ni < 4; ni++)
                #pragma unroll
                for (int q = 0; q < 4; q++)
                    comb[base + mi * 16 + ni * 4 + q] = acc[mi][ni][q];
    }
    __syncthreads();
    if (kg == 0) {
        #pragma unroll
        for (int mi = 0; mi < 2; mi++) {
            int row = m0 + wm * 32 + mi * 16 + (lane >> 2);
            #pragma unroll
            for (int ni = 0; ni < 4; ni++) {
                int col = n0 + wn * 32 + ni * 8 + (lane & 3) * 2;
                float v[4];
                #pragma unroll
                for (int q = 0; q < 4; q++) {
                    int idx = mi * 16 + ni * 4 + q;
                    v[q] = acc[mi][ni][q]
                         + comb[0 * 4224 + t7 * 33 + idx]
                         + comb[1 * 4224 + t7 * 33 + idx]
                         + comb[2 * 4224 + t7 * 33 + idx];
                }
                if (epi) {
                    float2 b = *(const float2*)&bias[col];
                    v[0] += b.x; v[1] += b.y; v[2] += b.x; v[3] += b.y;
                }
                if (epi == 1) {
                    v[0] = fmaxf(v[0], 0.f); v[1] = fmaxf(v[1], 0.f);
                    v[2] = fmaxf(v[2], 0.f); v[3] = fmaxf(v[3], 0.f);
                }
                #pragma unroll
                for (int rr = 0; rr < 2; rr++) {
                    float x0 = v[rr * 2], x1 = v[rr * 2 + 1];
                    __nv_bfloat16 h0 = __float2bfloat16(x0), h1 = __float2bfloat16(x1);
                    __nv_bfloat162 Hp, Lp;
                    Hp.x = h0; Hp.y = h1;
                    Lp.x = __float2bfloat16(x0 - __bfloat162float(h0));
                    Lp.y = __float2bfloat16(x1 - __bfloat162float(h1));
                    size_t off = (size_t)(row + rr * 8) * N + col;
                    *(__nv_bfloat162*)&Ch[off] = Hp;
                    *(__nv_bfloat162*)&Cl[off] = Lp;
                }
            }
        }
    }
    __syncthreads();
}

// ---------------- persistent chain kernel (512 threads) ----------------
__global__ __launch_bounds__(CTHREADS)
void k_chain(const float* __restrict__ bs1a, const float* __restrict__ bs1b,
             const float* __restrict__ bs2a, const float* __restrict__ bs2b,
             const float* __restrict__ bc1a, const float* __restrict__ bc1b,
             const float* __restrict__ Wc2a, const float* __restrict__ bc2a,
             const float* __restrict__ Wc2b, const float* __restrict__ bc2b,
             const float* __restrict__ Wd, const float* __restrict__ bd,
             float* __restrict__ out)
{
    extern __shared__ char s_all[];
    __shared__ float dred[16];

    const int bid = blockIdx.x, t = threadIdx.x;
    const int gid = bid * CTHREADS + t;         // 0..16383
    const int wid = t >> 5, lane = t & 31;

    // ---- phase 0: reduceP -> Ph/Pl ; convert B -> Bh ----
    #pragma unroll
    for (int j = 0; j < 2; j++) {
        int i = gid + j * 16384;                // 32768 float4
        float4 s = make_float4(0.f, 0.f, 0.f, 0.f);
        #pragma unroll
        for (int z = 0; z < SPLITKZ; z++) {
            float4 v = ((const float4*)g_Ppart)[(size_t)z * (NN * HH / 4) + i];
            s.x += v.x; s.y += v.y; s.z += v.z; s.w += v.w;
        }
        int e = i * 4;
        float f[4] = {s.x, s.y, s.z, s.w};
        union { __nv_bfloat16 b[4]; uint2 u; } H, L;
        #pragma unroll
        for (int q = 0; q < 4; q++) {
            __nv_bfloat16 h = __float2bfloat16(f[q]);
            H.b[q] = h; L.b[q] = __float2bfloat16(f[q] - __bfloat162float(h));
        }
        *(uint2*)&g_Ph[e] = H.u;
        *(uint2*)&g_Pl[e] = L.u;
    }
    if (gid < 8192) {
        float4 a = ((const float4*)g_B)[gid * 2], b = ((const float4*)g_B)[gid * 2 + 1];
        float f[8] = {a.x, a.y, a.z, a.w, b.x, b.y, b.z, b.w};
        union { __nv_bfloat16 v[8]; uint4 u; } H;
        #pragma unroll
        for (int q = 0; q < 8; q++) H.v[q] = __float2bfloat16(f[q]);
        ((uint4*)g_Bh)[gid] = H.u;
    }
    gbar();

    const int tx8 = bid & 7, ty8 = bid >> 3;
    const int tx4 = bid & 3, ty4 = bid >> 2;

    // G1: U1 = relu(B @ P + bs1a)   K=256, A exact
    dgemm64(g_Bh, (const __nv_bfloat16*)0, g_Ph, g_Pl, bs1a, g_U1h, g_U1l,
            HH, NN, ty8 * 64, tx8 * 64, 1, 1, s_all);
    gbar();
    // G2: h = relu(U1 @ Ws1b + bs1b)  K=512
    dgemm64(g_U1h, g_U1l, g_W1bh, g_W1bl, bs1b, g_hh, g_hl,
            HH, HH, ty8 * 64, tx8 * 64, 1, 0, s_all);
    gbar();
    // G3: Q2 = h @ Ws2a   K=512
    if (bid < 16)
        dgemm64(g_hh, g_hl, g_W2ah, g_W2al, (const float*)0, g_Q2h, g_Q2l,
                LL, HH, ty4 * 64, tx4 * 64, 0, 0, s_all);
    gbar();
    // G4: U2 = relu(B @ Q2 + bs2a)  K=256, A exact
    if (bid < 16)
        dgemm64(g_Bh, (const __nv_bfloat16*)0, g_Q2h, g_Q2l, bs2a, g_U2h, g_U2l,
                LL, NN, ty4 * 64, tx4 * 64, 1, 1, s_all);
    gbar();
    // G5: feat = U2 @ Ws2b + bs2b   K=256
    if (bid < 16)
        dgemm64(g_U2h, g_U2l, g_W2bh, g_W2bl, bs2b, g_fh, g_fl,
                LL, LL, ty4 * 64, tx4 * 64, 2, 0, s_all);
    gbar();
    // G6: Q3 = feat @ Wc1a   K=256
    dgemm64(g_fh, g_fl, g_Wc1ah, g_Wc1al, (const float*)0, g_Q3h, g_Q3l,
            HH, LL, ty8 * 64, tx8 * 64, 0, 0, s_all);
    gbar();
    // G7: U3 = relu(B @ Q3 + bc1a)  K=256, A exact
    dgemm64(g_Bh, (const __nv_bfloat16*)0, g_Q3h, g_Q3l, bc1a, g_U3h, g_U3l,
            HH, NN, ty8 * 64, tx8 * 64, 1, 1, s_all);
    gbar();
    // G8: s = relu(U3 @ Wc1b + bc1b)  K=512
    dgemm64(g_U3h, g_U3l, g_Wc1bh, g_Wc1bl, bc1b, g_sh2, g_sl2,
            HH, HH, ty8 * 64, tx8 * 64, 1, 0, s_all);
    gbar();

    // ---- q4 + dementia partials ----
    if (wid < 8) {
        int row = bid * 8 + wid;
        float s = 0.f;
        for (int i = lane; i < HH; i += 32)
            s += (__bfloat162float(g_sh2[row * HH + i]) + __bfloat162float(g_sl2[row * HH + i])) * Wc2a[i];
        #pragma unroll
        for (int o = 16; o; o >>= 1) s += __shfl_down_sync(0xFFFFFFFFu, s, o);
        if (lane == 0) g_Q4[row] = s;
    }
    {
        float ds = 0.f;
        int base = bid * 2048;
        for (int i = t; i < 2048; i += CTHREADS)
            ds += (__bfloat162float(g_fh[base + i]) + __bfloat162float(g_fl[base + i])) * Wd[base + i];
        #pragma unroll
        for (int o = 16; o; o >>= 1) ds += __shfl_down_sync(0xFFFFFFFFu, ds, o);
        if (lane == 0) dred[wid] = ds;
        __syncthreads();
        if (t == 0) {
            float v = 0.f;
            #pragma unroll
            for (int j = 0; j < 16; j++) v += dred[j];
            g_dpart[bid] = v;
        }
    }
    gbar();

    // ---- region scores + dementia combine ----
    if (wid < 8) {
        int row = bid * 8 + wid;
        float s = 0.f;
        for (int i = lane; i < NN; i += 32) s += g_B[row * NN + i] * g_Q4[i];
        #pragma unroll
        for (int o = 16; o; o >>= 1) s += __shfl_down_sync(0xFFFFFFFFu, s, o);
        if (lane == 0) {
            float u = fmaxf(s + bc2a[0], 0.f);
            float sc = u * Wc2b[0] + bc2b[0];
            out[1 + row] = 1.f / (1.f + expf(-sc));
        }
    }
    if (bid == 0 && wid == 0) {
        float v = g_dpart[lane];
        #pragma unroll
        for (int o = 16; o; o >>= 1) v += __shfl_down_sync(0xFFFFFFFFu, v, o);
        if (lane == 0) out[0] = 1.f / (1.f + expf(-(v + bd[0])));
    }
}

// ---------------- launch ----------------
extern "C" void kernel_launch(void* const* d_in, const int* in_sizes, int n_in,
                              void* d_out, int out_size) {
    const float* X    = (const float*)d_in[0];
    const int*   idx  = (const int*)d_in[1];
    const float* Ws1a = (const float*)d_in[3];
    const float* bs1a = (const float*)d_in[4];
    const float* Ws1b = (const float*)d_in[5];
    const float* bs1b = (const float*)d_in[6];
    const float* Ws2a = (const float*)d_in[7];
    const float* bs2a = (const float*)d_in[8];
    const float* Ws2b = (const float*)d_in[9];
    const float* bs2b = (const float*)d_in[10];
    const float* Wc1a = (const float*)d_in[11];
    const float* bc1a = (const float*)d_in[12];
    const float* Wc1b = (const float*)d_in[13];
    const float* bc1b = (const float*)d_in[14];
    const float* Wc2a = (const float*)d_in[15];
    const float* bc2a = (const float*)d_in[16];
    const float* Wc2b = (const float*)d_in[17];
    const float* bc2b = (const float*)d_in[18];
    const float* Wd   = (const float*)d_in[19];
    const float* bd   = (const float*)d_in[20];
    float* out = (float*)d_out;

    float* pPpart;
    cudaGetSymbolAddress((void**)&pPpart, g_Ppart);

    cudaFuncSetAttribute(bigmm3, cudaFuncAttributeMaxDynamicSharedMemorySize, SMEM_DYN);
    cudaFuncSetAttribute(k_chain, cudaFuncAttributeMaxDynamicSharedMemorySize, CH_TOT2);

    k_cvt2<<<(N_TOT + 255) / 256, 256>>>(X, Ws1a, Ws1b, Ws2a, Ws2b, Wc1a, Wc1b);
    k_edges<<<(EE + 255) / 256, 256>>>(idx);
    bigmm3<<<dim3(4, 2, SPLITKZ), 256, SMEM_DYN>>>(pPpart);
    k_chain<<<NCTA, CTHREADS, CH_TOT2>>>(bs1a, bs1b, bs2a, bs2b, bc1a, bc1b,
                                         Wc2a, bc2a, Wc2b, bc2b, Wd, bd, out);
}

// round 12
// speedup vs baseline: 1.1285x; 1.0229x over previous
#include <cuda_runtime.h>
#include <cuda_bf16.h>
#include <math.h>

#define NN 256
#define TT 30000
#define HH 512
#define LL 256
#define EE 32768

#define KSTEPS 1875
#define SPLITKZ 37
#define SPG 51

// bigmm bf16 buffer layout (within one 20992B buf)
#define ASTRIDE 24
#define BSTRIDE 136
#define ST_AH 0
#define ST_AL 6144
#define ST_BH 12288
#define ST_BL 16640
#define B16BUF 20992
// fp32 staging: 3 stages x (A 8192 + B 8192)
#define F32STG 16384
#define NF32 3
#define B16BASE (NF32 * F32STG)          // 49152
#define SMEM_DYN2 (B16BASE + 2 * B16BUF) // 91136

// chain gemm strides / smem layout — k16 stages, 4 K-groups
#define SASTR 24
#define SBSTR 72
#define NST 3
#define CG_AH 0
#define CG_AL 3072
#define CG_BH 6144
#define CG_BL 8448
#define CSTAGE 10752
#define CGRP (CSTAGE * NST)
#define NKG 4
#define CH_TOT2 (NKG * CGRP)             // 129024

#define NCTA 32
#define CTHREADS 512

// ---------------- device scratch ----------------
__device__ float g_B[NN * NN];
__device__ __nv_bfloat16 g_Bh[NN * NN];
__device__ float g_Ppart[SPLITKZ * NN * HH];
__device__ __nv_bfloat16 g_Ph[NN * HH], g_Pl[NN * HH];
__device__ __nv_bfloat16 g_U1h[NN * HH], g_U1l[NN * HH];
__device__ __nv_bfloat16 g_hh[NN * HH], g_hl[NN * HH];
__device__ __nv_bfloat16 g_Q2h[NN * LL], g_Q2l[NN * LL];
__device__ __nv_bfloat16 g_U2h[NN * LL], g_U2l[NN * LL];
__device__ __nv_bfloat16 g_fh[NN * LL], g_fl[NN * LL];
__device__ __nv_bfloat16 g_Q3h[NN * HH], g_Q3l[NN * HH];
__device__ __nv_bfloat16 g_U3h[NN * HH], g_U3l[NN * HH];
__device__ __nv_bfloat16 g_sh2[NN * HH], g_sl2[NN * HH];
__device__ __nv_bfloat16 g_W1bh[HH * HH], g_W1bl[HH * HH];
__device__ __nv_bfloat16 g_W2ah[HH * LL], g_W2al[HH * LL];
__device__ __nv_bfloat16 g_W2bh[LL * LL], g_W2bl[LL * LL];
__device__ __nv_bfloat16 g_Wc1ah[LL * HH], g_Wc1al[LL * HH];
__device__ __nv_bfloat16 g_Wc1bh[HH * HH], g_Wc1bl[HH * HH];
__device__ float g_Q4[NN];
__device__ float g_dpart[NCTA];
__device__ unsigned g_bar_cnt;
__device__ unsigned g_bar_gen;

// ---------------- conversion sizes (small weights only now) ----------------
#define N_W1B (HH * HH / 8)
#define N_W2A (HH * LL / 8)
#define N_W2B (LL * LL / 8)
#define N_WC1A (LL * HH / 8)
#define N_WC1B (HH * HH / 8)
#define N_CVT (N_W1B + N_W2A + N_W2B + N_WC1A + N_WC1B)
#define N_B4  (NN * NN / 4)
#define N_TOT (N_CVT + N_B4)

__device__ __forceinline__ void cvt8(const float* __restrict__ src,
                                     __nv_bfloat16* __restrict__ hi,
                                     __nv_bfloat16* __restrict__ lo, int j8) {
    float4 v0 = ((const float4*)src)[2 * j8], v1 = ((const float4*)src)[2 * j8 + 1];
    float f[8] = {v0.x, v0.y, v0.z, v0.w, v1.x, v1.y, v1.z, v1.w};
    union { __nv_bfloat16 b[8]; uint4 u; } H, L;
    #pragma unroll
    for (int j = 0; j < 8; j++) {
        __nv_bfloat16 h = __float2bfloat16(f[j]);
        H.b[j] = h; L.b[j] = __float2bfloat16(f[j] - __bfloat162float(h));
    }
    ((uint4*)hi)[j8] = H.u;
    ((uint4*)lo)[j8] = L.u;
}

__global__ void k_cvt2(const float* __restrict__ W1b, const float* __restrict__ W2a,
                       const float* __restrict__ W2b, const float* __restrict__ Wc1a,
                       const float* __restrict__ Wc1b) {
    int o = blockIdx.x * blockDim.x + threadIdx.x;
    if (o < N_W1B) { cvt8(W1b, g_W1bh, g_W1bl, o); return; }
    o -= N_W1B;
    if (o < N_W2A) { cvt8(W2a, g_W2ah, g_W2al, o); return; }
    o -= N_W2A;
    if (o < N_W2B) { cvt8(W2b, g_W2bh, g_W2bl, o); return; }
    o -= N_W2B;
    if (o < N_WC1A) { cvt8(Wc1a, g_Wc1ah, g_Wc1al, o); return; }
    o -= N_WC1A;
    if (o < N_WC1B) { cvt8(Wc1b, g_Wc1bh, g_Wc1bl, o); return; }
    o -= N_WC1B;
    if (o < N_B4) {
        int e0 = o * 4;
        float4 v = make_float4(0.f, 0.f, 0.f, 0.f);
        float* pv = &v.x;
        #pragma unroll
        for (int q = 0; q < 4; q++) {
            int e = e0 + q;
            if ((e >> 8) == (e & 255)) pv[q] = 1.f;
        }
        ((float4*)g_B)[o] = v;
    }
}

__global__ void k_edges(const int* __restrict__ idx) {
    int e = blockIdx.x * blockDim.x + threadIdx.x;
    if (e < EE) atomicAdd(&g_B[idx[EE + e] * NN + idx[e]], 1.0f);
}

// ---------------- PTX helpers ----------------
__device__ __forceinline__ void mma_bf16(float* c, const unsigned* a, const unsigned* b) {
    asm volatile(
        "mma.sync.aligned.m16n8k16.row.col.f32.bf16.bf16.f32 "
        "{%0,%1,%2,%3},{%4,%5,%6,%7},{%8,%9},{%0,%1,%2,%3};"
        : "+f"(c[0]), "+f"(c[1]), "+f"(c[2]), "+f"(c[3])
        : "r"(a[0]), "r"(a[1]), "r"(a[2]), "r"(a[3]), "r"(b[0]), "r"(b[1]));
}
__device__ __forceinline__ void ldsm4(unsigned* r, unsigned addr) {
    asm volatile("ldmatrix.sync.aligned.m8n8.x4.shared.b16 {%0,%1,%2,%3},[%4];"
                 : "=r"(r[0]), "=r"(r[1]), "=r"(r[2]), "=r"(r[3]) : "r"(addr));
}
__device__ __forceinline__ void ldsm4t(unsigned* r, unsigned addr) {
    asm volatile("ldmatrix.sync.aligned.m8n8.x4.trans.shared.b16 {%0,%1,%2,%3},[%4];"
                 : "=r"(r[0]), "=r"(r[1]), "=r"(r[2]), "=r"(r[3]) : "r"(addr));
}
__device__ __forceinline__ void cpa16(unsigned dst, const void* src) {
    asm volatile("cp.async.cg.shared.global [%0], [%1], 16;" :: "r"(dst), "l"(src));
}
__device__ __forceinline__ void cpa_commit() { asm volatile("cp.async.commit_group;"); }
template <int N> __device__ __forceinline__ void cpa_wait() {
    asm volatile("cp.async.wait_group %0;" :: "n"(N));
}

// ---------------- in-kernel fp32 -> bf16 hi/lo stage conversion ----------------
__device__ __forceinline__ void cvt_stage(char* f32s, char* b16s, int t) {
    const int arow = t >> 1, half = t & 1;
    {
        float4 a0 = *(float4*)(f32s + arow * 64 + half * 32);
        float4 a1 = *(float4*)(f32s + arow * 64 + half * 32 + 16);
        float f[8] = {a0.x, a0.y, a0.z, a0.w, a1.x, a1.y, a1.z, a1.w};
        union { __nv_bfloat16 b[8]; uint4 u; } H, L;
        #pragma unroll
        for (int j = 0; j < 8; j++) {
            __nv_bfloat16 h = __float2bfloat16(f[j]);
            H.b[j] = h; L.b[j] = __float2bfloat16(f[j] - __bfloat162float(h));
        }
        *(uint4*)(b16s + ST_AH + (arow * ASTRIDE + half * 8) * 2) = H.u;
        *(uint4*)(b16s + ST_AL + (arow * ASTRIDE + half * 8) * 2) = L.u;
    }
    {
        const int brow = t >> 4, bc = (t & 15) * 8;
        float4 b0 = *(float4*)(f32s + 8192 + brow * 512 + bc * 4);
        float4 b1 = *(float4*)(f32s + 8192 + brow * 512 + bc * 4 + 16);
        float f[8] = {b0.x, b0.y, b0.z, b0.w, b1.x, b1.y, b1.z, b1.w};
        union { __nv_bfloat16 b[8]; uint4 u; } H, L;
        #pragma unroll
        for (int j = 0; j < 8; j++) {
            __nv_bfloat16 h = __float2bfloat16(f[j]);
            H.b[j] = h; L.b[j] = __float2bfloat16(f[j] - __bfloat162float(h));
        }
        *(uint4*)(b16s + ST_BH + (brow * BSTRIDE + bc) * 2) = H.u;
        *(uint4*)(b16s + ST_BL + (brow * BSTRIDE + bc) * 2) = L.u;
    }
}

// ---------------- big GEMM: reads fp32 X/W directly, converts in-pipeline ----------------
__global__ __launch_bounds__(256, 2)
void bigmm3(const float* __restrict__ X, const float* __restrict__ W, float* __restrict__ Ppart)
{
    extern __shared__ char dyn[];
    const unsigned sb = (unsigned)__cvta_generic_to_shared(dyn);

    const int t = threadIdx.x;
    const int m0 = blockIdx.y * 128, n0 = blockIdx.x * 128, z = blockIdx.z;
    const int s0 = z * SPG;
    const int ns = min(SPG, KSTEPS - s0);

    // fp32 cp.async mapping
    const int arow = t >> 1, ahalf = t & 1;
    const int brow = t >> 4, bcol = (t & 15) * 8;
    const float* gA = X + (size_t)(m0 + arow) * TT + (size_t)s0 * 16 + ahalf * 8;
    const float* gB = W + (size_t)((size_t)s0 * 16 + brow) * HH + n0 + bcol;
    const unsigned dA32 = arow * 64 + ahalf * 32;
    const unsigned dB32 = 8192 + brow * 512 + bcol * 4;

    // fragment mapping (unchanged)
    const int lane = t & 31, wid = t >> 5;
    const int wm = wid & 3, wn = wid >> 2;
    unsigned offA[2], offB[4];
    {
        int r = lane & 15, c = (lane >> 4) * 8;
        offA[0] = ((wm * 32 + r) * ASTRIDE + c) * 2;
        offA[1] = ((wm * 32 + 16 + r) * ASTRIDE + c) * 2;
        int br = (lane & 7) + ((lane & 16) ? 8 : 0);
        int bc = (lane & 8) ? 8 : 0;
        #pragma unroll
        for (int p = 0; p < 4; p++)
            offB[p] = (br * BSTRIDE + wn * 64 + p * 16 + bc) * 2;
    }

    float acc[2][8][4];
    #pragma unroll
    for (int i = 0; i < 2; i++)
        #pragma unroll
        for (int j = 0; j < 8; j++)
            #pragma unroll
            for (int q = 0; q < 4; q++) acc[i][j][q] = 0.f;

    // prologue: fp32 stages 0,1
    #pragma unroll
    for (int sg = 0; sg < 2; sg++) {
        if (sg < ns) {
            unsigned fb = sb + sg * F32STG;
            cpa16(fb + dA32,      gA + (size_t)sg * 16);
            cpa16(fb + dA32 + 16, gA + (size_t)sg * 16 + 4);
            cpa16(fb + dB32,      gB + (size_t)sg * 16 * HH);
            cpa16(fb + dB32 + 16, gB + (size_t)sg * 16 * HH + 4);
        }
        cpa_commit();
    }
    cpa_wait<1>();
    __syncthreads();
    cvt_stage(dyn, dyn + B16BASE, t);   // stage 0 -> buf 0

    for (int s = 0; s < ns; s++) {
        int sg = s + 2;
        if (sg < ns) {
            unsigned fb = sb + (sg % NF32) * F32STG;
            cpa16(fb + dA32,      gA + (size_t)sg * 16);
            cpa16(fb + dA32 + 16, gA + (size_t)sg * 16 + 4);
            cpa16(fb + dB32,      gB + (size_t)sg * 16 * HH);
            cpa16(fb + dB32 + 16, gB + (size_t)sg * 16 * HH + 4);
        }
        cpa_commit();
        cpa_wait<1>();        // fp32 stage s+1 arrived
        __syncthreads();      // bf16 buf (s&1) conversion visible; f32 (s+1)%3 stable

        if (s + 1 < ns)
            cvt_stage(dyn + ((s + 1) % NF32) * F32STG,
                      dyn + B16BASE + ((s + 1) & 1) * B16BUF, t);

        const unsigned base = sb + B16BASE + (s & 1) * B16BUF;
        unsigned aH[2][4], aL[2][4];
        ldsm4(aH[0], base + ST_AH + offA[0]);
        ldsm4(aH[1], base + ST_AH + offA[1]);
        ldsm4(aL[0], base + ST_AL + offA[0]);
        ldsm4(aL[1], base + ST_AL + offA[1]);
        #pragma unroll
        for (int p = 0; p < 4; p++) {
            unsigned r[4], q[4];
            ldsm4t(r, base + ST_BH + offB[p]);
            ldsm4t(q, base + ST_BL + offB[p]);
            unsigned bh0[2] = {r[0], r[2]}, bh1[2] = {r[1], r[3]};
            unsigned bl0[2] = {q[0], q[2]}, bl1[2] = {q[1], q[3]};
            #pragma unroll
            for (int mi = 0; mi < 2; mi++) {
                mma_bf16(acc[mi][2 * p],     aH[mi], bh0);
                mma_bf16(acc[mi][2 * p],     aH[mi], bl0);
                mma_bf16(acc[mi][2 * p],     aL[mi], bh0);
                mma_bf16(acc[mi][2 * p + 1], aH[mi], bh1);
                mma_bf16(acc[mi][2 * p + 1], aH[mi], bl1);
                mma_bf16(acc[mi][2 * p + 1], aL[mi], bh1);
            }
        }
        __syncthreads();      // mma reads done before next iteration's conversion overwrites
    }

    float* Po = Ppart + (size_t)z * NN * HH;
    #pragma unroll
    for (int mi = 0; mi < 2; mi++) {
        int row = m0 + wm * 32 + mi * 16 + (lane >> 2);
        #pragma unroll
        for (int ni = 0; ni < 8; ni++) {
            int col = n0 + wn * 64 + ni * 8 + (lane & 3) * 2;
            *(float2*)&Po[(size_t)row * HH + col]       = make_float2(acc[mi][ni][0], acc[mi][ni][1]);
            *(float2*)&Po[(size_t)(row + 8) * HH + col] = make_float2(acc[mi][ni][2], acc[mi][ni][3]);
        }
    }
}

// ---------------- device-wide barrier ----------------
__device__ __forceinline__ void gbar() {
    __syncthreads();
    if (threadIdx.x == 0) {
        __threadfence();
        unsigned old = *(volatile unsigned*)&g_bar_gen;
        unsigned a = atomicAdd(&g_bar_cnt, 1u);
        if (a == NCTA - 1) {
            g_bar_cnt = 0;
            __threadfence();
            *(volatile unsigned*)&g_bar_gen = old + 1;
        } else {
            while (*(volatile unsigned*)&g_bar_gen == old) { }
        }
        __threadfence();
    }
    __syncthreads();
}

// ---------------- 64x64 tile GEMM: 512 threads, 4-way warp-split-K, k16 stages ----------------
__device__ void dgemm64(const __nv_bfloat16* __restrict__ Ah, const __nv_bfloat16* __restrict__ Al,
                        const __nv_bfloat16* __restrict__ Bh, const __nv_bfloat16* __restrict__ Bl,
                        const float* __restrict__ bias,
                        __nv_bfloat16* __restrict__ Ch, __nv_bfloat16* __restrict__ Cl,
                        int N, int K, int m0, int n0, int epi, int aexact, char* sm)
{
    const int t = threadIdx.x;
    const int kg = t >> 7, t7 = t & 127;
    const int Kq = K >> 2;
    const int ns = Kq >> 4;

    const int arow = t7 >> 1, ak = (t7 & 1) * 8;
    const int brow = t7 >> 3, bn = (t7 & 7) * 8;
    const __nv_bfloat16* gAh = Ah + (size_t)(m0 + arow) * K + kg * Kq + ak;
    const __nv_bfloat16* gAl = aexact ? gAh : (Al + (size_t)(m0 + arow) * K + kg * Kq + ak);
    const __nv_bfloat16* gBh = Bh + (size_t)(kg * Kq + brow) * N + n0 + bn;
    const __nv_bfloat16* gBl = Bl + (size_t)(kg * Kq + brow) * N + n0 + bn;

    const unsigned grpBase = (unsigned)__cvta_generic_to_shared(sm) + kg * CGRP;
    const unsigned dA = (arow * SASTR + ak) * 2;
    const unsigned dB = (brow * SBSTR + bn) * 2;

    const int lane = t & 31;
    const int wid2 = (t >> 5) & 3;
    const int wm = wid2 & 1, wn = wid2 >> 1;

    unsigned offA[2], offB[2];
    {
        int r = lane & 15, c = (lane >> 4) * 8;
        offA[0] = ((wm * 32 + r) * SASTR + c) * 2;
        offA[1] = ((wm * 32 + 16 + r) * SASTR + c) * 2;
        int br = (lane & 7) + ((lane & 16) ? 8 : 0);
        int bc = (lane & 8) ? 8 : 0;
        offB[0] = (br * SBSTR + wn * 32 + bc) * 2;
        offB[1] = (br * SBSTR + wn * 32 + 16 + bc) * 2;
    }

    float acc[2][4][4];
    #pragma unroll
    for (int i = 0; i < 2; i++)
        #pragma unroll
        for (int j = 0; j < 4; j++)
            #pragma unroll
            for (int q = 0; q < 4; q++) acc[i][j][q] = 0.f;

    #pragma unroll
    for (int sg = 0; sg < NST - 1; sg++) {
        if (sg < ns) {
            unsigned bs = grpBase + sg * CSTAGE;
            size_t ko = (size_t)sg * 16;
            cpa16(bs + CG_AH + dA, gAh + ko);
            if (!aexact) cpa16(bs + CG_AL + dA, gAl + ko);
            cpa16(bs + CG_BH + dB, gBh + ko * N);
            cpa16(bs + CG_BL + dB, gBl + ko * N);
        }
        cpa_commit();
    }

    for (int s = 0; s < ns; s++) {
        cpa_wait<NST - 2>();
        __syncthreads();

        int sg = s + NST - 1;
        if (sg < ns) {
            unsigned bs = grpBase + (sg % NST) * CSTAGE;
            size_t ko = (size_t)sg * 16;
            cpa16(bs + CG_AH + dA, gAh + ko);
            if (!aexact) cpa16(bs + CG_AL + dA, gAl + ko);
            cpa16(bs + CG_BH + dB, gBh + ko * N);
            cpa16(bs + CG_BL + dB, gBl + ko * N);
        }
        cpa_commit();

        const unsigned bs = grpBase + (s % NST) * CSTAGE;
        unsigned aH[2][4], aL[2][4];
        ldsm4(aH[0], bs + CG_AH + offA[0]);
        ldsm4(aH[1], bs + CG_AH + offA[1]);
        if (!aexact) {
            ldsm4(aL[0], bs + CG_AL + offA[0]);
            ldsm4(aL[1], bs + CG_AL + offA[1]);
        }
        unsigned bH[4][2], bL[4][2];
        #pragma unroll
        for (int p = 0; p < 2; p++) {
            unsigned r[4];
            ldsm4t(r, bs + CG_BH + offB[p]);
            bH[2*p][0] = r[0]; bH[2*p][1] = r[2]; bH[2*p+1][0] = r[1]; bH[2*p+1][1] = r[3];
            ldsm4t(r, bs + CG_BL + offB[p]);
            bL[2*p][0] = r[0]; bL[2*p][1] = r[2]; bL[2*p+1][0] = r[1]; bL[2*p+1][1] = r[3];
        }
        #pragma unroll
        for (int mi = 0; mi < 2; mi++)
            #pragma unroll
            for (int ni = 0; ni < 4; ni++) {
                mma_bf16(acc[mi][ni], aH[mi], bH[ni]);
                mma_bf16(acc[mi][ni], aH[mi], bL[ni]);
            }
        if (!aexact) {
            #pragma unroll
            for (int mi = 0; mi < 2; mi++)
                #pragma unroll
                for (int ni = 0; ni < 4; ni++)
                    mma_bf16(acc[mi][ni], aL[mi], bH[ni]);
        }
    }

    __syncthreads();
    float* comb = (float*)sm;
    if (kg != 0) {
        int base = (kg - 1) * 4224 + t7 * 33;
        #pragma unroll
        for (int mi = 0; mi < 2; mi++)
            #pragma unroll
            for (int ni = 0; ni < 4; ni++)
                #pragma unroll
                for (int q = 0; q < 4; q++)
                    comb[base + mi * 16 + ni * 4 + q] = acc[mi][ni][q];
    }
    __syncthreads();
    if (kg == 0) {
        #pragma unroll
        for (int mi = 0; mi < 2; mi++) {
            int row = m0 + wm * 32 + mi * 16 + (lane >> 2);
            #pragma unroll
            for (int ni = 0; ni < 4; ni++) {
                int col = n0 + wn * 32 + ni * 8 + (lane & 3) * 2;
                float v[4];
                #pragma unroll
                for (int q = 0; q < 4; q++) {
                    int idx = mi * 16 + ni * 4 + q;
                    v[q] = acc[mi][ni][q]
                         + comb[0 * 4224 + t7 * 33 + idx]
                         + comb[1 * 4224 + t7 * 33 + idx]
                         + comb[2 * 4224 + t7 * 33 + idx];
                }
                if (epi) {
                    float2 b = *(const float2*)&bias[col];
                    v[0] += b.x; v[1] += b.y; v[2] += b.x; v[3] += b.y;
                }
                if (epi == 1) {
                    v[0] = fmaxf(v[0], 0.f); v[1] = fmaxf(v[1], 0.f);
                    v[2] = fmaxf(v[2], 0.f); v[3] = fmaxf(v[3], 0.f);
                }
                #pragma unroll
                for (int rr = 0; rr < 2; rr++) {
                    float x0 = v[rr * 2], x1 = v[rr * 2 + 1];
                    __nv_bfloat16 h0 = __float2bfloat16(x0), h1 = __float2bfloat16(x1);
                    __nv_bfloat162 Hp, Lp;
                    Hp.x = h0; Hp.y = h1;
                    Lp.x = __float2bfloat16(x0 - __bfloat162float(h0));
                    Lp.y = __float2bfloat16(x1 - __bfloat162float(h1));
                    size_t off = (size_t)(row + rr * 8) * N + col;
                    *(__nv_bfloat162*)&Ch[off] = Hp;
                    *(__nv_bfloat162*)&Cl[off] = Lp;
                }
            }
        }
    }
    __syncthreads();
}

// ---------------- persistent chain kernel (512 threads) ----------------
__global__ __launch_bounds__(CTHREADS)
void k_chain(const float* __restrict__ bs1a, const float* __restrict__ bs1b,
             const float* __restrict__ bs2a, const float* __restrict__ bs2b,
             const float* __restrict__ bc1a, const float* __restrict__ bc1b,
             const float* __restrict__ Wc2a, const float* __restrict__ bc2a,
             const float* __restrict__ Wc2b, const float* __restrict__ bc2b,
             const float* __restrict__ Wd, const float* __restrict__ bd,
             float* __restrict__ out)
{
    extern __shared__ char s_all[];
    __shared__ float dred[16];

    const int bid = blockIdx.x, t = threadIdx.x;
    const int gid = bid * CTHREADS + t;
    const int wid = t >> 5, lane = t & 31;

    // ---- phase 0: reduceP -> Ph/Pl ; convert B -> Bh ----
    #pragma unroll
    for (int j = 0; j < 2; j++) {
        int i = gid + j * 16384;
        float4 s = make_float4(0.f, 0.f, 0.f, 0.f);
        #pragma unroll
        for (int z = 0; z < SPLITKZ; z++) {
            float4 v = ((const float4*)g_Ppart)[(size_t)z * (NN * HH / 4) + i];
            s.x += v.x; s.y += v.y; s.z += v.z; s.w += v.w;
        }
        int e = i * 4;
        float f[4] = {s.x, s.y, s.z, s.w};
        union { __nv_bfloat16 b[4]; uint2 u; } H, L;
        #pragma unroll
        for (int q = 0; q < 4; q++) {
            __nv_bfloat16 h = __float2bfloat16(f[q]);
            H.b[q] = h; L.b[q] = __float2bfloat16(f[q] - __bfloat162float(h));
        }
        *(uint2*)&g_Ph[e] = H.u;
        *(uint2*)&g_Pl[e] = L.u;
    }
    if (gid < 8192) {
        float4 a = ((const float4*)g_B)[gid * 2], b = ((const float4*)g_B)[gid * 2 + 1];
        float f[8] = {a.x, a.y, a.z, a.w, b.x, b.y, b.z, b.w};
        union { __nv_bfloat16 v[8]; uint4 u; } H;
        #pragma unroll
        for (int q = 0; q < 8; q++) H.v[q] = __float2bfloat16(f[q]);
        ((uint4*)g_Bh)[gid] = H.u;
    }
    gbar();

    const int tx8 = bid & 7, ty8 = bid >> 3;
    const int tx4 = bid & 3, ty4 = bid >> 2;

    dgemm64(g_Bh, (const __nv_bfloat16*)0, g_Ph, g_Pl, bs1a, g_U1h, g_U1l,
            HH, NN, ty8 * 64, tx8 * 64, 1, 1, s_all);
    gbar();
    dgemm64(g_U1h, g_U1l, g_W1bh, g_W1bl, bs1b, g_hh, g_hl,
            HH, HH, ty8 * 64, tx8 * 64, 1, 0, s_all);
    gbar();
    if (bid < 16)
        dgemm64(g_hh, g_hl, g_W2ah, g_W2al, (const float*)0, g_Q2h, g_Q2l,
                LL, HH, ty4 * 64, tx4 * 64, 0, 0, s_all);
    gbar();
    if (bid < 16)
        dgemm64(g_Bh, (const __nv_bfloat16*)0, g_Q2h, g_Q2l, bs2a, g_U2h, g_U2l,
                LL, NN, ty4 * 64, tx4 * 64, 1, 1, s_all);
    gbar();
    if (bid < 16)
        dgemm64(g_U2h, g_U2l, g_W2bh, g_W2bl, bs2b, g_fh, g_fl,
                LL, LL, ty4 * 64, tx4 * 64, 2, 0, s_all);
    gbar();
    dgemm64(g_fh, g_fl, g_Wc1ah, g_Wc1al, (const float*)0, g_Q3h, g_Q3l,
            HH, LL, ty8 * 64, tx8 * 64, 0, 0, s_all);
    gbar();
    dgemm64(g_Bh, (const __nv_bfloat16*)0, g_Q3h, g_Q3l, bc1a, g_U3h, g_U3l,
            HH, NN, ty8 * 64, tx8 * 64, 1, 1, s_all);
    gbar();
    dgemm64(g_U3h, g_U3l, g_Wc1bh, g_Wc1bl, bc1b, g_sh2, g_sl2,
            HH, HH, ty8 * 64, tx8 * 64, 1, 0, s_all);
    gbar();

    if (wid < 8) {
        int row = bid * 8 + wid;
        float s = 0.f;
        for (int i = lane; i < HH; i += 32)
            s += (__bfloat162float(g_sh2[row * HH + i]) + __bfloat162float(g_sl2[row * HH + i])) * Wc2a[i];
        #pragma unroll
        for (int o = 16; o; o >>= 1) s += __shfl_down_sync(0xFFFFFFFFu, s, o);
        if (lane == 0) g_Q4[row] = s;
    }
    {
        float ds = 0.f;
        int base = bid * 2048;
        for (int i = t; i < 2048; i += CTHREADS)
            ds += (__bfloat162float(g_fh[base + i]) + __bfloat162float(g_fl[base + i])) * Wd[base + i];
        #pragma unroll
        for (int o = 16; o; o >>= 1) ds += __shfl_down_sync(0xFFFFFFFFu, ds, o);
        if (lane == 0) dred[wid] = ds;
        __syncthreads();
        if (t == 0) {
            float v = 0.f;
            #pragma unroll
            for (int j = 0; j < 16; j++) v += dred[j];
            g_dpart[bid] = v;
        }
    }
    gbar();

    if (wid < 8) {
        int row = bid * 8 + wid;
        float s = 0.f;
        for (int i = lane; i < NN; i += 32) s += g_B[row * NN + i] * g_Q4[i];
        #pragma unroll
        for (int o = 16; o; o >>= 1) s += __shfl_down_sync(0xFFFFFFFFu, s, o);
        if (lane == 0) {
            float u = fmaxf(s + bc2a[0], 0.f);
            float sc = u * Wc2b[0] + bc2b[0];
            out[1 + row] = 1.f / (1.f + expf(-sc));
        }
    }
    if (bid == 0 && wid == 0) {
        float v = g_dpart[lane];
        #pragma unroll
        for (int o = 16; o; o >>= 1) v += __shfl_down_sync(0xFFFFFFFFu, v, o);
        if (lane == 0) out[0] = 1.f / (1.f + expf(-(v + bd[0])));
    }
}

// ---------------- launch ----------------
extern "C" void kernel_launch(void* const* d_in, const int* in_sizes, int n_in,
                              void* d_out, int out_size) {
    const float* X    = (const float*)d_in[0];
    const int*   idx  = (const int*)d_in[1];
    const float* Ws1a = (const float*)d_in[3];
    const float* bs1a = (const float*)d_in[4];
    const float* Ws1b = (const float*)d_in[5];
    const float* bs1b = (const float*)d_in[6];
    const float* Ws2a = (const float*)d_in[7];
    const float* bs2a = (const float*)d_in[8];
    const float* Ws2b = (const float*)d_in[9];
    const float* bs2b = (const float*)d_in[10];
    const float* Wc1a = (const float*)d_in[11];
    const float* bc1a = (const float*)d_in[12];
    const float* Wc1b = (const float*)d_in[13];
    const float* bc1b = (const float*)d_in[14];
    const float* Wc2a = (const float*)d_in[15];
    const float* bc2a = (const float*)d_in[16];
    const float* Wc2b = (const float*)d_in[17];
    const float* bc2b = (const float*)d_in[18];
    const float* Wd   = (const float*)d_in[19];
    const float* bd   = (const float*)d_in[20];
    float* out = (float*)d_out;

    float* pPpart;
    cudaGetSymbolAddress((void**)&pPpart, g_Ppart);

    cudaFuncSetAttribute(bigmm3, cudaFuncAttributeMaxDynamicSharedMemorySize, SMEM_DYN2);
    cudaFuncSetAttribute(k_chain, cudaFuncAttributeMaxDynamicSharedMemorySize, CH_TOT2);

    k_cvt2<<<(N_TOT + 255) / 256, 256>>>(Ws1b, Ws2a, Ws2b, Wc1a, Wc1b);
    k_edges<<<(EE + 255) / 256, 256>>>(idx);
    bigmm3<<<dim3(4, 2, SPLITKZ), 256, SMEM_DYN2>>>(X, Ws1a, pPpart);
    k_chain<<<NCTA, CTHREADS, CH_TOT2>>>(bs1a, bs1b, bs2a, bs2b, bc1a, bc1b,
                                         Wc2a, bc2a, Wc2b, bc2b, Wd, bd, out);
}

// round 13
// speedup vs baseline: 1.3259x; 1.1749x over previous
#include <cuda_runtime.h>
#include <cuda_bf16.h>
#include <math.h>

#define NN 256
#define TT 30000
#define HH 512
#define LL 256
#define EE 32768

#define KSTEPS 1875
#define SPLITKZ 37
#define SPG 51

// bigmm bf16 buffer layout (within one 20992B buf)
#define ASTRIDE 24
#define BSTRIDE 136
#define ST_AH 0
#define ST_AL 6144
#define ST_BH 12288
#define ST_BL 16640
#define B16BUF 20992
// fp32 staging: 3 stages x (A 8192 + B 8192)
#define F32STG 16384
#define NF32 3
#define B16BASE (NF32 * F32STG)
#define SMEM_DYN2 (B16BASE + 2 * B16BUF)   // 91136

// chain gemm (32x64 tiles) smem layout — k16 stages, 4 K-groups
#define SASTR 24
#define SBSTR 72
#define NST 3
#define CG_AH 0
#define CG_AL 1536
#define CG_BH 3072
#define CG_BL 5376
#define CSTAGE 7680
#define CGRP (CSTAGE * NST)        // 23040 per K-group
#define NKG 4
#define CH_TOT3 (NKG * CGRP)       // 92160

#define NCTA 64
#define CTHREADS 512

// ---------------- device scratch ----------------
__device__ float g_B[NN * NN];
__device__ __nv_bfloat16 g_Bh[NN * NN];
__device__ float g_Ppart[SPLITKZ * NN * HH];
__device__ __nv_bfloat16 g_Ph[NN * HH], g_Pl[NN * HH];
__device__ __nv_bfloat16 g_U1h[NN * HH], g_U1l[NN * HH];
__device__ __nv_bfloat16 g_hh[NN * HH], g_hl[NN * HH];
__device__ __nv_bfloat16 g_Q2h[NN * LL], g_Q2l[NN * LL];
__device__ __nv_bfloat16 g_U2h[NN * LL], g_U2l[NN * LL];
__device__ __nv_bfloat16 g_fh[NN * LL], g_fl[NN * LL];
__device__ __nv_bfloat16 g_Q3h[NN * HH], g_Q3l[NN * HH];
__device__ __nv_bfloat16 g_U3h[NN * HH], g_U3l[NN * HH];
__device__ __nv_bfloat16 g_sh2[NN * HH], g_sl2[NN * HH];
__device__ __nv_bfloat16 g_W1bh[HH * HH], g_W1bl[HH * HH];
__device__ __nv_bfloat16 g_W2ah[HH * LL], g_W2al[HH * LL];
__device__ __nv_bfloat16 g_W2bh[LL * LL], g_W2bl[LL * LL];
__device__ __nv_bfloat16 g_Wc1ah[LL * HH], g_Wc1al[LL * HH];
__device__ __nv_bfloat16 g_Wc1bh[HH * HH], g_Wc1bl[HH * HH];
__device__ float g_Q4[NN];
__device__ float g_dpart[NCTA];
__device__ unsigned g_bar_cnt;
__device__ unsigned g_bar_gen;

// ---------------- weight conversion ----------------
#define N_W1B (HH * HH / 8)
#define N_W2A (HH * LL / 8)
#define N_W2B (LL * LL / 8)
#define N_WC1A (LL * HH / 8)
#define N_WC1B (HH * HH / 8)
#define N_CVT (N_W1B + N_W2A + N_W2B + N_WC1A + N_WC1B)
#define N_B4  (NN * NN / 4)

__device__ __forceinline__ void cvt8(const float* __restrict__ src,
                                     __nv_bfloat16* __restrict__ hi,
                                     __nv_bfloat16* __restrict__ lo, int j8) {
    float4 v0 = ((const float4*)src)[2 * j8], v1 = ((const float4*)src)[2 * j8 + 1];
    float f[8] = {v0.x, v0.y, v0.z, v0.w, v1.x, v1.y, v1.z, v1.w};
    union { __nv_bfloat16 b[8]; uint4 u; } H, L;
    #pragma unroll
    for (int j = 0; j < 8; j++) {
        __nv_bfloat16 h = __float2bfloat16(f[j]);
        H.b[j] = h; L.b[j] = __float2bfloat16(f[j] - __bfloat162float(h));
    }
    ((uint4*)hi)[j8] = H.u;
    ((uint4*)lo)[j8] = L.u;
}

__global__ void k_cvtW(const float* __restrict__ W1b, const float* __restrict__ W2a,
                       const float* __restrict__ W2b, const float* __restrict__ Wc1a,
                       const float* __restrict__ Wc1b) {
    int o = blockIdx.x * blockDim.x + threadIdx.x;
    if (o < N_W1B) { cvt8(W1b, g_W1bh, g_W1bl, o); return; }
    o -= N_W1B;
    if (o < N_W2A) { cvt8(W2a, g_W2ah, g_W2al, o); return; }
    o -= N_W2A;
    if (o < N_W2B) { cvt8(W2b, g_W2bh, g_W2bl, o); return; }
    o -= N_W2B;
    if (o < N_WC1A) { cvt8(Wc1a, g_Wc1ah, g_Wc1al, o); return; }
    o -= N_WC1A;
    if (o < N_WC1B) { cvt8(Wc1b, g_Wc1bh, g_Wc1bl, o); }
}

__global__ void k_initB2() {
    int o = blockIdx.x * blockDim.x + threadIdx.x;
    if (o < N_B4) {
        int e0 = o * 4;
        float4 v = make_float4(0.f, 0.f, 0.f, 0.f);
        float* pv = &v.x;
        #pragma unroll
        for (int q = 0; q < 4; q++) {
            int e = e0 + q;
            if ((e >> 8) == (e & 255)) pv[q] = 1.f;
        }
        ((float4*)g_B)[o] = v;
    }
}

__global__ void k_edges(const int* __restrict__ idx) {
    int e = blockIdx.x * blockDim.x + threadIdx.x;
    if (e < EE) atomicAdd(&g_B[idx[EE + e] * NN + idx[e]], 1.0f);
}

// ---------------- PTX helpers ----------------
__device__ __forceinline__ void mma_bf16(float* c, const unsigned* a, const unsigned* b) {
    asm volatile(
        "mma.sync.aligned.m16n8k16.row.col.f32.bf16.bf16.f32 "
        "{%0,%1,%2,%3},{%4,%5,%6,%7},{%8,%9},{%0,%1,%2,%3};"
        : "+f"(c[0]), "+f"(c[1]), "+f"(c[2]), "+f"(c[3])
        : "r"(a[0]), "r"(a[1]), "r"(a[2]), "r"(a[3]), "r"(b[0]), "r"(b[1]));
}
__device__ __forceinline__ void ldsm4(unsigned* r, unsigned addr) {
    asm volatile("ldmatrix.sync.aligned.m8n8.x4.shared.b16 {%0,%1,%2,%3},[%4];"
                 : "=r"(r[0]), "=r"(r[1]), "=r"(r[2]), "=r"(r[3]) : "r"(addr));
}
__device__ __forceinline__ void ldsm4t(unsigned* r, unsigned addr) {
    asm volatile("ldmatrix.sync.aligned.m8n8.x4.trans.shared.b16 {%0,%1,%2,%3},[%4];"
                 : "=r"(r[0]), "=r"(r[1]), "=r"(r[2]), "=r"(r[3]) : "r"(addr));
}
__device__ __forceinline__ void cpa16(unsigned dst, const void* src) {
    asm volatile("cp.async.cg.shared.global [%0], [%1], 16;" :: "r"(dst), "l"(src));
}
__device__ __forceinline__ void cpa8(unsigned dst, const void* src) {
    asm volatile("cp.async.ca.shared.global [%0], [%1], 8;" :: "r"(dst), "l"(src));
}
__device__ __forceinline__ void cpa_commit() { asm volatile("cp.async.commit_group;"); }
template <int N> __device__ __forceinline__ void cpa_wait() {
    asm volatile("cp.async.wait_group %0;" :: "n"(N));
}

// ---------------- in-kernel fp32 -> bf16 hi/lo stage conversion (bigmm) ----------------
__device__ __forceinline__ void cvt_stage(char* f32s, char* b16s, int t) {
    const int arow = t >> 1, half = t & 1;
    {
        float4 a0 = *(float4*)(f32s + arow * 64 + half * 32);
        float4 a1 = *(float4*)(f32s + arow * 64 + half * 32 + 16);
        float f[8] = {a0.x, a0.y, a0.z, a0.w, a1.x, a1.y, a1.z, a1.w};
        union { __nv_bfloat16 b[8]; uint4 u; } H, L;
        #pragma unroll
        for (int j = 0; j < 8; j++) {
            __nv_bfloat16 h = __float2bfloat16(f[j]);
            H.b[j] = h; L.b[j] = __float2bfloat16(f[j] - __bfloat162float(h));
        }
        *(uint4*)(b16s + ST_AH + (arow * ASTRIDE + half * 8) * 2) = H.u;
        *(uint4*)(b16s + ST_AL + (arow * ASTRIDE + half * 8) * 2) = L.u;
    }
    {
        const int brow = t >> 4, bc = (t & 15) * 8;
        float4 b0 = *(float4*)(f32s + 8192 + brow * 512 + bc * 4);
        float4 b1 = *(float4*)(f32s + 8192 + brow * 512 + bc * 4 + 16);
        float f[8] = {b0.x, b0.y, b0.z, b0.w, b1.x, b1.y, b1.z, b1.w};
        union { __nv_bfloat16 b[8]; uint4 u; } H, L;
        #pragma unroll
        for (int j = 0; j < 8; j++) {
            __nv_bfloat16 h = __float2bfloat16(f[j]);
            H.b[j] = h; L.b[j] = __float2bfloat16(f[j] - __bfloat162float(h));
        }
        *(uint4*)(b16s + ST_BH + (brow * BSTRIDE + bc) * 2) = H.u;
        *(uint4*)(b16s + ST_BL + (brow * BSTRIDE + bc) * 2) = L.u;
    }
}

// ---------------- big GEMM (unchanged from R12 passing) ----------------
__global__ __launch_bounds__(256, 2)
void bigmm3(const float* __restrict__ X, const float* __restrict__ W, float* __restrict__ Ppart)
{
    extern __shared__ char dyn[];
    const unsigned sb = (unsigned)__cvta_generic_to_shared(dyn);

    const int t = threadIdx.x;
    const int m0 = blockIdx.y * 128, n0 = blockIdx.x * 128, z = blockIdx.z;
    const int s0 = z * SPG;
    const int ns = min(SPG, KSTEPS - s0);

    const int arow = t >> 1, ahalf = t & 1;
    const int brow = t >> 4, bcol = (t & 15) * 8;
    const float* gA = X + (size_t)(m0 + arow) * TT + (size_t)s0 * 16 + ahalf * 8;
    const float* gB = W + (size_t)((size_t)s0 * 16 + brow) * HH + n0 + bcol;
    const unsigned dA32 = arow * 64 + ahalf * 32;
    const unsigned dB32 = 8192 + brow * 512 + bcol * 4;

    const int lane = t & 31, wid = t >> 5;
    const int wm = wid & 3, wn = wid >> 2;
    unsigned offA[2], offB[4];
    {
        int r = lane & 15, c = (lane >> 4) * 8;
        offA[0] = ((wm * 32 + r) * ASTRIDE + c) * 2;
        offA[1] = ((wm * 32 + 16 + r) * ASTRIDE + c) * 2;
        int br = (lane & 7) + ((lane & 16) ? 8 : 0);
        int bc = (lane & 8) ? 8 : 0;
        #pragma unroll
        for (int p = 0; p < 4; p++)
            offB[p] = (br * BSTRIDE + wn * 64 + p * 16 + bc) * 2;
    }

    float acc[2][8][4];
    #pragma unroll
    for (int i = 0; i < 2; i++)
        #pragma unroll
        for (int j = 0; j < 8; j++)
            #pragma unroll
            for (int q = 0; q < 4; q++) acc[i][j][q] = 0.f;

    #pragma unroll
    for (int sg = 0; sg < 2; sg++) {
        if (sg < ns) {
            unsigned fb = sb + sg * F32STG;
            cpa16(fb + dA32,      gA + (size_t)sg * 16);
            cpa16(fb + dA32 + 16, gA + (size_t)sg * 16 + 4);
            cpa16(fb + dB32,      gB + (size_t)sg * 16 * HH);
            cpa16(fb + dB32 + 16, gB + (size_t)sg * 16 * HH + 4);
        }
        cpa_commit();
    }
    cpa_wait<1>();
    __syncthreads();
    cvt_stage(dyn, dyn + B16BASE, t);

    for (int s = 0; s < ns; s++) {
        int sg = s + 2;
        if (sg < ns) {
            unsigned fb = sb + (sg % NF32) * F32STG;
            cpa16(fb + dA32,      gA + (size_t)sg * 16);
            cpa16(fb + dA32 + 16, gA + (size_t)sg * 16 + 4);
            cpa16(fb + dB32,      gB + (size_t)sg * 16 * HH);
            cpa16(fb + dB32 + 16, gB + (size_t)sg * 16 * HH + 4);
        }
        cpa_commit();
        cpa_wait<1>();
        __syncthreads();

        if (s + 1 < ns)
            cvt_stage(dyn + ((s + 1) % NF32) * F32STG,
                      dyn + B16BASE + ((s + 1) & 1) * B16BUF, t);

        const unsigned base = sb + B16BASE + (s & 1) * B16BUF;
        unsigned aH[2][4], aL[2][4];
        ldsm4(aH[0], base + ST_AH + offA[0]);
        ldsm4(aH[1], base + ST_AH + offA[1]);
        ldsm4(aL[0], base + ST_AL + offA[0]);
        ldsm4(aL[1], base + ST_AL + offA[1]);
        #pragma unroll
        for (int p = 0; p < 4; p++) {
            unsigned r[4], q[4];
            ldsm4t(r, base + ST_BH + offB[p]);
            ldsm4t(q, base + ST_BL + offB[p]);
            unsigned bh0[2] = {r[0], r[2]}, bh1[2] = {r[1], r[3]};
            unsigned bl0[2] = {q[0], q[2]}, bl1[2] = {q[1], q[3]};
            #pragma unroll
            for (int mi = 0; mi < 2; mi++) {
                mma_bf16(acc[mi][2 * p],     aH[mi], bh0);
                mma_bf16(acc[mi][2 * p],     aH[mi], bl0);
                mma_bf16(acc[mi][2 * p],     aL[mi], bh0);
                mma_bf16(acc[mi][2 * p + 1], aH[mi], bh1);
                mma_bf16(acc[mi][2 * p + 1], aH[mi], bl1);
                mma_bf16(acc[mi][2 * p + 1], aL[mi], bh1);
            }
        }
        __syncthreads();
    }

    float* Po = Ppart + (size_t)z * NN * HH;
    #pragma unroll
    for (int mi = 0; mi < 2; mi++) {
        int row = m0 + wm * 32 + mi * 16 + (lane >> 2);
        #pragma unroll
        for (int ni = 0; ni < 8; ni++) {
            int col = n0 + wn * 64 + ni * 8 + (lane & 3) * 2;
            *(float2*)&Po[(size_t)row * HH + col]       = make_float2(acc[mi][ni][0], acc[mi][ni][1]);
            *(float2*)&Po[(size_t)(row + 8) * HH + col] = make_float2(acc[mi][ni][2], acc[mi][ni][3]);
        }
    }
}

// ---------------- device-wide barrier ----------------
__device__ __forceinline__ void gbar() {
    __syncthreads();
    if (threadIdx.x == 0) {
        __threadfence();
        unsigned old = *(volatile unsigned*)&g_bar_gen;
        unsigned a = atomicAdd(&g_bar_cnt, 1u);
        if (a == NCTA - 1) {
            g_bar_cnt = 0;
            __threadfence();
            *(volatile unsigned*)&g_bar_gen = old + 1;
        } else {
            while (*(volatile unsigned*)&g_bar_gen == old) { }
        }
        __threadfence();
    }
    __syncthreads();
}

// ---------------- 32x64 tile GEMM: 512 threads, 4-way warp-split-K ----------------
__device__ void dgemm32(const __nv_bfloat16* __restrict__ Ah, const __nv_bfloat16* __restrict__ Al,
                        const __nv_bfloat16* __restrict__ Bh, const __nv_bfloat16* __restrict__ Bl,
                        const float* __restrict__ bias,
                        __nv_bfloat16* __restrict__ Ch, __nv_bfloat16* __restrict__ Cl,
                        int N, int K, int m0, int n0, int epi, int aexact, char* sm)
{
    const int t = threadIdx.x;
    const int kg = t >> 7, t7 = t & 127;
    const int Kq = K >> 2;
    const int ns = Kq >> 4;

    const int arow = t7 >> 2, ak = (t7 & 3) * 4;   // 32 rows x 4-elem chunks
    const int brow = t7 >> 3, bn = (t7 & 7) * 8;
    const __nv_bfloat16* gAh = Ah + (size_t)(m0 + arow) * K + kg * Kq + ak;
    const __nv_bfloat16* gAl = aexact ? gAh : (Al + (size_t)(m0 + arow) * K + kg * Kq + ak);
    const __nv_bfloat16* gBh = Bh + (size_t)(kg * Kq + brow) * N + n0 + bn;
    const __nv_bfloat16* gBl = Bl + (size_t)(kg * Kq + brow) * N + n0 + bn;

    const unsigned grpBase = (unsigned)__cvta_generic_to_shared(sm) + kg * CGRP;
    const unsigned dA = (arow * SASTR + ak) * 2;
    const unsigned dB = (brow * SBSTR + bn) * 2;

    const int lane = t & 31;
    const int wid2 = (t >> 5) & 3;
    const int wm = wid2 & 1, wn = wid2 >> 1;       // m16 x n32 per warp

    unsigned offA0, offB[2];
    {
        int r = lane & 15, c = (lane >> 4) * 8;
        offA0 = ((wm * 16 + r) * SASTR + c) * 2;
        int br = (lane & 7) + ((lane & 16) ? 8 : 0);
        int bc = (lane & 8) ? 8 : 0;
        offB[0] = (br * SBSTR + wn * 32 + bc) * 2;
        offB[1] = (br * SBSTR + wn * 32 + 16 + bc) * 2;
    }

    float acc[4][4];
    #pragma unroll
    for (int j = 0; j < 4; j++)
        #pragma unroll
        for (int q = 0; q < 4; q++) acc[j][q] = 0.f;

    #pragma unroll
    for (int sg = 0; sg < NST - 1; sg++) {
        if (sg < ns) {
            unsigned bs = grpBase + sg * CSTAGE;
            size_t ko = (size_t)sg * 16;
            cpa8(bs + CG_AH + dA, gAh + ko);
            if (!aexact) cpa8(bs + CG_AL + dA, gAl + ko);
            cpa16(bs + CG_BH + dB, gBh + ko * N);
            cpa16(bs + CG_BL + dB, gBl + ko * N);
        }
        cpa_commit();
    }

    for (int s = 0; s < ns; s++) {
        cpa_wait<NST - 2>();
        __syncthreads();

        int sg = s + NST - 1;
        if (sg < ns) {
            unsigned bs = grpBase + (sg % NST) * CSTAGE;
            size_t ko = (size_t)sg * 16;
            cpa8(bs + CG_AH + dA, gAh + ko);
            if (!aexact) cpa8(bs + CG_AL + dA, gAl + ko);
            cpa16(bs + CG_BH + dB, gBh + ko * N);
            cpa16(bs + CG_BL + dB, gBl + ko * N);
        }
        cpa_commit();

        const unsigned bs = grpBase + (s % NST) * CSTAGE;
        unsigned aH[4], aL[4];
        ldsm4(aH, bs + CG_AH + offA0);
        if (!aexact) ldsm4(aL, bs + CG_AL + offA0);
        unsigned bH[4][2], bL[4][2];
        #pragma unroll
        for (int p = 0; p < 2; p++) {
            unsigned r[4];
            ldsm4t(r, bs + CG_BH + offB[p]);
            bH[2*p][0] = r[0]; bH[2*p][1] = r[2]; bH[2*p+1][0] = r[1]; bH[2*p+1][1] = r[3];
            ldsm4t(r, bs + CG_BL + offB[p]);
            bL[2*p][0] = r[0]; bL[2*p][1] = r[2]; bL[2*p+1][0] = r[1]; bL[2*p+1][1] = r[3];
        }
        #pragma unroll
        for (int ni = 0; ni < 4; ni++) {
            mma_bf16(acc[ni], aH, bH[ni]);
            mma_bf16(acc[ni], aH, bL[ni]);
        }
        if (!aexact) {
            #pragma unroll
            for (int ni = 0; ni < 4; ni++)
                mma_bf16(acc[ni], aL, bH[ni]);
        }
    }

    // combine 4 K-groups through smem (deterministic order)
    __syncthreads();
    float* comb = (float*)sm;
    if (kg != 0) {
        int base = (kg - 1) * 2176 + t7 * 17;
        #pragma unroll
        for (int ni = 0; ni < 4; ni++)
            #pragma unroll
            for (int q = 0; q < 4; q++)
                comb[base + ni * 4 + q] = acc[ni][q];
    }
    __syncthreads();
    if (kg == 0) {
        int row = m0 + wm * 16 + (lane >> 2);
        #pragma unroll
        for (int ni = 0; ni < 4; ni++) {
            int col = n0 + wn * 32 + ni * 8 + (lane & 3) * 2;
            float v[4];
            #pragma unroll
            for (int q = 0; q < 4; q++) {
                int idx = ni * 4 + q;
                v[q] = acc[ni][q]
                     + comb[0 * 2176 + t7 * 17 + idx]
                     + comb[1 * 2176 + t7 * 17 + idx]
                     + comb[2 * 2176 + t7 * 17 + idx];
            }
            if (epi) {
                float2 b = *(const float2*)&bias[col];
                v[0] += b.x; v[1] += b.y; v[2] += b.x; v[3] += b.y;
            }
            if (epi == 1) {
                v[0] = fmaxf(v[0], 0.f); v[1] = fmaxf(v[1], 0.f);
                v[2] = fmaxf(v[2], 0.f); v[3] = fmaxf(v[3], 0.f);
            }
            #pragma unroll
            for (int rr = 0; rr < 2; rr++) {
                float x0 = v[rr * 2], x1 = v[rr * 2 + 1];
                __nv_bfloat16 h0 = __float2bfloat16(x0), h1 = __float2bfloat16(x1);
                __nv_bfloat162 Hp, Lp;
                Hp.x = h0; Hp.y = h1;
                Lp.x = __float2bfloat16(x0 - __bfloat162float(h0));
                Lp.y = __float2bfloat16(x1 - __bfloat162float(h1));
                size_t off = (size_t)(row + rr * 8) * N + col;
                *(__nv_bfloat162*)&Ch[off] = Hp;
                *(__nv_bfloat162*)&Cl[off] = Lp;
            }
        }
    }
    __syncthreads();
}

// ---------------- persistent chain kernel (64 CTAs x 512 threads) ----------------
__global__ __launch_bounds__(CTHREADS)
void k_chain(const float* __restrict__ bs1a, const float* __restrict__ bs1b,
             const float* __restrict__ bs2a, const float* __restrict__ bs2b,
             const float* __restrict__ bc1a, const float* __restrict__ bc1b,
             const float* __restrict__ Wc2a, const float* __restrict__ bc2a,
             const float* __restrict__ Wc2b, const float* __restrict__ bc2b,
             const float* __restrict__ Wd, const float* __restrict__ bd,
             float* __restrict__ out)
{
    extern __shared__ char s_all[];
    __shared__ float dred[16];

    const int bid = blockIdx.x, t = threadIdx.x;
    const int gid = bid * CTHREADS + t;            // 0..32767
    const int wid = t >> 5, lane = t & 31;

    // ---- phase 0: reduceP -> Ph/Pl ; convert B -> Bh ----
    {
        int i = gid;                                // 32768 float4 exactly
        float4 s = make_float4(0.f, 0.f, 0.f, 0.f);
        #pragma unroll
        for (int z = 0; z < SPLITKZ; z++) {
            float4 v = ((const float4*)g_Ppart)[(size_t)z * (NN * HH / 4) + i];
            s.x += v.x; s.y += v.y; s.z += v.z; s.w += v.w;
        }
        int e = i * 4;
        float f[4] = {s.x, s.y, s.z, s.w};
        union { __nv_bfloat16 b[4]; uint2 u; } H, L;
        #pragma unroll
        for (int q = 0; q < 4; q++) {
            __nv_bfloat16 h = __float2bfloat16(f[q]);
            H.b[q] = h; L.b[q] = __float2bfloat16(f[q] - __bfloat162float(h));
        }
        *(uint2*)&g_Ph[e] = H.u;
        *(uint2*)&g_Pl[e] = L.u;
    }
    if (gid < 8192) {
        float4 a = ((const float4*)g_B)[gid * 2], b = ((const float4*)g_B)[gid * 2 + 1];
        float f[8] = {a.x, a.y, a.z, a.w, b.x, b.y, b.z, b.w};
        union { __nv_bfloat16 v[8]; uint4 u; } H;
        #pragma unroll
        for (int q = 0; q < 8; q++) H.v[q] = __float2bfloat16(f[q]);
        ((uint4*)g_Bh)[gid] = H.u;
    }
    gbar();

    // tile coords: big GEMMs 8m x 8n; small 8m x 4n
    const int tx8 = bid & 7, ty8 = bid >> 3;
    const int tx4 = bid & 3, ty4 = bid >> 2;

    // G1: U1 = relu(B @ P + bs1a)   K=256, A exact
    dgemm32(g_Bh, (const __nv_bfloat16*)0, g_Ph, g_Pl, bs1a, g_U1h, g_U1l,
            HH, NN, ty8 * 32, tx8 * 64, 1, 1, s_all);
    gbar();
    // G2: h = relu(U1 @ Ws1b + bs1b)  K=512
    dgemm32(g_U1h, g_U1l, g_W1bh, g_W1bl, bs1b, g_hh, g_hl,
            HH, HH, ty8 * 32, tx8 * 64, 1, 0, s_all);
    gbar();
    // G3: Q2 = h @ Ws2a   K=512   (32 tiles)
    if (bid < 32)
        dgemm32(g_hh, g_hl, g_W2ah, g_W2al, (const float*)0, g_Q2h, g_Q2l,
                LL, HH, ty4 * 32, tx4 * 64, 0, 0, s_all);
    gbar();
    // G4: U2 = relu(B @ Q2 + bs2a)  K=256, A exact
    if (bid < 32)
        dgemm32(g_Bh, (const __nv_bfloat16*)0, g_Q2h, g_Q2l, bs2a, g_U2h, g_U2l,
                LL, NN, ty4 * 32, tx4 * 64, 1, 1, s_all);
    gbar();
    // G5: feat = U2 @ Ws2b + bs2b   K=256
    if (bid < 32)
        dgemm32(g_U2h, g_U2l, g_W2bh, g_W2bl, bs2b, g_fh, g_fl,
                LL, LL, ty4 * 32, tx4 * 64, 2, 0, s_all);
    gbar();
    // G6: Q3 = feat @ Wc1a   K=256
    dgemm32(g_fh, g_fl, g_Wc1ah, g_Wc1al, (const float*)0, g_Q3h, g_Q3l,
            HH, LL, ty8 * 32, tx8 * 64, 0, 0, s_all);
    gbar();
    // G7: U3 = relu(B @ Q3 + bc1a)  K=256, A exact
    dgemm32(g_Bh, (const __nv_bfloat16*)0, g_Q3h, g_Q3l, bc1a, g_U3h, g_U3l,
            HH, NN, ty8 * 32, tx8 * 64, 1, 1, s_all);
    gbar();
    // G8: s = relu(U3 @ Wc1b + bc1b)  K=512
    dgemm32(g_U3h, g_U3l, g_Wc1bh, g_Wc1bl, bc1b, g_sh2, g_sl2,
            HH, HH, ty8 * 32, tx8 * 64, 1, 0, s_all);
    gbar();

    // ---- q4 + dementia partials ----
    if (wid < 4) {
        int row = bid * 4 + wid;
        float s = 0.f;
        for (int i = lane; i < HH; i += 32)
            s += (__bfloat162float(g_sh2[row * HH + i]) + __bfloat162float(g_sl2[row * HH + i])) * Wc2a[i];
        #pragma unroll
        for (int o = 16; o; o >>= 1) s += __shfl_down_sync(0xFFFFFFFFu, s, o);
        if (lane == 0) g_Q4[row] = s;
    }
    {
        float ds = 0.f;
        int base = bid * 1024;
        for (int i = t; i < 1024; i += CTHREADS)
            ds += (__bfloat162float(g_fh[base + i]) + __bfloat162float(g_fl[base + i])) * Wd[base + i];
        #pragma unroll
        for (int o = 16; o; o >>= 1) ds += __shfl_down_sync(0xFFFFFFFFu, ds, o);
        if (lane == 0) dred[wid] = ds;
        __syncthreads();
        if (t == 0) {
            float v = 0.f;
            #pragma unroll
            for (int j = 0; j < 16; j++) v += dred[j];
            g_dpart[bid] = v;
        }
    }
    gbar();

    // ---- region scores + dementia combine ----
    if (wid < 4) {
        int row = bid * 4 + wid;
        float s = 0.f;
        for (int i = lane; i < NN; i += 32) s += g_B[row * NN + i] * g_Q4[i];
        #pragma unroll
        for (int o = 16; o; o >>= 1) s += __shfl_down_sync(0xFFFFFFFFu, s, o);
        if (lane == 0) {
            float u = fmaxf(s + bc2a[0], 0.f);
            float sc = u * Wc2b[0] + bc2b[0];
            out[1 + row] = 1.f / (1.f + expf(-sc));
        }
    }
    if (bid == 0 && wid == 0) {
        float v = g_dpart[lane] + g_dpart[lane + 32];
        #pragma unroll
        for (int o = 16; o; o >>= 1) v += __shfl_down_sync(0xFFFFFFFFu, v, o);
        if (lane == 0) out[0] = 1.f / (1.f + expf(-(v + bd[0])));
    }
}

// ---------------- launch ----------------
extern "C" void kernel_launch(void* const* d_in, const int* in_sizes, int n_in,
                              void* d_out, int out_size) {
    const float* X    = (const float*)d_in[0];
    const int*   idx  = (const int*)d_in[1];
    const float* Ws1a = (const float*)d_in[3];
    const float* bs1a = (const float*)d_in[4];
    const float* Ws1b = (const float*)d_in[5];
    const float* bs1b = (const float*)d_in[6];
    const float* Ws2a = (const float*)d_in[7];
    const float* bs2a = (const float*)d_in[8];
    const float* Ws2b = (const float*)d_in[9];
    const float* bs2b = (const float*)d_in[10];
    const float* Wc1a = (const float*)d_in[11];
    const float* bc1a = (const float*)d_in[12];
    const float* Wc1b = (const float*)d_in[13];
    const float* bc1b = (const float*)d_in[14];
    const float* Wc2a = (const float*)d_in[15];
    const float* bc2a = (const float*)d_in[16];
    const float* Wc2b = (const float*)d_in[17];
    const float* bc2b = (const float*)d_in[18];
    const float* Wd   = (const float*)d_in[19];
    const float* bd   = (const float*)d_in[20];
    float* out = (float*)d_out;

    float* pPpart;
    cudaGetSymbolAddress((void**)&pPpart, g_Ppart);

    cudaFuncSetAttribute(bigmm3, cudaFuncAttributeMaxDynamicSharedMemorySize, SMEM_DYN2);
    cudaFuncSetAttribute(k_chain, cudaFuncAttributeMaxDynamicSharedMemorySize, CH_TOT3);

    // order chosen so bigmm3 is launch #4 (the slot ncu captures)
    k_cvtW<<<(N_CVT + 255) / 256, 256>>>(Ws1b, Ws2a, Ws2b, Wc1a, Wc1b);   // 1
    k_initB2<<<(N_B4 + 255) / 256, 256>>>();                               // 2
    k_edges<<<(EE + 255) / 256, 256>>>(idx);                               // 3
    bigmm3<<<dim3(4, 2, SPLITKZ), 256, SMEM_DYN2>>>(X, Ws1a, pPpart);      // 4
    k_chain<<<NCTA, CTHREADS, CH_TOT3>>>(bs1a, bs1b, bs2a, bs2b, bc1a, bc1b,
                                         Wc2a, bc2a, Wc2b, bc2b, Wd, bd, out);
}

// round 15
// speedup vs baseline: 1.4032x; 1.0583x over previous
#include <cuda_runtime.h>
#include <cuda_bf16.h>
#include <math.h>

#define NN 256
#define TT 30000
#define HH 512
#define LL 256
#define EE 32768

#define KSTEPS 1875
#define SPLITKZ 37
#define SPG 51

// bigmm bf16 buffer layout (within one 20992B buf)
#define ASTRIDE 24
#define BSTRIDE 136
#define ST_AH 0
#define ST_AL 6144
#define ST_BH 12288
#define ST_BL 16640
#define B16BUF 20992
#define SMEM_DYN3 (2 * B16BUF)     // 41984

// chain gemm (32x64 tiles) smem layout — k16 stages, 4 K-groups
#define SASTR 24
#define SBSTR 72
#define NST 3
#define CG_AH 0
#define CG_AL 1536
#define CG_BH 3072
#define CG_BL 5376
#define CSTAGE 7680
#define CGRP (CSTAGE * NST)
#define NKG 4
#define CH_TOT3 (NKG * CGRP)       // 92160

#define NCTA 64
#define CTHREADS 512

// ---------------- device scratch ----------------
__device__ float g_B[NN * NN];
__device__ __nv_bfloat16 g_Bh[NN * NN];
__device__ float g_Ppart[SPLITKZ * NN * HH];
__device__ __nv_bfloat16 g_Ph[NN * HH], g_Pl[NN * HH];
__device__ __nv_bfloat16 g_U1h[NN * HH], g_U1l[NN * HH];
__device__ __nv_bfloat16 g_hh[NN * HH], g_hl[NN * HH];
__device__ __nv_bfloat16 g_Q2h[NN * LL], g_Q2l[NN * LL];
__device__ __nv_bfloat16 g_U2h[NN * LL], g_U2l[NN * LL];
__device__ __nv_bfloat16 g_fh[NN * LL], g_fl[NN * LL];
__device__ __nv_bfloat16 g_Q3h[NN * HH], g_Q3l[NN * HH];
__device__ __nv_bfloat16 g_U3h[NN * HH], g_U3l[NN * HH];
__device__ __nv_bfloat16 g_sh2[NN * HH], g_sl2[NN * HH];
__device__ __nv_bfloat16 g_W1bh[HH * HH], g_W1bl[HH * HH];
__device__ __nv_bfloat16 g_W2ah[HH * LL], g_W2al[HH * LL];
__device__ __nv_bfloat16 g_W2bh[LL * LL], g_W2bl[LL * LL];
__device__ __nv_bfloat16 g_Wc1ah[LL * HH], g_Wc1al[LL * HH];
__device__ __nv_bfloat16 g_Wc1bh[HH * HH], g_Wc1bl[HH * HH];
__device__ float g_Q4[NN];
__device__ float g_dpart[NCTA];
__device__ unsigned g_bar_cnt;
__device__ unsigned g_bar_gen;

// ---------------- weight conversion ----------------
#define N_W1B (HH * HH / 8)
#define N_W2A (HH * LL / 8)
#define N_W2B (LL * LL / 8)
#define N_WC1A (LL * HH / 8)
#define N_WC1B (HH * HH / 8)
#define N_CVT (N_W1B + N_W2A + N_W2B + N_WC1A + N_WC1B)
#define N_B4  (NN * NN / 4)

__device__ __forceinline__ void cvt8(const float* __restrict__ src,
                                     __nv_bfloat16* __restrict__ hi,
                                     __nv_bfloat16* __restrict__ lo, int j8) {
    float4 v0 = ((const float4*)src)[2 * j8], v1 = ((const float4*)src)[2 * j8 + 1];
    float f[8] = {v0.x, v0.y, v0.z, v0.w, v1.x, v1.y, v1.z, v1.w};
    union { __nv_bfloat16 b[8]; uint4 u; } H, L;
    #pragma unroll
    for (int j = 0; j < 8; j++) {
        __nv_bfloat16 h = __float2bfloat16(f[j]);
        H.b[j] = h; L.b[j] = __float2bfloat16(f[j] - __bfloat162float(h));
    }
    ((uint4*)hi)[j8] = H.u;
    ((uint4*)lo)[j8] = L.u;
}

__global__ void k_cvtW(const float* __restrict__ W1b, const float* __restrict__ W2a,
                       const float* __restrict__ W2b, const float* __restrict__ Wc1a,
                       const float* __restrict__ Wc1b) {
    int o = blockIdx.x * blockDim.x + threadIdx.x;
    if (o < N_W1B) { cvt8(W1b, g_W1bh, g_W1bl, o); return; }
    o -= N_W1B;
    if (o < N_W2A) { cvt8(W2a, g_W2ah, g_W2al, o); return; }
    o -= N_W2A;
    if (o < N_W2B) { cvt8(W2b, g_W2bh, g_W2bl, o); return; }
    o -= N_W2B;
    if (o < N_WC1A) { cvt8(Wc1a, g_Wc1ah, g_Wc1al, o); return; }
    o -= N_WC1A;
    if (o < N_WC1B) { cvt8(Wc1b, g_Wc1bh, g_Wc1bl, o); }
}

__global__ void k_initB2() {
    int o = blockIdx.x * blockDim.x + threadIdx.x;
    if (o < N_B4) {
        int e0 = o * 4;
        float4 v = make_float4(0.f, 0.f, 0.f, 0.f);
        float* pv = &v.x;
        #pragma unroll
        for (int q = 0; q < 4; q++) {
            int e = e0 + q;
            if ((e >> 8) == (e & 255)) pv[q] = 1.f;
        }
        ((float4*)g_B)[o] = v;
    }
}

__global__ void k_edges(const int* __restrict__ idx) {
    int e = blockIdx.x * blockDim.x + threadIdx.x;
    if (e < EE) atomicAdd(&g_B[idx[EE + e] * NN + idx[e]], 1.0f);
}

// ---------------- PTX helpers ----------------
__device__ __forceinline__ void mma_bf16(float* c, const unsigned* a, const unsigned* b) {
    asm volatile(
        "mma.sync.aligned.m16n8k16.row.col.f32.bf16.bf16.f32 "
        "{%0,%1,%2,%3},{%4,%5,%6,%7},{%8,%9},{%0,%1,%2,%3};"
        : "+f"(c[0]), "+f"(c[1]), "+f"(c[2]), "+f"(c[3])
        : "r"(a[0]), "r"(a[1]), "r"(a[2]), "r"(a[3]), "r"(b[0]), "r"(b[1]));
}
__device__ __forceinline__ void ldsm4(unsigned* r, unsigned addr) {
    asm volatile("ldmatrix.sync.aligned.m8n8.x4.shared.b16 {%0,%1,%2,%3},[%4];"
                 : "=r"(r[0]), "=r"(r[1]), "=r"(r[2]), "=r"(r[3]) : "r"(addr));
}
__device__ __forceinline__ void ldsm4t(unsigned* r, unsigned addr) {
    asm volatile("ldmatrix.sync.aligned.m8n8.x4.trans.shared.b16 {%0,%1,%2,%3},[%4];"
                 : "=r"(r[0]), "=r"(r[1]), "=r"(r[2]), "=r"(r[3]) : "r"(addr));
}
__device__ __forceinline__ void cpa16(unsigned dst, const void* src) {
    asm volatile("cp.async.cg.shared.global [%0], [%1], 16;" :: "r"(dst), "l"(src));
}
__device__ __forceinline__ void cpa8(unsigned dst, const void* src) {
    asm volatile("cp.async.ca.shared.global [%0], [%1], 8;" :: "r"(dst), "l"(src));
}
__device__ __forceinline__ void cpa_commit() { asm volatile("cp.async.commit_group;"); }
template <int N> __device__ __forceinline__ void cpa_wait() {
    asm volatile("cp.async.wait_group %0;" :: "n"(N));
}

// ---------------- big GEMM: LDG register prefetch + in-reg convert + STS ----------------
__global__ __launch_bounds__(256, 2)
void bigmm4(const float* __restrict__ X, const float* __restrict__ W, float* __restrict__ Ppart)
{
    extern __shared__ char dyn[];
    const unsigned sb = (unsigned)__cvta_generic_to_shared(dyn);

    const int t = threadIdx.x;
    const int m0 = blockIdx.y * 128, n0 = blockIdx.x * 128, z = blockIdx.z;
    const int s0 = z * SPG;
    const int ns = min(SPG, KSTEPS - s0);

    const int arow = t >> 1, ahalf = t & 1;
    const int brow = t >> 4, bcol = (t & 15) * 8;
    const float* gA = X + (size_t)(m0 + arow) * TT + (size_t)s0 * 16 + ahalf * 8;
    const float* gB = W + (size_t)((size_t)s0 * 16 + brow) * HH + n0 + bcol;
    const unsigned dA = (arow * ASTRIDE + ahalf * 8) * 2;
    const unsigned dB = (brow * BSTRIDE + bcol) * 2;

    const int lane = t & 31, wid = t >> 5;
    const int wm = wid & 3, wn = wid >> 2;
    unsigned offA[2], offB[4];
    {
        int r = lane & 15, c = (lane >> 4) * 8;
        offA[0] = ((wm * 32 + r) * ASTRIDE + c) * 2;
        offA[1] = ((wm * 32 + 16 + r) * ASTRIDE + c) * 2;
        int br = (lane & 7) + ((lane & 16) ? 8 : 0);
        int bc = (lane & 8) ? 8 : 0;
        #pragma unroll
        for (int p = 0; p < 4; p++)
            offB[p] = (br * BSTRIDE + wn * 64 + p * 16 + bc) * 2;
    }

    float acc[2][8][4];
    #pragma unroll
    for (int i = 0; i < 2; i++)
        #pragma unroll
        for (int j = 0; j < 8; j++)
            #pragma unroll
            for (int q = 0; q < 4; q++) acc[i][j][q] = 0.f;

    float fa[8], fb[8];
    // prologue: load step 0, convert+store into buf 0
    {
        float4 v0 = *(const float4*)gA, v1 = *(const float4*)(gA + 4);
        fa[0]=v0.x; fa[1]=v0.y; fa[2]=v0.z; fa[3]=v0.w; fa[4]=v1.x; fa[5]=v1.y; fa[6]=v1.z; fa[7]=v1.w;
        float4 w0 = *(const float4*)gB, w1 = *(const float4*)(gB + 4);
        fb[0]=w0.x; fb[1]=w0.y; fb[2]=w0.z; fb[3]=w0.w; fb[4]=w1.x; fb[5]=w1.y; fb[6]=w1.z; fb[7]=w1.w;
        union { __nv_bfloat16 b[8]; uint4 u; } H, L;
        #pragma unroll
        for (int j = 0; j < 8; j++) {
            __nv_bfloat16 h = __float2bfloat16(fa[j]);
            H.b[j] = h; L.b[j] = __float2bfloat16(fa[j] - __bfloat162float(h));
        }
        *(uint4*)(dyn + ST_AH + dA) = H.u;
        *(uint4*)(dyn + ST_AL + dA) = L.u;
        #pragma unroll
        for (int j = 0; j < 8; j++) {
            __nv_bfloat16 h = __float2bfloat16(fb[j]);
            H.b[j] = h; L.b[j] = __float2bfloat16(fb[j] - __bfloat162float(h));
        }
        *(uint4*)(dyn + ST_BH + dB) = H.u;
        *(uint4*)(dyn + ST_BL + dB) = L.u;
    }
    __syncthreads();

    for (int s = 0; s < ns; s++) {
        const int buf = s & 1;
        if (s + 1 < ns) {
            const float* pa = gA + (size_t)(s + 1) * 16;
            float4 v0 = *(const float4*)pa, v1 = *(const float4*)(pa + 4);
            fa[0]=v0.x; fa[1]=v0.y; fa[2]=v0.z; fa[3]=v0.w; fa[4]=v1.x; fa[5]=v1.y; fa[6]=v1.z; fa[7]=v1.w;
            const float* pb = gB + (size_t)(s + 1) * 16 * HH;
            float4 w0 = *(const float4*)pb, w1 = *(const float4*)(pb + 4);
            fb[0]=w0.x; fb[1]=w0.y; fb[2]=w0.z; fb[3]=w0.w; fb[4]=w1.x; fb[5]=w1.y; fb[6]=w1.z; fb[7]=w1.w;
        }

        {
            const unsigned base = sb + buf * B16BUF;
            unsigned aH[2][4], aL[2][4];
            ldsm4(aH[0], base + ST_AH + offA[0]);
            ldsm4(aH[1], base + ST_AH + offA[1]);
            ldsm4(aL[0], base + ST_AL + offA[0]);
            ldsm4(aL[1], base + ST_AL + offA[1]);
            #pragma unroll
            for (int p = 0; p < 4; p++) {
                unsigned r[4], q[4];
                ldsm4t(r, base + ST_BH + offB[p]);
                ldsm4t(q, base + ST_BL + offB[p]);
                unsigned bh0[2] = {r[0], r[2]}, bh1[2] = {r[1], r[3]};
                unsigned bl0[2] = {q[0], q[2]}, bl1[2] = {q[1], q[3]};
                #pragma unroll
                for (int mi = 0; mi < 2; mi++) {
                    mma_bf16(acc[mi][2 * p],     aH[mi], bh0);
                    mma_bf16(acc[mi][2 * p],     aH[mi], bl0);
                    mma_bf16(acc[mi][2 * p],     aL[mi], bh0);
                    mma_bf16(acc[mi][2 * p + 1], aH[mi], bh1);
                    mma_bf16(acc[mi][2 * p + 1], aH[mi], bl1);
                    mma_bf16(acc[mi][2 * p + 1], aL[mi], bh1);
                }
            }
        }

        if (s + 1 < ns) {
            char* nb = dyn + (buf ^ 1) * B16BUF;
            union { __nv_bfloat16 b[8]; uint4 u; } H, L;
            #pragma unroll
            for (int j = 0; j < 8; j++) {
                __nv_bfloat16 h = __float2bfloat16(fa[j]);
                H.b[j] = h; L.b[j] = __float2bfloat16(fa[j] - __bfloat162float(h));
            }
            *(uint4*)(nb + ST_AH + dA) = H.u;
            *(uint4*)(nb + ST_AL + dA) = L.u;
            #pragma unroll
            for (int j = 0; j < 8; j++) {
                __nv_bfloat16 h = __float2bfloat16(fb[j]);
                H.b[j] = h; L.b[j] = __float2bfloat16(fb[j] - __bfloat162float(h));
            }
            *(uint4*)(nb + ST_BH + dB) = H.u;
            *(uint4*)(nb + ST_BL + dB) = L.u;
        }
        __syncthreads();
    }

    float* Po = Ppart + (size_t)z * NN * HH;
    #pragma unroll
    for (int mi = 0; mi < 2; mi++) {
        int row = m0 + wm * 32 + mi * 16 + (lane >> 2);
        #pragma unroll
        for (int ni = 0; ni < 8; ni++) {
            int col = n0 + wn * 64 + ni * 8 + (lane & 3) * 2;
            *(float2*)&Po[(size_t)row * HH + col]       = make_float2(acc[mi][ni][0], acc[mi][ni][1]);
            *(float2*)&Po[(size_t)(row + 8) * HH + col] = make_float2(acc[mi][ni][2], acc[mi][ni][3]);
        }
    }
}

// ---------------- device-wide barrier ----------------
__device__ __forceinline__ void gbar() {
    __syncthreads();
    if (threadIdx.x == 0) {
        __threadfence();
        unsigned old = *(volatile unsigned*)&g_bar_gen;
        unsigned a = atomicAdd(&g_bar_cnt, 1u);
        if (a == NCTA - 1) {
            g_bar_cnt = 0;
            __threadfence();
            *(volatile unsigned*)&g_bar_gen = old + 1;
        } else {
            while (*(volatile unsigned*)&g_bar_gen == old) { }
        }
        __threadfence();
    }
    __syncthreads();
}

// ---------------- 32x64 tile GEMM: 512 threads, 4-way warp-split-K ----------------
__device__ void dgemm32(const __nv_bfloat16* __restrict__ Ah, const __nv_bfloat16* __restrict__ Al,
                        const __nv_bfloat16* __restrict__ Bh, const __nv_bfloat16* __restrict__ Bl,
                        const float* __restrict__ bias,
                        __nv_bfloat16* __restrict__ Ch, __nv_bfloat16* __restrict__ Cl,
                        int N, int K, int m0, int n0, int epi, int aexact, char* sm)
{
    const int t = threadIdx.x;
    const int kg = t >> 7, t7 = t & 127;
    const int Kq = K >> 2;
    const int ns = Kq >> 4;

    const int arow = t7 >> 2, ak = (t7 & 3) * 4;
    const int brow = t7 >> 3, bn = (t7 & 7) * 8;
    const __nv_bfloat16* gAh = Ah + (size_t)(m0 + arow) * K + kg * Kq + ak;
    const __nv_bfloat16* gAl = aexact ? gAh : (Al + (size_t)(m0 + arow) * K + kg * Kq + ak);
    const __nv_bfloat16* gBh = Bh + (size_t)(kg * Kq + brow) * N + n0 + bn;
    const __nv_bfloat16* gBl = Bl + (size_t)(kg * Kq + brow) * N + n0 + bn;

    const unsigned grpBase = (unsigned)__cvta_generic_to_shared(sm) + kg * CGRP;
    const unsigned dA = (arow * SASTR + ak) * 2;
    const unsigned dB = (brow * SBSTR + bn) * 2;

    const int lane = t & 31;
    const int wid2 = (t >> 5) & 3;
    const int wm = wid2 & 1, wn = wid2 >> 1;

    unsigned offA0, offB[2];
    {
        int r = lane & 15, c = (lane >> 4) * 8;
        offA0 = ((wm * 16 + r) * SASTR + c) * 2;
        int br = (lane & 7) + ((lane & 16) ? 8 : 0);
        int bc = (lane & 8) ? 8 : 0;
        offB[0] = (br * SBSTR + wn * 32 + bc) * 2;
        offB[1] = (br * SBSTR + wn * 32 + 16 + bc) * 2;
    }

    float acc[4][4];
    #pragma unroll
    for (int j = 0; j < 4; j++)
        #pragma unroll
        for (int q = 0; q < 4; q++) acc[j][q] = 0.f;

    #pragma unroll
    for (int sg = 0; sg < NST - 1; sg++) {
        if (sg < ns) {
            unsigned bs = grpBase + sg * CSTAGE;
            size_t ko = (size_t)sg * 16;
            cpa8(bs + CG_AH + dA, gAh + ko);
            if (!aexact) cpa8(bs + CG_AL + dA, gAl + ko);
            cpa16(bs + CG_BH + dB, gBh + ko * N);
            cpa16(bs + CG_BL + dB, gBl + ko * N);
        }
        cpa_commit();
    }

    for (int s = 0; s < ns; s++) {
        cpa_wait<NST - 2>();
        __syncthreads();

        int sg = s + NST - 1;
        if (sg < ns) {
            unsigned bs = grpBase + (sg % NST) * CSTAGE;
            size_t ko = (size_t)sg * 16;
            cpa8(bs + CG_AH + dA, gAh + ko);
            if (!aexact) cpa8(bs + CG_AL + dA, gAl + ko);
            cpa16(bs + CG_BH + dB, gBh + ko * N);
            cpa16(bs + CG_BL + dB, gBl + ko * N);
        }
        cpa_commit();

        const unsigned bs = grpBase + (s % NST) * CSTAGE;
        unsigned aH[4], aL[4];
        ldsm4(aH, bs + CG_AH + offA0);
        if (!aexact) ldsm4(aL, bs + CG_AL + offA0);
        unsigned bH[4][2], bL[4][2];
        #pragma unroll
        for (int p = 0; p < 2; p++) {
            unsigned r[4];
            ldsm4t(r, bs + CG_BH + offB[p]);
            bH[2*p][0] = r[0]; bH[2*p][1] = r[2]; bH[2*p+1][0] = r[1]; bH[2*p+1][1] = r[3];
            ldsm4t(r, bs + CG_BL + offB[p]);
            bL[2*p][0] = r[0]; bL[2*p][1] = r[2]; bL[2*p+1][0] = r[1]; bL[2*p+1][1] = r[3];
        }
        #pragma unroll
        for (int ni = 0; ni < 4; ni++) {
            mma_bf16(acc[ni], aH, bH[ni]);
            mma_bf16(acc[ni], aH, bL[ni]);
        }
        if (!aexact) {
            #pragma unroll
            for (int ni = 0; ni < 4; ni++)
                mma_bf16(acc[ni], aL, bH[ni]);
        }
    }

    __syncthreads();
    float* comb = (float*)sm;
    if (kg != 0) {
        int base = (kg - 1) * 2176 + t7 * 17;
        #pragma unroll
        for (int ni = 0; ni < 4; ni++)
            #pragma unroll
            for (int q = 0; q < 4; q++)
                comb[base + ni * 4 + q] = acc[ni][q];
    }
    __syncthreads();
    if (kg == 0) {
        int row = m0 + wm * 16 + (lane >> 2);
        #pragma unroll
        for (int ni = 0; ni < 4; ni++) {
            int col = n0 + wn * 32 + ni * 8 + (lane & 3) * 2;
            float v[4];
            #pragma unroll
            for (int q = 0; q < 4; q++) {
                int idx = ni * 4 + q;
                v[q] = acc[ni][q]
                     + comb[0 * 2176 + t7 * 17 + idx]
                     + comb[1 * 2176 + t7 * 17 + idx]
                     + comb[2 * 2176 + t7 * 17 + idx];
            }
            if (epi) {
                float2 b = *(const float2*)&bias[col];
                v[0] += b.x; v[1] += b.y; v[2] += b.x; v[3] += b.y;
            }
            if (epi == 1) {
                v[0] = fmaxf(v[0], 0.f); v[1] = fmaxf(v[1], 0.f);
                v[2] = fmaxf(v[2], 0.f); v[3] = fmaxf(v[3], 0.f);
            }
            #pragma unroll
            for (int rr = 0; rr < 2; rr++) {
                float x0 = v[rr * 2], x1 = v[rr * 2 + 1];
                __nv_bfloat16 h0 = __float2bfloat16(x0), h1 = __float2bfloat16(x1);
                __nv_bfloat162 Hp, Lp;
                Hp.x = h0; Hp.y = h1;
                Lp.x = __float2bfloat16(x0 - __bfloat162float(h0));
                Lp.y = __float2bfloat16(x1 - __bfloat162float(h1));
                size_t off = (size_t)(row + rr * 8) * N + col;
                *(__nv_bfloat162*)&Ch[off] = Hp;
                *(__nv_bfloat162*)&Cl[off] = Lp;
            }
        }
    }
    __syncthreads();
}

// ---------------- persistent chain kernel (64 CTAs x 512 threads) ----------------
__global__ __launch_bounds__(CTHREADS)
void k_chain(const float* __restrict__ bs1a, const float* __restrict__ bs1b,
             const float* __restrict__ bs2a, const float* __restrict__ bs2b,
             const float* __restrict__ bc1a, const float* __restrict__ bc1b,
             const float* __restrict__ Wc2a, const float* __restrict__ bc2a,
             const float* __restrict__ Wc2b, const float* __restrict__ bc2b,
             const float* __restrict__ Wd, const float* __restrict__ bd,
             float* __restrict__ out)
{
    extern __shared__ char s_all[];
    __shared__ float dred[16];

    const int bid = blockIdx.x, t = threadIdx.x;
    const int gid = bid * CTHREADS + t;
    const int wid = t >> 5, lane = t & 31;

    {
        int i = gid;
        float4 s = make_float4(0.f, 0.f, 0.f, 0.f);
        #pragma unroll
        for (int z = 0; z < SPLITKZ; z++) {
            float4 v = ((const float4*)g_Ppart)[(size_t)z * (NN * HH / 4) + i];
            s.x += v.x; s.y += v.y; s.z += v.z; s.w += v.w;
        }
        int e = i * 4;
        float f[4] = {s.x, s.y, s.z, s.w};
        union { __nv_bfloat16 b[4]; uint2 u; } H, L;
        #pragma unroll
        for (int q = 0; q < 4; q++) {
            __nv_bfloat16 h = __float2bfloat16(f[q]);
            H.b[q] = h; L.b[q] = __float2bfloat16(f[q] - __bfloat162float(h));
        }
        *(uint2*)&g_Ph[e] = H.u;
        *(uint2*)&g_Pl[e] = L.u;
    }
    if (gid < 8192) {
        float4 a = ((const float4*)g_B)[gid * 2], b = ((const float4*)g_B)[gid * 2 + 1];
        float f[8] = {a.x, a.y, a.z, a.w, b.x, b.y, b.z, b.w};
        union { __nv_bfloat16 v[8]; uint4 u; } H;
        #pragma unroll
        for (int q = 0; q < 8; q++) H.v[q] = __float2bfloat16(f[q]);
        ((uint4*)g_Bh)[gid] = H.u;
    }
    gbar();

    const int tx8 = bid & 7, ty8 = bid >> 3;
    const int tx4 = bid & 3, ty4 = bid >> 2;

    dgemm32(g_Bh, (const __nv_bfloat16*)0, g_Ph, g_Pl, bs1a, g_U1h, g_U1l,
            HH, NN, ty8 * 32, tx8 * 64, 1, 1, s_all);
    gbar();
    dgemm32(g_U1h, g_U1l, g_W1bh, g_W1bl, bs1b, g_hh, g_hl,
            HH, HH, ty8 * 32, tx8 * 64, 1, 0, s_all);
    gbar();
    if (bid < 32)
        dgemm32(g_hh, g_hl, g_W2ah, g_W2al, (const float*)0, g_Q2h, g_Q2l,
                LL, HH, ty4 * 32, tx4 * 64, 0, 0, s_all);
    gbar();
    if (bid < 32)
        dgemm32(g_Bh, (const __nv_bfloat16*)0, g_Q2h, g_Q2l, bs2a, g_U2h, g_U2l,
                LL, NN, ty4 * 32, tx4 * 64, 1, 1, s_all);
    gbar();
    if (bid < 32)
        dgemm32(g_U2h, g_U2l, g_W2bh, g_W2bl, bs2b, g_fh, g_fl,
                LL, LL, ty4 * 32, tx4 * 64, 2, 0, s_all);
    gbar();
    dgemm32(g_fh, g_fl, g_Wc1ah, g_Wc1al, (const float*)0, g_Q3h, g_Q3l,
            HH, LL, ty8 * 32, tx8 * 64, 0, 0, s_all);
    gbar();
    dgemm32(g_Bh, (const __nv_bfloat16*)0, g_Q3h, g_Q3l, bc1a, g_U3h, g_U3l,
            HH, NN, ty8 * 32, tx8 * 64, 1, 1, s_all);
    gbar();
    dgemm32(g_U3h, g_U3l, g_Wc1bh, g_Wc1bl, bc1b, g_sh2, g_sl2,
            HH, HH, ty8 * 32, tx8 * 64, 1, 0, s_all);
    gbar();

    if (wid < 4) {
        int row = bid * 4 + wid;
        float s = 0.f;
        for (int i = lane; i < HH; i += 32)
            s += (__bfloat162float(g_sh2[row * HH + i]) + __bfloat162float(g_sl2[row * HH + i])) * Wc2a[i];
        #pragma unroll
        for (int o = 16; o; o >>= 1) s += __shfl_down_sync(0xFFFFFFFFu, s, o);
        if (lane == 0) g_Q4[row] = s;
    }
    {
        float ds = 0.f;
        int base = bid * 1024;
        for (int i = t; i < 1024; i += CTHREADS)
            ds += (__bfloat162float(g_fh[base + i]) + __bfloat162float(g_fl[base + i])) * Wd[base + i];
        #pragma unroll
        for (int o = 16; o; o >>= 1) ds += __shfl_down_sync(0xFFFFFFFFu, ds, o);
        if (lane == 0) dred[wid] = ds;
        __syncthreads();
        if (t == 0) {
            float v = 0.f;
            #pragma unroll
            for (int j = 0; j < 16; j++) v += dred[j];
            g_dpart[bid] = v;
        }
    }
    gbar();

    if (wid < 4) {
        int row = bid * 4 + wid;
        float s = 0.f;
        for (int i = lane; i < NN; i += 32) s += g_B[row * NN + i] * g_Q4[i];
        #pragma unroll
        for (int o = 16; o; o >>= 1) s += __shfl_down_sync(0xFFFFFFFFu, s, o);
        if (lane == 0) {
            float u = fmaxf(s + bc2a[0], 0.f);
            float sc = u * Wc2b[0] + bc2b[0];
            out[1 + row] = 1.f / (1.f + expf(-sc));
        }
    }
    if (bid == 0 && wid == 0) {
        float v = g_dpart[lane] + g_dpart[lane + 32];
        #pragma unroll
        for (int o = 16; o; o >>= 1) v += __shfl_down_sync(0xFFFFFFFFu, v, o);
        if (lane == 0) out[0] = 1.f / (1.f + expf(-(v + bd[0])));
    }
}

// ---------------- launch ----------------
extern "C" void kernel_launch(void* const* d_in, const int* in_sizes, int n_in,
                              void* d_out, int out_size) {
    const float* X    = (const float*)d_in[0];
    const int*   idx  = (const int*)d_in[1];
    const float* Ws1a = (const float*)d_in[3];
    const float* bs1a = (const float*)d_in[4];
    const float* Ws1b = (const float*)d_in[5];
    const float* bs1b = (const float*)d_in[6];
    const float* Ws2a = (const float*)d_in[7];
    const float* bs2a = (const float*)d_in[8];
    const float* Ws2b = (const float*)d_in[9];
    const float* bs2b = (const float*)d_in[10];
    const float* Wc1a = (const float*)d_in[11];
    const float* bc1a = (const float*)d_in[12];
    const float* Wc1b = (const float*)d_in[13];
    const float* bc1b = (const float*)d_in[14];
    const float* Wc2a = (const float*)d_in[15];
    const float* bc2a = (const float*)d_in[16];
    const float* Wc2b = (const float*)d_in[17];
    const float* bc2b = (const float*)d_in[18];
    const float* Wd   = (const float*)d_in[19];
    const float* bd   = (const float*)d_in[20];
    float* out = (float*)d_out;

    float* pPpart;
    cudaGetSymbolAddress((void**)&pPpart, g_Ppart);

    cudaFuncSetAttribute(bigmm4, cudaFuncAttributeMaxDynamicSharedMemorySize, SMEM_DYN3);
    cudaFuncSetAttribute(k_chain, cudaFuncAttributeMaxDynamicSharedMemorySize, CH_TOT3);

    k_cvtW<<<(N_CVT + 255) / 256, 256>>>(Ws1b, Ws2a, Ws2b, Wc1a, Wc1b);   // 1
    k_initB2<<<(N_B4 + 255) / 256, 256>>>();                               // 2
    k_edges<<<(EE + 255) / 256, 256>>>(idx);                               // 3
    bigmm4<<<dim3(4, 2, SPLITKZ), 256, SMEM_DYN3>>>(X, Ws1a, pPpart);      // 4
    k_chain<<<NCTA, CTHREADS, CH_TOT3>>>(bs1a, bs1b, bs2a, bs2b, bc1a, bc1b,
                                         Wc2a, bc2a, Wc2b, bc2b, Wd, bd, out);
}

// round 16
// speedup vs baseline: 1.4667x; 1.0453x over previous
#include <cuda_runtime.h>
#include <cuda_bf16.h>
#include <math.h>

#define NN 256
#define TT 30000
#define HH 512
#define LL 256
#define EE 32768

#define KSTEPS 1875
#define SPLITKZ 37
#define SPG 51

// bigmm bf16 buffer layout (within one 20992B buf)
#define ASTRIDE 24
#define BSTRIDE 136
#define ST_AH 0
#define ST_AL 6144
#define ST_BH 12288
#define ST_BL 16640
#define B16BUF 20992
#define SMEM_DYN3 (2 * B16BUF)     // 41984

// chain gemm (32x32 tiles) smem layout — k16 stages, 4 K-groups
#define SASTR 24
#define SBSTR 72
#define NST 3
#define CG_AH 0
#define CG_AL 1536
#define CG_BH 3072
#define CG_BL 5376
#define CSTAGE 7680
#define CGRP (CSTAGE * NST)
#define NKG 4
#define CH_TOT3 (NKG * CGRP)       // 92160

#define NCTA 128
#define CTHREADS 512

// ---------------- device scratch ----------------
__device__ float g_B[NN * NN];
__device__ __nv_bfloat16 g_Bh[NN * NN];
__device__ float g_Ppart[SPLITKZ * NN * HH];
__device__ __nv_bfloat16 g_Ph[NN * HH], g_Pl[NN * HH];
__device__ __nv_bfloat16 g_U1h[NN * HH], g_U1l[NN * HH];
__device__ __nv_bfloat16 g_hh[NN * HH], g_hl[NN * HH];
__device__ __nv_bfloat16 g_Q2h[NN * LL], g_Q2l[NN * LL];
__device__ __nv_bfloat16 g_U2h[NN * LL], g_U2l[NN * LL];
__device__ __nv_bfloat16 g_fh[NN * LL], g_fl[NN * LL];
__device__ __nv_bfloat16 g_Q3h[NN * HH], g_Q3l[NN * HH];
__device__ __nv_bfloat16 g_U3h[NN * HH], g_U3l[NN * HH];
__device__ __nv_bfloat16 g_sh2[NN * HH], g_sl2[NN * HH];
__device__ __nv_bfloat16 g_W1bh[HH * HH], g_W1bl[HH * HH];
__device__ __nv_bfloat16 g_W2ah[HH * LL], g_W2al[HH * LL];
__device__ __nv_bfloat16 g_W2bh[LL * LL], g_W2bl[LL * LL];
__device__ __nv_bfloat16 g_Wc1ah[LL * HH], g_Wc1al[LL * HH];
__device__ __nv_bfloat16 g_Wc1bh[HH * HH], g_Wc1bl[HH * HH];
__device__ float g_Q4[NN];
__device__ float g_dpart[NCTA];
__device__ unsigned g_bar_cnt;
__device__ unsigned g_bar_gen;

// ---------------- weight conversion ----------------
#define N_W1B (HH * HH / 8)
#define N_W2A (HH * LL / 8)
#define N_W2B (LL * LL / 8)
#define N_WC1A (LL * HH / 8)
#define N_WC1B (HH * HH / 8)
#define N_CVT (N_W1B + N_W2A + N_W2B + N_WC1A + N_WC1B)
#define N_B4  (NN * NN / 4)

__device__ __forceinline__ void cvt8(const float* __restrict__ src,
                                     __nv_bfloat16* __restrict__ hi,
                                     __nv_bfloat16* __restrict__ lo, int j8) {
    float4 v0 = ((const float4*)src)[2 * j8], v1 = ((const float4*)src)[2 * j8 + 1];
    float f[8] = {v0.x, v0.y, v0.z, v0.w, v1.x, v1.y, v1.z, v1.w};
    union { __nv_bfloat16 b[8]; uint4 u; } H, L;
    #pragma unroll
    for (int j = 0; j < 8; j++) {
        __nv_bfloat16 h = __float2bfloat16(f[j]);
        H.b[j] = h; L.b[j] = __float2bfloat16(f[j] - __bfloat162float(h));
    }
    ((uint4*)hi)[j8] = H.u;
    ((uint4*)lo)[j8] = L.u;
}

__global__ void k_cvtW(const float* __restrict__ W1b, const float* __restrict__ W2a,
                       const float* __restrict__ W2b, const float* __restrict__ Wc1a,
                       const float* __restrict__ Wc1b) {
    int o = blockIdx.x * blockDim.x + threadIdx.x;
    if (o < N_W1B) { cvt8(W1b, g_W1bh, g_W1bl, o); return; }
    o -= N_W1B;
    if (o < N_W2A) { cvt8(W2a, g_W2ah, g_W2al, o); return; }
    o -= N_W2A;
    if (o < N_W2B) { cvt8(W2b, g_W2bh, g_W2bl, o); return; }
    o -= N_W2B;
    if (o < N_WC1A) { cvt8(Wc1a, g_Wc1ah, g_Wc1al, o); return; }
    o -= N_WC1A;
    if (o < N_WC1B) { cvt8(Wc1b, g_Wc1bh, g_Wc1bl, o); }
}

__global__ void k_initB2() {
    int o = blockIdx.x * blockDim.x + threadIdx.x;
    if (o < N_B4) {
        int e0 = o * 4;
        float4 v = make_float4(0.f, 0.f, 0.f, 0.f);
        float* pv = &v.x;
        #pragma unroll
        for (int q = 0; q < 4; q++) {
            int e = e0 + q;
            if ((e >> 8) == (e & 255)) pv[q] = 1.f;
        }
        ((float4*)g_B)[o] = v;
    }
}

__global__ void k_edges(const int* __restrict__ idx) {
    int e = blockIdx.x * blockDim.x + threadIdx.x;
    if (e < EE) atomicAdd(&g_B[idx[EE + e] * NN + idx[e]], 1.0f);
}

// ---------------- PTX helpers ----------------
__device__ __forceinline__ void mma_bf16(float* c, const unsigned* a, const unsigned* b) {
    asm volatile(
        "mma.sync.aligned.m16n8k16.row.col.f32.bf16.bf16.f32 "
        "{%0,%1,%2,%3},{%4,%5,%6,%7},{%8,%9},{%0,%1,%2,%3};"
        : "+f"(c[0]), "+f"(c[1]), "+f"(c[2]), "+f"(c[3])
        : "r"(a[0]), "r"(a[1]), "r"(a[2]), "r"(a[3]), "r"(b[0]), "r"(b[1]));
}
__device__ __forceinline__ void ldsm4(unsigned* r, unsigned addr) {
    asm volatile("ldmatrix.sync.aligned.m8n8.x4.shared.b16 {%0,%1,%2,%3},[%4];"
                 : "=r"(r[0]), "=r"(r[1]), "=r"(r[2]), "=r"(r[3]) : "r"(addr));
}
__device__ __forceinline__ void ldsm4t(unsigned* r, unsigned addr) {
    asm volatile("ldmatrix.sync.aligned.m8n8.x4.trans.shared.b16 {%0,%1,%2,%3},[%4];"
                 : "=r"(r[0]), "=r"(r[1]), "=r"(r[2]), "=r"(r[3]) : "r"(addr));
}
__device__ __forceinline__ void cpa16(unsigned dst, const void* src) {
    asm volatile("cp.async.cg.shared.global [%0], [%1], 16;" :: "r"(dst), "l"(src));
}
__device__ __forceinline__ void cpa8(unsigned dst, const void* src) {
    asm volatile("cp.async.ca.shared.global [%0], [%1], 8;" :: "r"(dst), "l"(src));
}
__device__ __forceinline__ void cpa_commit() { asm volatile("cp.async.commit_group;"); }
template <int N> __device__ __forceinline__ void cpa_wait() {
    asm volatile("cp.async.wait_group %0;" :: "n"(N));
}

// ---------------- big GEMM (unchanged from R15 passing) ----------------
__global__ __launch_bounds__(256, 2)
void bigmm4(const float* __restrict__ X, const float* __restrict__ W, float* __restrict__ Ppart)
{
    extern __shared__ char dyn[];
    const unsigned sb = (unsigned)__cvta_generic_to_shared(dyn);

    const int t = threadIdx.x;
    const int m0 = blockIdx.y * 128, n0 = blockIdx.x * 128, z = blockIdx.z;
    const int s0 = z * SPG;
    const int ns = min(SPG, KSTEPS - s0);

    const int arow = t >> 1, ahalf = t & 1;
    const int brow = t >> 4, bcol = (t & 15) * 8;
    const float* gA = X + (size_t)(m0 + arow) * TT + (size_t)s0 * 16 + ahalf * 8;
    const float* gB = W + (size_t)((size_t)s0 * 16 + brow) * HH + n0 + bcol;
    const unsigned dA = (arow * ASTRIDE + ahalf * 8) * 2;
    const unsigned dB = (brow * BSTRIDE + bcol) * 2;

    const int lane = t & 31, wid = t >> 5;
    const int wm = wid & 3, wn = wid >> 2;
    unsigned offA[2], offB[4];
    {
        int r = lane & 15, c = (lane >> 4) * 8;
        offA[0] = ((wm * 32 + r) * ASTRIDE + c) * 2;
        offA[1] = ((wm * 32 + 16 + r) * ASTRIDE + c) * 2;
        int br = (lane & 7) + ((lane & 16) ? 8 : 0);
        int bc = (lane & 8) ? 8 : 0;
        #pragma unroll
        for (int p = 0; p < 4; p++)
            offB[p] = (br * BSTRIDE + wn * 64 + p * 16 + bc) * 2;
    }

    float acc[2][8][4];
    #pragma unroll
    for (int i = 0; i < 2; i++)
        #pragma unroll
        for (int j = 0; j < 8; j++)
            #pragma unroll
            for (int q = 0; q < 4; q++) acc[i][j][q] = 0.f;

    float fa[8], fb[8];
    {
        float4 v0 = *(const float4*)gA, v1 = *(const float4*)(gA + 4);
        fa[0]=v0.x; fa[1]=v0.y; fa[2]=v0.z; fa[3]=v0.w; fa[4]=v1.x; fa[5]=v1.y; fa[6]=v1.z; fa[7]=v1.w;
        float4 w0 = *(const float4*)gB, w1 = *(const float4*)(gB + 4);
        fb[0]=w0.x; fb[1]=w0.y; fb[2]=w0.z; fb[3]=w0.w; fb[4]=w1.x; fb[5]=w1.y; fb[6]=w1.z; fb[7]=w1.w;
        union { __nv_bfloat16 b[8]; uint4 u; } H, L;
        #pragma unroll
        for (int j = 0; j < 8; j++) {
            __nv_bfloat16 h = __float2bfloat16(fa[j]);
            H.b[j] = h; L.b[j] = __float2bfloat16(fa[j] - __bfloat162float(h));
        }
        *(uint4*)(dyn + ST_AH + dA) = H.u;
        *(uint4*)(dyn + ST_AL + dA) = L.u;
        #pragma unroll
        for (int j = 0; j < 8; j++) {
            __nv_bfloat16 h = __float2bfloat16(fb[j]);
            H.b[j] = h; L.b[j] = __float2bfloat16(fb[j] - __bfloat162float(h));
        }
        *(uint4*)(dyn + ST_BH + dB) = H.u;
        *(uint4*)(dyn + ST_BL + dB) = L.u;
    }
    __syncthreads();

    for (int s = 0; s < ns; s++) {
        const int buf = s & 1;
        if (s + 1 < ns) {
            const float* pa = gA + (size_t)(s + 1) * 16;
            float4 v0 = *(const float4*)pa, v1 = *(const float4*)(pa + 4);
            fa[0]=v0.x; fa[1]=v0.y; fa[2]=v0.z; fa[3]=v0.w; fa[4]=v1.x; fa[5]=v1.y; fa[6]=v1.z; fa[7]=v1.w;
            const float* pb = gB + (size_t)(s + 1) * 16 * HH;
            float4 w0 = *(const float4*)pb, w1 = *(const float4*)(pb + 4);
            fb[0]=w0.x; fb[1]=w0.y; fb[2]=w0.z; fb[3]=w0.w; fb[4]=w1.x; fb[5]=w1.y; fb[6]=w1.z; fb[7]=w1.w;
        }

        {
            const unsigned base = sb + buf * B16BUF;
            unsigned aH[2][4], aL[2][4];
            ldsm4(aH[0], base + ST_AH + offA[0]);
            ldsm4(aH[1], base + ST_AH + offA[1]);
            ldsm4(aL[0], base + ST_AL + offA[0]);
            ldsm4(aL[1], base + ST_AL + offA[1]);
            #pragma unroll
            for (int p = 0; p < 4; p++) {
                unsigned r[4], q[4];
                ldsm4t(r, base + ST_BH + offB[p]);
                ldsm4t(q, base + ST_BL + offB[p]);
                unsigned bh0[2] = {r[0], r[2]}, bh1[2] = {r[1], r[3]};
                unsigned bl0[2] = {q[0], q[2]}, bl1[2] = {q[1], q[3]};
                #pragma unroll
                for (int mi = 0; mi < 2; mi++) {
                    mma_bf16(acc[mi][2 * p],     aH[mi], bh0);
                    mma_bf16(acc[mi][2 * p],     aH[mi], bl0);
                    mma_bf16(acc[mi][2 * p],     aL[mi], bh0);
                    mma_bf16(acc[mi][2 * p + 1], aH[mi], bh1);
                    mma_bf16(acc[mi][2 * p + 1], aH[mi], bl1);
                    mma_bf16(acc[mi][2 * p + 1], aL[mi], bh1);
                }
            }
        }

        if (s + 1 < ns) {
            char* nb = dyn + (buf ^ 1) * B16BUF;
            union { __nv_bfloat16 b[8]; uint4 u; } H, L;
            #pragma unroll
            for (int j = 0; j < 8; j++) {
                __nv_bfloat16 h = __float2bfloat16(fa[j]);
                H.b[j] = h; L.b[j] = __float2bfloat16(fa[j] - __bfloat162float(h));
            }
            *(uint4*)(nb + ST_AH + dA) = H.u;
            *(uint4*)(nb + ST_AL + dA) = L.u;
            #pragma unroll
            for (int j = 0; j < 8; j++) {
                __nv_bfloat16 h = __float2bfloat16(fb[j]);
                H.b[j] = h; L.b[j] = __float2bfloat16(fb[j] - __bfloat162float(h));
            }
            *(uint4*)(nb + ST_BH + dB) = H.u;
            *(uint4*)(nb + ST_BL + dB) = L.u;
        }
        __syncthreads();
    }

    float* Po = Ppart + (size_t)z * NN * HH;
    #pragma unroll
    for (int mi = 0; mi < 2; mi++) {
        int row = m0 + wm * 32 + mi * 16 + (lane >> 2);
        #pragma unroll
        for (int ni = 0; ni < 8; ni++) {
            int col = n0 + wn * 64 + ni * 8 + (lane & 3) * 2;
            *(float2*)&Po[(size_t)row * HH + col]       = make_float2(acc[mi][ni][0], acc[mi][ni][1]);
            *(float2*)&Po[(size_t)(row + 8) * HH + col] = make_float2(acc[mi][ni][2], acc[mi][ni][3]);
        }
    }
}

// ---------------- device-wide barrier ----------------
__device__ __forceinline__ void gbar() {
    __syncthreads();
    if (threadIdx.x == 0) {
        __threadfence();
        unsigned old = *(volatile unsigned*)&g_bar_gen;
        unsigned a = atomicAdd(&g_bar_cnt, 1u);
        if (a == NCTA - 1) {
            g_bar_cnt = 0;
            __threadfence();
            *(volatile unsigned*)&g_bar_gen = old + 1;
        } else {
            while (*(volatile unsigned*)&g_bar_gen == old) { }
        }
        __threadfence();
    }
    __syncthreads();
}

// ---------------- 32x32 tile GEMM: 512 threads, 4-way warp-split-K ----------------
__device__ void dgemm16(const __nv_bfloat16* __restrict__ Ah, const __nv_bfloat16* __restrict__ Al,
                        const __nv_bfloat16* __restrict__ Bh, const __nv_bfloat16* __restrict__ Bl,
                        const float* __restrict__ bias,
                        __nv_bfloat16* __restrict__ Ch, __nv_bfloat16* __restrict__ Cl,
                        int N, int K, int m0, int n0, int epi, int aexact, char* sm)
{
    const int t = threadIdx.x;
    const int kg = t >> 7, t7 = t & 127;
    const int Kq = K >> 2;
    const int ns = Kq >> 4;

    const int arow = t7 >> 2, ak = (t7 & 3) * 4;   // A: 32 rows x 4-elem chunks
    const int brow = t7 >> 3, bn = (t7 & 7) * 4;   // B: 16 rows x 32 cols, 4-elem chunks
    const __nv_bfloat16* gAh = Ah + (size_t)(m0 + arow) * K + kg * Kq + ak;
    const __nv_bfloat16* gAl = aexact ? gAh : (Al + (size_t)(m0 + arow) * K + kg * Kq + ak);
    const __nv_bfloat16* gBh = Bh + (size_t)(kg * Kq + brow) * N + n0 + bn;
    const __nv_bfloat16* gBl = Bl + (size_t)(kg * Kq + brow) * N + n0 + bn;

    const unsigned grpBase = (unsigned)__cvta_generic_to_shared(sm) + kg * CGRP;
    const unsigned dA = (arow * SASTR + ak) * 2;
    const unsigned dB = (brow * SBSTR + bn) * 2;

    const int lane = t & 31;
    const int wid2 = (t >> 5) & 3;
    const int wm = wid2 & 1, wn = wid2 >> 1;       // m16 x n16 per warp

    unsigned offA0, offB0;
    {
        int r = lane & 15, c = (lane >> 4) * 8;
        offA0 = ((wm * 16 + r) * SASTR + c) * 2;
        int br = (lane & 7) + ((lane & 16) ? 8 : 0);
        int bc = (lane & 8) ? 8 : 0;
        offB0 = (br * SBSTR + wn * 16 + bc) * 2;
    }

    float acc[2][4];
    #pragma unroll
    for (int j = 0; j < 2; j++)
        #pragma unroll
        for (int q = 0; q < 4; q++) acc[j][q] = 0.f;

    #pragma unroll
    for (int sg = 0; sg < NST - 1; sg++) {
        if (sg < ns) {
            unsigned bs = grpBase + sg * CSTAGE;
            size_t ko = (size_t)sg * 16;
            cpa8(bs + CG_AH + dA, gAh + ko);
            if (!aexact) cpa8(bs + CG_AL + dA, gAl + ko);
            cpa8(bs + CG_BH + dB, gBh + ko * N);
            cpa8(bs + CG_BL + dB, gBl + ko * N);
        }
        cpa_commit();
    }

    for (int s = 0; s < ns; s++) {
        cpa_wait<NST - 2>();
        __syncthreads();

        int sg = s + NST - 1;
        if (sg < ns) {
            unsigned bs = grpBase + (sg % NST) * CSTAGE;
            size_t ko = (size_t)sg * 16;
            cpa8(bs + CG_AH + dA, gAh + ko);
            if (!aexact) cpa8(bs + CG_AL + dA, gAl + ko);
            cpa8(bs + CG_BH + dB, gBh + ko * N);
            cpa8(bs + CG_BL + dB, gBl + ko * N);
        }
        cpa_commit();

        const unsigned bs = grpBase + (s % NST) * CSTAGE;
        unsigned aH[4], aL[4];
        ldsm4(aH, bs + CG_AH + offA0);
        if (!aexact) ldsm4(aL, bs + CG_AL + offA0);
        unsigned bH[2][2], bL[2][2];
        {
            unsigned r[4];
            ldsm4t(r, bs + CG_BH + offB0);
            bH[0][0] = r[0]; bH[0][1] = r[2]; bH[1][0] = r[1]; bH[1][1] = r[3];
            ldsm4t(r, bs + CG_BL + offB0);
            bL[0][0] = r[0]; bL[0][1] = r[2]; bL[1][0] = r[1]; bL[1][1] = r[3];
        }
        #pragma unroll
        for (int ni = 0; ni < 2; ni++) {
            mma_bf16(acc[ni], aH, bH[ni]);
            mma_bf16(acc[ni], aH, bL[ni]);
        }
        if (!aexact) {
            #pragma unroll
            for (int ni = 0; ni < 2; ni++)
                mma_bf16(acc[ni], aL, bH[ni]);
        }
    }

    // combine 4 K-groups through smem (deterministic order)
    __syncthreads();
    float* comb = (float*)sm;
    if (kg != 0) {
        int base = (kg - 1) * 1184 + t7 * 9;
        #pragma unroll
        for (int ni = 0; ni < 2; ni++)
            #pragma unroll
            for (int q = 0; q < 4; q++)
                comb[base + ni * 4 + q] = acc[ni][q];
    }
    __syncthreads();
    if (kg == 0) {
        int row = m0 + wm * 16 + (lane >> 2);
        #pragma unroll
        for (int ni = 0; ni < 2; ni++) {
            int col = n0 + wn * 16 + ni * 8 + (lane & 3) * 2;
            float v[4];
            #pragma unroll
            for (int q = 0; q < 4; q++) {
                int idx = ni * 4 + q;
                v[q] = acc[ni][q]
                     + comb[0 * 1184 + t7 * 9 + idx]
                     + comb[1 * 1184 + t7 * 9 + idx]
                     + comb[2 * 1184 + t7 * 9 + idx];
            }
            if (epi) {
                float2 b = *(const float2*)&bias[col];
                v[0] += b.x; v[1] += b.y; v[2] += b.x; v[3] += b.y;
            }
            if (epi == 1) {
                v[0] = fmaxf(v[0], 0.f); v[1] = fmaxf(v[1], 0.f);
                v[2] = fmaxf(v[2], 0.f); v[3] = fmaxf(v[3], 0.f);
            }
            #pragma unroll
            for (int rr = 0; rr < 2; rr++) {
                float x0 = v[rr * 2], x1 = v[rr * 2 + 1];
                __nv_bfloat16 h0 = __float2bfloat16(x0), h1 = __float2bfloat16(x1);
                __nv_bfloat162 Hp, Lp;
                Hp.x = h0; Hp.y = h1;
                Lp.x = __float2bfloat16(x0 - __bfloat162float(h0));
                Lp.y = __float2bfloat16(x1 - __bfloat162float(h1));
                size_t off = (size_t)(row + rr * 8) * N + col;
                *(__nv_bfloat162*)&Ch[off] = Hp;
                *(__nv_bfloat162*)&Cl[off] = Lp;
            }
        }
    }
    __syncthreads();
}

// ---------------- persistent chain kernel (128 CTAs x 512 threads) ----------------
__global__ __launch_bounds__(CTHREADS)
void k_chain(const float* __restrict__ bs1a, const float* __restrict__ bs1b,
             const float* __restrict__ bs2a, const float* __restrict__ bs2b,
             const float* __restrict__ bc1a, const float* __restrict__ bc1b,
             const float* __restrict__ Wc2a, const float* __restrict__ bc2a,
             const float* __restrict__ Wc2b, const float* __restrict__ bc2b,
             const float* __restrict__ Wd, const float* __restrict__ bd,
             float* __restrict__ out)
{
    extern __shared__ char s_all[];
    __shared__ float dred[16];

    const int bid = blockIdx.x, t = threadIdx.x;
    const int gid = bid * CTHREADS + t;            // 0..65535
    const int wid = t >> 5, lane = t & 31;

    // ---- phase 0: reduceP -> Ph/Pl (32768 float4) ; convert B -> Bh ----
    if (gid < 32768) {
        int i = gid;
        float4 s = make_float4(0.f, 0.f, 0.f, 0.f);
        #pragma unroll
        for (int z = 0; z < SPLITKZ; z++) {
            float4 v = ((const float4*)g_Ppart)[(size_t)z * (NN * HH / 4) + i];
            s.x += v.x; s.y += v.y; s.z += v.z; s.w += v.w;
        }
        int e = i * 4;
        float f[4] = {s.x, s.y, s.z, s.w};
        union { __nv_bfloat16 b[4]; uint2 u; } H, L;
        #pragma unroll
        for (int q = 0; q < 4; q++) {
            __nv_bfloat16 h = __float2bfloat16(f[q]);
            H.b[q] = h; L.b[q] = __float2bfloat16(f[q] - __bfloat162float(h));
        }
        *(uint2*)&g_Ph[e] = H.u;
        *(uint2*)&g_Pl[e] = L.u;
    }
    if (gid < 8192) {
        float4 a = ((const float4*)g_B)[gid * 2], b = ((const float4*)g_B)[gid * 2 + 1];
        float f[8] = {a.x, a.y, a.z, a.w, b.x, b.y, b.z, b.w};
        union { __nv_bfloat16 v[8]; uint4 u; } H;
        #pragma unroll
        for (int q = 0; q < 8; q++) H.v[q] = __float2bfloat16(f[q]);
        ((uint4*)g_Bh)[gid] = H.u;
    }
    gbar();

    // tile coords: 256x512 -> 8m x 16n tiles of 32x32 (128); 256x256 -> 8m x 8n (64)
    const int tx16 = bid & 15, ty16 = bid >> 4;
    const int tx8 = bid & 7, ty8 = bid >> 3;

    // G1: U1 = relu(B @ P + bs1a)   K=256, A exact
    dgemm16(g_Bh, (const __nv_bfloat16*)0, g_Ph, g_Pl, bs1a, g_U1h, g_U1l,
            HH, NN, ty16 * 32, tx16 * 32, 1, 1, s_all);
    gbar();
    // G2: h = relu(U1 @ Ws1b + bs1b)  K=512
    dgemm16(g_U1h, g_U1l, g_W1bh, g_W1bl, bs1b, g_hh, g_hl,
            HH, HH, ty16 * 32, tx16 * 32, 1, 0, s_all);
    gbar();
    // G3: Q2 = h @ Ws2a   K=512   (64 tiles)
    if (bid < 64)
        dgemm16(g_hh, g_hl, g_W2ah, g_W2al, (const float*)0, g_Q2h, g_Q2l,
                LL, HH, ty8 * 32, tx8 * 32, 0, 0, s_all);
    gbar();
    // G4: U2 = relu(B @ Q2 + bs2a)  K=256, A exact
    if (bid < 64)
        dgemm16(g_Bh, (const __nv_bfloat16*)0, g_Q2h, g_Q2l, bs2a, g_U2h, g_U2l,
                LL, NN, ty8 * 32, tx8 * 32, 1, 1, s_all);
    gbar();
    // G5: feat = U2 @ Ws2b + bs2b   K=256
    if (bid < 64)
        dgemm16(g_U2h, g_U2l, g_W2bh, g_W2bl, bs2b, g_fh, g_fl,
                LL, LL, ty8 * 32, tx8 * 32, 2, 0, s_all);
    gbar();
    // G6: Q3 = feat @ Wc1a   K=256
    dgemm16(g_fh, g_fl, g_Wc1ah, g_Wc1al, (const float*)0, g_Q3h, g_Q3l,
            HH, LL, ty16 * 32, tx16 * 32, 0, 0, s_all);
    gbar();
    // G7: U3 = relu(B @ Q3 + bc1a)  K=256, A exact
    dgemm16(g_Bh, (const __nv_bfloat16*)0, g_Q3h, g_Q3l, bc1a, g_U3h, g_U3l,
            HH, NN, ty16 * 32, tx16 * 32, 1, 1, s_all);
    gbar();
    // G8: s = relu(U3 @ Wc1b + bc1b)  K=512
    dgemm16(g_U3h, g_U3l, g_Wc1bh, g_Wc1bl, bc1b, g_sh2, g_sl2,
            HH, HH, ty16 * 32, tx16 * 32, 1, 0, s_all);
    gbar();

    // ---- q4 + dementia partials ----
    if (wid < 2) {
        int row = bid * 2 + wid;
        float s = 0.f;
        for (int i = lane; i < HH; i += 32)
            s += (__bfloat162float(g_sh2[row * HH + i]) + __bfloat162float(g_sl2[row * HH + i])) * Wc2a[i];
        #pragma unroll
        for (int o = 16; o; o >>= 1) s += __shfl_down_sync(0xFFFFFFFFu, s, o);
        if (lane == 0) g_Q4[row] = s;
    }
    {
        float ds = 0.f;
        int base = bid * 512;
        for (int i = t; i < 512; i += CTHREADS)
            ds += (__bfloat162float(g_fh[base + i]) + __bfloat162float(g_fl[base + i])) * Wd[base + i];
        #pragma unroll
        for (int o = 16; o; o >>= 1) ds += __shfl_down_sync(0xFFFFFFFFu, ds, o);
        if (lane == 0) dred[wid] = ds;
        __syncthreads();
        if (t == 0) {
            float v = 0.f;
            #pragma unroll
            for (int j = 0; j < 16; j++) v += dred[j];
            g_dpart[bid] = v;
        }
    }
    gbar();

    // ---- region scores + dementia combine ----
    if (wid < 2) {
        int row = bid * 2 + wid;
        float s = 0.f;
        for (int i = lane; i < NN; i += 32) s += g_B[row * NN + i] * g_Q4[i];
        #pragma unroll
        for (int o = 16; o; o >>= 1) s += __shfl_down_sync(0xFFFFFFFFu, s, o);
        if (lane == 0) {
            float u = fmaxf(s + bc2a[0], 0.f);
            float sc = u * Wc2b[0] + bc2b[0];
            out[1 + row] = 1.f / (1.f + expf(-sc));
        }
    }
    if (bid == 0 && wid == 0) {
        float v = g_dpart[lane] + g_dpart[lane + 32] + g_dpart[lane + 64] + g_dpart[lane + 96];
        #pragma unroll
        for (int o = 16; o; o >>= 1) v += __shfl_down_sync(0xFFFFFFFFu, v, o);
        if (lane == 0) out[0] = 1.f / (1.f + expf(-(v + bd[0])));
    }
}

// ---------------- launch ----------------
extern "C" void kernel_launch(void* const* d_in, const int* in_sizes, int n_in,
                              void* d_out, int out_size) {
    const float* X    = (const float*)d_in[0];
    const int*   idx  = (const int*)d_in[1];
    const float* Ws1a = (const float*)d_in[3];
    const float* bs1a = (const float*)d_in[4];
    const float* Ws1b = (const float*)d_in[5];
    const float* bs1b = (const float*)d_in[6];
    const float* Ws2a = (const float*)d_in[7];
    const float* bs2a = (const float*)d_in[8];
    const float* Ws2b = (const float*)d_in[9];
    const float* bs2b = (const float*)d_in[10];
    const float* Wc1a = (const float*)d_in[11];
    const float* bc1a = (const float*)d_in[12];
    const float* Wc1b = (const float*)d_in[13];
    const float* bc1b = (const float*)d_in[14];
    const float* Wc2a = (const float*)d_in[15];
    const float* bc2a = (const float*)d_in[16];
    const float* Wc2b = (const float*)d_in[17];
    const float* bc2b = (const float*)d_in[18];
    const float* Wd   = (const float*)d_in[19];
    const float* bd   = (const float*)d_in[20];
    float* out = (float*)d_out;

    float* pPpart;
    cudaGetSymbolAddress((void**)&pPpart, g_Ppart);

    cudaFuncSetAttribute(bigmm4, cudaFuncAttributeMaxDynamicSharedMemorySize, SMEM_DYN3);
    cudaFuncSetAttribute(k_chain, cudaFuncAttributeMaxDynamicSharedMemorySize, CH_TOT3);

    k_cvtW<<<(N_CVT + 255) / 256, 256>>>(Ws1b, Ws2a, Ws2b, Wc1a, Wc1b);   // 1
    k_initB2<<<(N_B4 + 255) / 256, 256>>>();                               // 2
    k_edges<<<(EE + 255) / 256, 256>>>(idx);                               // 3
    bigmm4<<<dim3(4, 2, SPLITKZ), 256, SMEM_DYN3>>>(X, Ws1a, pPpart);      // 4
    k_chain<<<NCTA, CTHREADS, CH_TOT3>>>(bs1a, bs1b, bs2a, bs2b, bc1a, bc1b,
                                         Wc2a, bc2a, Wc2b, bc2b, Wd, bd, out);
}

// round 17
// speedup vs baseline: 1.7375x; 1.1846x over previous
#include <cuda_runtime.h>
#include <cuda_bf16.h>
#include <math.h>

#define NN 256
#define TT 30000
#define HH 512
#define LL 256
#define EE 32768

#define KSTEPS 1875
#define SPLITKZ 37
#define SPG 51

// bigmm bf16 buffer layout (2-pass: no Wl)
#define ASTRIDE 24
#define BSTRIDE 136
#define ST_AH 0
#define ST_AL 6144
#define ST_BH 12288
#define B16BUF 16640               // 12288 + 16*136*2
#define SMEM_DYN3 (2 * B16BUF)     // 33280

// chain gemm (32x32 tiles) smem layout — k16 stages, 4 K-groups
#define SASTR 24
#define SBSTR 72
#define NST 3
#define CG_AH 0
#define CG_AL 1536
#define CG_BH 3072
#define CG_BL 5376
#define CSTAGE 7680
#define CGRP (CSTAGE * NST)
#define NKG 4
#define CH_TOT3 (NKG * CGRP)       // 92160

#define NCTA 128
#define CTHREADS 512

// ---------------- device scratch ----------------
__device__ float g_B[NN * NN];
__device__ __nv_bfloat16 g_Bh[NN * NN];
__device__ float g_Ppart[SPLITKZ * NN * HH];
__device__ __nv_bfloat16 g_Ph[NN * HH], g_Pl[NN * HH];
__device__ __nv_bfloat16 g_U1h[NN * HH], g_U1l[NN * HH];
__device__ __nv_bfloat16 g_hh[NN * HH], g_hl[NN * HH];
__device__ __nv_bfloat16 g_Q2h[NN * LL], g_Q2l[NN * LL];
__device__ __nv_bfloat16 g_U2h[NN * LL], g_U2l[NN * LL];
__device__ __nv_bfloat16 g_fh[NN * LL], g_fl[NN * LL];
__device__ __nv_bfloat16 g_Q3h[NN * HH], g_Q3l[NN * HH];
__device__ __nv_bfloat16 g_U3h[NN * HH], g_U3l[NN * HH];
__device__ __nv_bfloat16 g_sh2[NN * HH], g_sl2[NN * HH];
__device__ __nv_bfloat16 g_W1bh[HH * HH], g_W1bl[HH * HH];
__device__ __nv_bfloat16 g_W2ah[HH * LL], g_W2al[HH * LL];
__device__ __nv_bfloat16 g_W2bh[LL * LL], g_W2bl[LL * LL];
__device__ __nv_bfloat16 g_Wc1ah[LL * HH], g_Wc1al[LL * HH];
__device__ __nv_bfloat16 g_Wc1bh[HH * HH], g_Wc1bl[HH * HH];
__device__ float g_Q4[NN];
__device__ float g_dpart[NCTA];
__device__ unsigned g_bar_cnt;
__device__ unsigned g_bar_gen;

// ---------------- weight conversion ----------------
#define N_W1B (HH * HH / 8)
#define N_W2A (HH * LL / 8)
#define N_W2B (LL * LL / 8)
#define N_WC1A (LL * HH / 8)
#define N_WC1B (HH * HH / 8)
#define N_CVT (N_W1B + N_W2A + N_W2B + N_WC1A + N_WC1B)
#define N_B4  (NN * NN / 4)

__device__ __forceinline__ void cvt8(const float* __restrict__ src,
                                     __nv_bfloat16* __restrict__ hi,
                                     __nv_bfloat16* __restrict__ lo, int j8) {
    float4 v0 = ((const float4*)src)[2 * j8], v1 = ((const float4*)src)[2 * j8 + 1];
    float f[8] = {v0.x, v0.y, v0.z, v0.w, v1.x, v1.y, v1.z, v1.w};
    union { __nv_bfloat16 b[8]; uint4 u; } H, L;
    #pragma unroll
    for (int j = 0; j < 8; j++) {
        __nv_bfloat16 h = __float2bfloat16(f[j]);
        H.b[j] = h; L.b[j] = __float2bfloat16(f[j] - __bfloat162float(h));
    }
    ((uint4*)hi)[j8] = H.u;
    ((uint4*)lo)[j8] = L.u;
}

__global__ void k_cvtW(const float* __restrict__ W1b, const float* __restrict__ W2a,
                       const float* __restrict__ W2b, const float* __restrict__ Wc1a,
                       const float* __restrict__ Wc1b) {
    int o = blockIdx.x * blockDim.x + threadIdx.x;
    if (o < N_W1B) { cvt8(W1b, g_W1bh, g_W1bl, o); return; }
    o -= N_W1B;
    if (o < N_W2A) { cvt8(W2a, g_W2ah, g_W2al, o); return; }
    o -= N_W2A;
    if (o < N_W2B) { cvt8(W2b, g_W2bh, g_W2bl, o); return; }
    o -= N_W2B;
    if (o < N_WC1A) { cvt8(Wc1a, g_Wc1ah, g_Wc1al, o); return; }
    o -= N_WC1A;
    if (o < N_WC1B) { cvt8(Wc1b, g_Wc1bh, g_Wc1bl, o); }
}

__global__ void k_initB2() {
    int o = blockIdx.x * blockDim.x + threadIdx.x;
    if (o < N_B4) {
        int e0 = o * 4;
        float4 v = make_float4(0.f, 0.f, 0.f, 0.f);
        float* pv = &v.x;
        #pragma unroll
        for (int q = 0; q < 4; q++) {
            int e = e0 + q;
            if ((e >> 8) == (e & 255)) pv[q] = 1.f;
        }
        ((float4*)g_B)[o] = v;
    }
}

__global__ void k_edges(const int* __restrict__ idx) {
    int e = blockIdx.x * blockDim.x + threadIdx.x;
    if (e < EE) atomicAdd(&g_B[idx[EE + e] * NN + idx[e]], 1.0f);
}

// ---------------- PTX helpers ----------------
__device__ __forceinline__ void mma_bf16(float* c, const unsigned* a, const unsigned* b) {
    asm volatile(
        "mma.sync.aligned.m16n8k16.row.col.f32.bf16.bf16.f32 "
        "{%0,%1,%2,%3},{%4,%5,%6,%7},{%8,%9},{%0,%1,%2,%3};"
        : "+f"(c[0]), "+f"(c[1]), "+f"(c[2]), "+f"(c[3])
        : "r"(a[0]), "r"(a[1]), "r"(a[2]), "r"(a[3]), "r"(b[0]), "r"(b[1]));
}
__device__ __forceinline__ void ldsm4(unsigned* r, unsigned addr) {
    asm volatile("ldmatrix.sync.aligned.m8n8.x4.shared.b16 {%0,%1,%2,%3},[%4];"
                 : "=r"(r[0]), "=r"(r[1]), "=r"(r[2]), "=r"(r[3]) : "r"(addr));
}
__device__ __forceinline__ void ldsm4t(unsigned* r, unsigned addr) {
    asm volatile("ldmatrix.sync.aligned.m8n8.x4.trans.shared.b16 {%0,%1,%2,%3},[%4];"
                 : "=r"(r[0]), "=r"(r[1]), "=r"(r[2]), "=r"(r[3]) : "r"(addr));
}
__device__ __forceinline__ void cpa16(unsigned dst, const void* src) {
    asm volatile("cp.async.cg.shared.global [%0], [%1], 16;" :: "r"(dst), "l"(src));
}
__device__ __forceinline__ void cpa8(unsigned dst, const void* src) {
    asm volatile("cp.async.ca.shared.global [%0], [%1], 8;" :: "r"(dst), "l"(src));
}
__device__ __forceinline__ void cpa_commit() { asm volatile("cp.async.commit_group;"); }
template <int N> __device__ __forceinline__ void cpa_wait() {
    asm volatile("cp.async.wait_group %0;" :: "n"(N));
}

// ---------------- big GEMM: 2-pass bf16 (X split, W hi only) ----------------
__global__ __launch_bounds__(256, 2)
void bigmm5(const float* __restrict__ X, const float* __restrict__ W, float* __restrict__ Ppart)
{
    extern __shared__ char dyn[];
    const unsigned sb = (unsigned)__cvta_generic_to_shared(dyn);

    const int t = threadIdx.x;
    const int m0 = blockIdx.y * 128, n0 = blockIdx.x * 128, z = blockIdx.z;
    const int s0 = z * SPG;
    const int ns = min(SPG, KSTEPS - s0);

    const int arow = t >> 1, ahalf = t & 1;
    const int brow = t >> 4, bcol = (t & 15) * 8;
    const float* gA = X + (size_t)(m0 + arow) * TT + (size_t)s0 * 16 + ahalf * 8;
    const float* gB = W + (size_t)((size_t)s0 * 16 + brow) * HH + n0 + bcol;
    const unsigned dA = (arow * ASTRIDE + ahalf * 8) * 2;
    const unsigned dB = (brow * BSTRIDE + bcol) * 2;

    const int lane = t & 31, wid = t >> 5;
    const int wm = wid & 3, wn = wid >> 2;
    unsigned offA[2], offB[4];
    {
        int r = lane & 15, c = (lane >> 4) * 8;
        offA[0] = ((wm * 32 + r) * ASTRIDE + c) * 2;
        offA[1] = ((wm * 32 + 16 + r) * ASTRIDE + c) * 2;
        int br = (lane & 7) + ((lane & 16) ? 8 : 0);
        int bc = (lane & 8) ? 8 : 0;
        #pragma unroll
        for (int p = 0; p < 4; p++)
            offB[p] = (br * BSTRIDE + wn * 64 + p * 16 + bc) * 2;
    }

    float acc[2][8][4];
    #pragma unroll
    for (int i = 0; i < 2; i++)
        #pragma unroll
        for (int j = 0; j < 8; j++)
            #pragma unroll
            for (int q = 0; q < 4; q++) acc[i][j][q] = 0.f;

    float fa[8], fb[8];
    // prologue: load step 0, convert+store into buf 0
    {
        float4 v0 = *(const float4*)gA, v1 = *(const float4*)(gA + 4);
        fa[0]=v0.x; fa[1]=v0.y; fa[2]=v0.z; fa[3]=v0.w; fa[4]=v1.x; fa[5]=v1.y; fa[6]=v1.z; fa[7]=v1.w;
        float4 w0 = *(const float4*)gB, w1 = *(const float4*)(gB + 4);
        fb[0]=w0.x; fb[1]=w0.y; fb[2]=w0.z; fb[3]=w0.w; fb[4]=w1.x; fb[5]=w1.y; fb[6]=w1.z; fb[7]=w1.w;
        union { __nv_bfloat16 b[8]; uint4 u; } H, L;
        #pragma unroll
        for (int j = 0; j < 8; j++) {
            __nv_bfloat16 h = __float2bfloat16(fa[j]);
            H.b[j] = h; L.b[j] = __float2bfloat16(fa[j] - __bfloat162float(h));
        }
        *(uint4*)(dyn + ST_AH + dA) = H.u;
        *(uint4*)(dyn + ST_AL + dA) = L.u;
        #pragma unroll
        for (int j = 0; j < 8; j++) H.b[j] = __float2bfloat16(fb[j]);
        *(uint4*)(dyn + ST_BH + dB) = H.u;
    }
    __syncthreads();

    for (int s = 0; s < ns; s++) {
        const int buf = s & 1;
        if (s + 1 < ns) {
            const float* pa = gA + (size_t)(s + 1) * 16;
            float4 v0 = *(const float4*)pa, v1 = *(const float4*)(pa + 4);
            fa[0]=v0.x; fa[1]=v0.y; fa[2]=v0.z; fa[3]=v0.w; fa[4]=v1.x; fa[5]=v1.y; fa[6]=v1.z; fa[7]=v1.w;
            const float* pb = gB + (size_t)(s + 1) * 16 * HH;
            float4 w0 = *(const float4*)pb, w1 = *(const float4*)(pb + 4);
            fb[0]=w0.x; fb[1]=w0.y; fb[2]=w0.z; fb[3]=w0.w; fb[4]=w1.x; fb[5]=w1.y; fb[6]=w1.z; fb[7]=w1.w;
        }

        // compute from buf: acc += (Xh + Xl) @ Wh
        {
            const unsigned base = sb + buf * B16BUF;
            unsigned aH[2][4], aL[2][4];
            ldsm4(aH[0], base + ST_AH + offA[0]);
            ldsm4(aH[1], base + ST_AH + offA[1]);
            ldsm4(aL[0], base + ST_AL + offA[0]);
            ldsm4(aL[1], base + ST_AL + offA[1]);
            #pragma unroll
            for (int p = 0; p < 4; p++) {
                unsigned r[4];
                ldsm4t(r, base + ST_BH + offB[p]);
                unsigned bh0[2] = {r[0], r[2]}, bh1[2] = {r[1], r[3]};
                #pragma unroll
                for (int mi = 0; mi < 2; mi++) {
                    mma_bf16(acc[mi][2 * p],     aH[mi], bh0);
                    mma_bf16(acc[mi][2 * p],     aL[mi], bh0);
                    mma_bf16(acc[mi][2 * p + 1], aH[mi], bh1);
                    mma_bf16(acc[mi][2 * p + 1], aL[mi], bh1);
                }
            }
        }

        if (s + 1 < ns) {
            char* nb = dyn + (buf ^ 1) * B16BUF;
            union { __nv_bfloat16 b[8]; uint4 u; } H, L;
            #pragma unroll
            for (int j = 0; j < 8; j++) {
                __nv_bfloat16 h = __float2bfloat16(fa[j]);
                H.b[j] = h; L.b[j] = __float2bfloat16(fa[j] - __bfloat162float(h));
            }
            *(uint4*)(nb + ST_AH + dA) = H.u;
            *(uint4*)(nb + ST_AL + dA) = L.u;
            #pragma unroll
            for (int j = 0; j < 8; j++) H.b[j] = __float2bfloat16(fb[j]);
            *(uint4*)(nb + ST_BH + dB) = H.u;
        }
        __syncthreads();
    }

    float* Po = Ppart + (size_t)z * NN * HH;
    #pragma unroll
    for (int mi = 0; mi < 2; mi++) {
        int row = m0 + wm * 32 + mi * 16 + (lane >> 2);
        #pragma unroll
        for (int ni = 0; ni < 8; ni++) {
            int col = n0 + wn * 64 + ni * 8 + (lane & 3) * 2;
            *(float2*)&Po[(size_t)row * HH + col]       = make_float2(acc[mi][ni][0], acc[mi][ni][1]);
            *(float2*)&Po[(size_t)(row + 8) * HH + col] = make_float2(acc[mi][ni][2], acc[mi][ni][3]);
        }
    }
}

// ---------------- device-wide barrier ----------------
__device__ __forceinline__ void gbar() {
    __syncthreads();
    if (threadIdx.x == 0) {
        __threadfence();
        unsigned old = *(volatile unsigned*)&g_bar_gen;
        unsigned a = atomicAdd(&g_bar_cnt, 1u);
        if (a == NCTA - 1) {
            g_bar_cnt = 0;
            __threadfence();
            *(volatile unsigned*)&g_bar_gen = old + 1;
        } else {
            while (*(volatile unsigned*)&g_bar_gen == old) { }
        }
        __threadfence();
    }
    __syncthreads();
}

// ---------------- 32x32 tile GEMM: 512 threads, 4-way warp-split-K ----------------
__device__ void dgemm16(const __nv_bfloat16* __restrict__ Ah, const __nv_bfloat16* __restrict__ Al,
                        const __nv_bfloat16* __restrict__ Bh, const __nv_bfloat16* __restrict__ Bl,
                        const float* __restrict__ bias,
                        __nv_bfloat16* __restrict__ Ch, __nv_bfloat16* __restrict__ Cl,
                        int N, int K, int m0, int n0, int epi, int aexact, char* sm)
{
    const int t = threadIdx.x;
    const int kg = t >> 7, t7 = t & 127;
    const int Kq = K >> 2;
    const int ns = Kq >> 4;

    const int arow = t7 >> 2, ak = (t7 & 3) * 4;
    const int brow = t7 >> 3, bn = (t7 & 7) * 4;
    const __nv_bfloat16* gAh = Ah + (size_t)(m0 + arow) * K + kg * Kq + ak;
    const __nv_bfloat16* gAl = aexact ? gAh : (Al + (size_t)(m0 + arow) * K + kg * Kq + ak);
    const __nv_bfloat16* gBh = Bh + (size_t)(kg * Kq + brow) * N + n0 + bn;
    const __nv_bfloat16* gBl = Bl + (size_t)(kg * Kq + brow) * N + n0 + bn;

    const unsigned grpBase = (unsigned)__cvta_generic_to_shared(sm) + kg * CGRP;
    const unsigned dA = (arow * SASTR + ak) * 2;
    const unsigned dB = (brow * SBSTR + bn) * 2;

    const int lane = t & 31;
    const int wid2 = (t >> 5) & 3;
    const int wm = wid2 & 1, wn = wid2 >> 1;

    unsigned offA0, offB0;
    {
        int r = lane & 15, c = (lane >> 4) * 8;
        offA0 = ((wm * 16 + r) * SASTR + c) * 2;
        int br = (lane & 7) + ((lane & 16) ? 8 : 0);
        int bc = (lane & 8) ? 8 : 0;
        offB0 = (br * SBSTR + wn * 16 + bc) * 2;
    }

    float acc[2][4];
    #pragma unroll
    for (int j = 0; j < 2; j++)
        #pragma unroll
        for (int q = 0; q < 4; q++) acc[j][q] = 0.f;

    #pragma unroll
    for (int sg = 0; sg < NST - 1; sg++) {
        if (sg < ns) {
            unsigned bs = grpBase + sg * CSTAGE;
            size_t ko = (size_t)sg * 16;
            cpa8(bs + CG_AH + dA, gAh + ko);
            if (!aexact) cpa8(bs + CG_AL + dA, gAl + ko);
            cpa8(bs + CG_BH + dB, gBh + ko * N);
            cpa8(bs + CG_BL + dB, gBl + ko * N);
        }
        cpa_commit();
    }

    for (int s = 0; s < ns; s++) {
        cpa_wait<NST - 2>();
        __syncthreads();

        int sg = s + NST - 1;
        if (sg < ns) {
            unsigned bs = grpBase + (sg % NST) * CSTAGE;
            size_t ko = (size_t)sg * 16;
            cpa8(bs + CG_AH + dA, gAh + ko);
            if (!aexact) cpa8(bs + CG_AL + dA, gAl + ko);
            cpa8(bs + CG_BH + dB, gBh + ko * N);
            cpa8(bs + CG_BL + dB, gBl + ko * N);
        }
        cpa_commit();

        const unsigned bs = grpBase + (s % NST) * CSTAGE;
        unsigned aH[4], aL[4];
        ldsm4(aH, bs + CG_AH + offA0);
        if (!aexact) ldsm4(aL, bs + CG_AL + offA0);
        unsigned bH[2][2], bL[2][2];
        {
            unsigned r[4];
            ldsm4t(r, bs + CG_BH + offB0);
            bH[0][0] = r[0]; bH[0][1] = r[2]; bH[1][0] = r[1]; bH[1][1] = r[3];
            ldsm4t(r, bs + CG_BL + offB0);
            bL[0][0] = r[0]; bL[0][1] = r[2]; bL[1][0] = r[1]; bL[1][1] = r[3];
        }
        #pragma unroll
        for (int ni = 0; ni < 2; ni++) {
            mma_bf16(acc[ni], aH, bH[ni]);
            mma_bf16(acc[ni], aH, bL[ni]);
        }
        if (!aexact) {
            #pragma unroll
            for (int ni = 0; ni < 2; ni++)
                mma_bf16(acc[ni], aL, bH[ni]);
        }
    }

    __syncthreads();
    float* comb = (float*)sm;
    if (kg != 0) {
        int base = (kg - 1) * 1184 + t7 * 9;
        #pragma unroll
        for (int ni = 0; ni < 2; ni++)
            #pragma unroll
            for (int q = 0; q < 4; q++)
                comb[base + ni * 4 + q] = acc[ni][q];
    }
    __syncthreads();
    if (kg == 0) {
        int row = m0 + wm * 16 + (lane >> 2);
        #pragma unroll
        for (int ni = 0; ni < 2; ni++) {
            int col = n0 + wn * 16 + ni * 8 + (lane & 3) * 2;
            float v[4];
            #pragma unroll
            for (int q = 0; q < 4; q++) {
                int idx = ni * 4 + q;
                v[q] = acc[ni][q]
                     + comb[0 * 1184 + t7 * 9 + idx]
                     + comb[1 * 1184 + t7 * 9 + idx]
                     + comb[2 * 1184 + t7 * 9 + idx];
            }
            if (epi) {
                float2 b = *(const float2*)&bias[col];
                v[0] += b.x; v[1] += b.y; v[2] += b.x; v[3] += b.y;
            }
            if (epi == 1) {
                v[0] = fmaxf(v[0], 0.f); v[1] = fmaxf(v[1], 0.f);
                v[2] = fmaxf(v[2], 0.f); v[3] = fmaxf(v[3], 0.f);
            }
            #pragma unroll
            for (int rr = 0; rr < 2; rr++) {
                float x0 = v[rr * 2], x1 = v[rr * 2 + 1];
                __nv_bfloat16 h0 = __float2bfloat16(x0), h1 = __float2bfloat16(x1);
                __nv_bfloat162 Hp, Lp;
                Hp.x = h0; Hp.y = h1;
                Lp.x = __float2bfloat16(x0 - __bfloat162float(h0));
                Lp.y = __float2bfloat16(x1 - __bfloat162float(h1));
                size_t off = (size_t)(row + rr * 8) * N + col;
                *(__nv_bfloat162*)&Ch[off] = Hp;
                *(__nv_bfloat162*)&Cl[off] = Lp;
            }
        }
    }
    __syncthreads();
}

// ---------------- persistent chain kernel (128 CTAs x 512 threads) ----------------
__global__ __launch_bounds__(CTHREADS)
void k_chain(const float* __restrict__ bs1a, const float* __restrict__ bs1b,
             const float* __restrict__ bs2a, const float* __restrict__ bs2b,
             const float* __restrict__ bc1a, const float* __restrict__ bc1b,
             const float* __restrict__ Wc2a, const float* __restrict__ bc2a,
             const float* __restrict__ Wc2b, const float* __restrict__ bc2b,
             const float* __restrict__ Wd, const float* __restrict__ bd,
             float* __restrict__ out)
{
    extern __shared__ char s_all[];
    __shared__ float dred[16];

    const int bid = blockIdx.x, t = threadIdx.x;
    const int gid = bid * CTHREADS + t;
    const int wid = t >> 5, lane = t & 31;

    if (gid < 32768) {
        int i = gid;
        float4 s = make_float4(0.f, 0.f, 0.f, 0.f);
        #pragma unroll
        for (int z = 0; z < SPLITKZ; z++) {
            float4 v = ((const float4*)g_Ppart)[(size_t)z * (NN * HH / 4) + i];
            s.x += v.x; s.y += v.y; s.z += v.z; s.w += v.w;
        }
        int e = i * 4;
        float f[4] = {s.x, s.y, s.z, s.w};
        union { __nv_bfloat16 b[4]; uint2 u; } H, L;
        #pragma unroll
        for (int q = 0; q < 4; q++) {
            __nv_bfloat16 h = __float2bfloat16(f[q]);
            H.b[q] = h; L.b[q] = __float2bfloat16(f[q] - __bfloat162float(h));
        }
        *(uint2*)&g_Ph[e] = H.u;
        *(uint2*)&g_Pl[e] = L.u;
    }
    if (gid < 8192) {
        float4 a = ((const float4*)g_B)[gid * 2], b = ((const float4*)g_B)[gid * 2 + 1];
        float f[8] = {a.x, a.y, a.z, a.w, b.x, b.y, b.z, b.w};
        union { __nv_bfloat16 v[8]; uint4 u; } H;
        #pragma unroll
        for (int q = 0; q < 8; q++) H.v[q] = __float2bfloat16(f[q]);
        ((uint4*)g_Bh)[gid] = H.u;
    }
    gbar();

    const int tx16 = bid & 15, ty16 = bid >> 4;
    const int tx8 = bid & 7, ty8 = bid >> 3;

    dgemm16(g_Bh, (const __nv_bfloat16*)0, g_Ph, g_Pl, bs1a, g_U1h, g_U1l,
            HH, NN, ty16 * 32, tx16 * 32, 1, 1, s_all);
    gbar();
    dgemm16(g_U1h, g_U1l, g_W1bh, g_W1bl, bs1b, g_hh, g_hl,
            HH, HH, ty16 * 32, tx16 * 32, 1, 0, s_all);
    gbar();
    if (bid < 64)
        dgemm16(g_hh, g_hl, g_W2ah, g_W2al, (const float*)0, g_Q2h, g_Q2l,
                LL, HH, ty8 * 32, tx8 * 32, 0, 0, s_all);
    gbar();
    if (bid < 64)
        dgemm16(g_Bh, (const __nv_bfloat16*)0, g_Q2h, g_Q2l, bs2a, g_U2h, g_U2l,
                LL, NN, ty8 * 32, tx8 * 32, 1, 1, s_all);
    gbar();
    if (bid < 64)
        dgemm16(g_U2h, g_U2l, g_W2bh, g_W2bl, bs2b, g_fh, g_fl,
                LL, LL, ty8 * 32, tx8 * 32, 2, 0, s_all);
    gbar();
    dgemm16(g_fh, g_fl, g_Wc1ah, g_Wc1al, (const float*)0, g_Q3h, g_Q3l,
            HH, LL, ty16 * 32, tx16 * 32, 0, 0, s_all);
    gbar();
    dgemm16(g_Bh, (const __nv_bfloat16*)0, g_Q3h, g_Q3l, bc1a, g_U3h, g_U3l,
            HH, NN, ty16 * 32, tx16 * 32, 1, 1, s_all);
    gbar();
    dgemm16(g_U3h, g_U3l, g_Wc1bh, g_Wc1bl, bc1b, g_sh2, g_sl2,
            HH, HH, ty16 * 32, tx16 * 32, 1, 0, s_all);
    gbar();

    if (wid < 2) {
        int row = bid * 2 + wid;
        float s = 0.f;
        for (int i = lane; i < HH; i += 32)
            s += (__bfloat162float(g_sh2[row * HH + i]) + __bfloat162float(g_sl2[row * HH + i])) * Wc2a[i];
        #pragma unroll
        for (int o = 16; o; o >>= 1) s += __shfl_down_sync(0xFFFFFFFFu, s, o);
        if (lane == 0) g_Q4[row] = s;
    }
    {
        float ds = 0.f;
        int base = bid * 512;
        for (int i = t; i < 512; i += CTHREADS)
            ds += (__bfloat162float(g_fh[base + i]) + __bfloat162float(g_fl[base + i])) * Wd[base + i];
        #pragma unroll
        for (int o = 16; o; o >>= 1) ds += __shfl_down_sync(0xFFFFFFFFu, ds, o);
        if (lane == 0) dred[wid] = ds;
        __syncthreads();
        if (t == 0) {
            float v = 0.f;
            #pragma unroll
            for (int j = 0; j < 16; j++) v += dred[j];
            g_dpart[bid] = v;
        }
    }
    gbar();

    if (wid < 2) {
        int row = bid * 2 + wid;
        float s = 0.f;
        for (int i = lane; i < NN; i += 32) s += g_B[row * NN + i] * g_Q4[i];
        #pragma unroll
        for (int o = 16; o; o >>= 1) s += __shfl_down_sync(0xFFFFFFFFu, s, o);
        if (lane == 0) {
            float u = fmaxf(s + bc2a[0], 0.f);
            float sc = u * Wc2b[0] + bc2b[0];
            out[1 + row] = 1.f / (1.f + expf(-sc));
        }
    }
    if (bid == 0 && wid == 0) {
        float v = g_dpart[lane] + g_dpart[lane + 32] + g_dpart[lane + 64] + g_dpart[lane + 96];
        #pragma unroll
        for (int o = 16; o; o >>= 1) v += __shfl_down_sync(0xFFFFFFFFu, v, o);
        if (lane == 0) out[0] = 1.f / (1.f + expf(-(v + bd[0])));
    }
}

// ---------------- launch ----------------
extern "C" void kernel_launch(void* const* d_in, const int* in_sizes, int n_in,
                              void* d_out, int out_size) {
    const float* X    = (const float*)d_in[0];
    const int*   idx  = (const int*)d_in[1];
    const float* Ws1a = (const float*)d_in[3];
    const float* bs1a = (const float*)d_in[4];
    const float* Ws1b = (const float*)d_in[5];
    const float* bs1b = (const float*)d_in[6];
    const float* Ws2a = (const float*)d_in[7];
    const float* bs2a = (const float*)d_in[8];
    const float* Ws2b = (const float*)d_in[9];
    const float* bs2b = (const float*)d_in[10];
    const float* Wc1a = (const float*)d_in[11];
    const float* bc1a = (const float*)d_in[12];
    const float* Wc1b = (const float*)d_in[13];
    const float* bc1b = (const float*)d_in[14];
    const float* Wc2a = (const float*)d_in[15];
    const float* bc2a = (const float*)d_in[16];
    const float* Wc2b = (const float*)d_in[17];
    const float* bc2b = (const float*)d_in[18];
    const float* Wd   = (const float*)d_in[19];
    const float* bd   = (const float*)d_in[20];
    float* out = (float*)d_out;

    float* pPpart;
    cudaGetSymbolAddress((void**)&pPpart, g_Ppart);

    cudaFuncSetAttribute(bigmm5, cudaFuncAttributeMaxDynamicSharedMemorySize, SMEM_DYN3);
    cudaFuncSetAttribute(k_chain, cudaFuncAttributeMaxDynamicSharedMemorySize, CH_TOT3);

    k_cvtW<<<(N_CVT + 255) / 256, 256>>>(Ws1b, Ws2a, Ws2b, Wc1a, Wc1b);   // 1
    k_initB2<<<(N_B4 + 255) / 256, 256>>>();                               // 2
    k_edges<<<(EE + 255) / 256, 256>>>(idx);                               // 3
    bigmm5<<<dim3(4, 2, SPLITKZ), 256, SMEM_DYN3>>>(X, Ws1a, pPpart);      // 4
    k_chain<<<NCTA, CTHREADS, CH_TOT3>>>(bs1a, bs1b, bs2a, bs2b, bc1a, bc1b,
                                         Wc2a, bc2a, Wc2b, bc2b, Wd, bd, out);
}